// round 2
// baseline (speedup 1.0000x reference)
#include <cuda_runtime.h>
#include <cuda_fp16.h>
#include <math.h>

#define B_ 32
#define C_ 256
#define H_ 56
#define W_ 56
#define HW_ 3136
#define G_ 8
#define CG_ 32
#define BG_ 256
#define EPSV 1e-5f

// ---------------- static device scratch ----------------
__device__ __half d_x16[(size_t)B_*C_*HW_];   // fp16 x
__device__ __half d_x4 [(size_t)B_*C_*HW_];   // conv4 output
__device__ __half d_w4t[9*256*256];           // w3b -> [r][o][i]
__device__ __half d_w2t[9*32*32];             // w3a -> [r][o][i]
__device__ float d_xhm[BG_*CG_*H_], d_xwm[BG_*CG_*W_];
__device__ float d_sh [BG_*CG_*H_], d_sw [BG_*CG_*W_];
__device__ float d_chsum[BG_*CG_], d_chsq[BG_*CG_];
__device__ float d_mu[BG_*CG_], d_rstd[BG_*CG_];
__device__ float d_bm[C_], d_rbstd[C_];
__device__ float d_x11[CG_];
__device__ float d_m2[BG_*CG_];
__device__ float d_A1[BG_*CG_], d_C1[BG_];
__device__ float d_w1[(size_t)BG_*HW_];
__device__ float d_s3[(size_t)B_*HW_], d_s4[(size_t)B_*HW_];
__device__ float d_sw2[B_*C_];

// ---------------- helpers ----------------
__device__ __forceinline__ unsigned smem_u32(const void* p){
    return (unsigned)__cvta_generic_to_shared(p);
}
__device__ __forceinline__ void ldsm4(unsigned a, unsigned &r0, unsigned &r1, unsigned &r2, unsigned &r3){
    asm volatile("ldmatrix.sync.aligned.m8n8.x4.shared.b16 {%0,%1,%2,%3},[%4];\n"
        : "=r"(r0),"=r"(r1),"=r"(r2),"=r"(r3) : "r"(a));
}
__device__ __forceinline__ void ldsm4t(unsigned a, unsigned &r0, unsigned &r1, unsigned &r2, unsigned &r3){
    asm volatile("ldmatrix.sync.aligned.m8n8.x4.trans.shared.b16 {%0,%1,%2,%3},[%4];\n"
        : "=r"(r0),"=r"(r1),"=r"(r2),"=r"(r3) : "r"(a));
}
__device__ __forceinline__ void mma16816(float* c, unsigned a0, unsigned a1, unsigned a2, unsigned a3,
                                         unsigned b0, unsigned b1){
    asm volatile("mma.sync.aligned.m16n8k16.row.col.f32.f16.f16.f32 "
        "{%0,%1,%2,%3}, {%4,%5,%6,%7}, {%8,%9}, {%0,%1,%2,%3};\n"
        : "+f"(c[0]),"+f"(c[1]),"+f"(c[2]),"+f"(c[3])
        : "r"(a0),"r"(a1),"r"(a2),"r"(a3),"r"(b0),"r"(b1));
}
__device__ __forceinline__ float sigf(float v){ return 1.f/(1.f+expf(-v)); }

// ---------------- small kernels ----------------
__global__ void k_zero(){
    int i = blockIdx.x*blockDim.x + threadIdx.x;
    if (i < BG_*CG_) d_m2[i] = 0.f;
}

__global__ void k_wprep(const float* __restrict__ w3b, const float* __restrict__ w3a){
    int j = blockIdx.x*blockDim.x + threadIdx.x;
    if (j < 256*256*9){
        int o = j/2304, ic = (j/9)%256, r = j%9;
        d_w4t[(r*256+o)*256+ic] = __float2half(w3b[j]);
    }
    if (j < 32*32*9){
        int o = j/288, ic = (j/9)%32, r = j%9;
        d_w2t[(r*32+o)*32+ic] = __float2half(w3a[j]);
    }
}

__global__ void k_x11(const float* __restrict__ gnb){
    int t = threadIdx.x;
    float v = gnb[t], m = v;
    #pragma unroll
    for (int s=16;s;s>>=1) m = fmaxf(m, __shfl_xor_sync(~0u, m, s));
    float e = expf(v-m), sum = e;
    #pragma unroll
    for (int s=16;s;s>>=1) sum += __shfl_xor_sync(~0u, sum, s);
    d_x11[t] = e/sum;
}

__global__ void __launch_bounds__(256) k_rowcol(const float* __restrict__ x){
    __shared__ float tile[HW_];
    int ch = blockIdx.x;
    const float* src = x + (size_t)ch*HW_;
    for (int i = threadIdx.x; i < HW_; i += 256){
        float v = src[i];
        tile[i] = v;
        d_x16[(size_t)ch*HW_ + i] = __float2half(v);
    }
    __syncthreads();
    int t = threadIdx.x;
    if (t < H_){
        float rs = 0.f, cs = 0.f;
        #pragma unroll 8
        for (int w = 0; w < W_; w++) rs += tile[t*W_ + w];
        #pragma unroll 8
        for (int h = 0; h < H_; h++) cs += tile[h*W_ + t];
        d_xhm[ch*H_ + t] = rs * (1.0f/W_);
        d_xwm[ch*W_ + t] = cs * (1.0f/H_);
    }
}

__global__ void __launch_bounds__(128) k_hw(const float* __restrict__ w1, const float* __restrict__ b1){
    __shared__ float ws[1024], cat[32*112], bs[32];
    int bg = blockIdx.x;
    for (int i = threadIdx.x; i < 1024; i += 128) ws[i] = w1[i];
    if (threadIdx.x < 32) bs[threadIdx.x] = b1[threadIdx.x];
    for (int i = threadIdx.x; i < 32*112; i += 128){
        int c = i/112, p = i%112;
        cat[i] = (p < H_) ? d_xhm[(bg*CG_+c)*H_+p] : d_xwm[(bg*CG_+c)*W_+(p-H_)];
    }
    __syncthreads();
    for (int i = threadIdx.x; i < 32*112; i += 128){
        int o = i/112, p = i%112;
        float acc = bs[o];
        #pragma unroll 8
        for (int c = 0; c < 32; c++) acc += ws[o*32+c]*cat[c*112+p];
        float s = sigf(acc);
        if (p < H_) d_sh[(bg*CG_+o)*H_+p] = s;
        else        d_sw[(bg*CG_+o)*W_+(p-H_)] = s;
    }
}

__global__ void __launch_bounds__(128) k_stats(const float* __restrict__ x){
    int ch = blockIdx.x;
    const float* src = x + (size_t)ch*HW_;
    const float* shp = d_sh + ch*H_;
    const float* swp = d_sw + ch*W_;
    float s = 0.f, q = 0.f;
    for (int i = threadIdx.x; i < HW_; i += 128){
        float v = src[i]*shp[i/W_]*swp[i%W_];
        s += v; q += v*v;
    }
    __shared__ float ss[4], qq[4];
    int lane = threadIdx.x & 31, w = threadIdx.x >> 5;
    #pragma unroll
    for (int o=16;o;o>>=1){ s += __shfl_xor_sync(~0u,s,o); q += __shfl_xor_sync(~0u,q,o); }
    if (lane==0){ ss[w]=s; qq[w]=q; }
    __syncthreads();
    if (threadIdx.x==0){
        d_chsum[ch] = ss[0]+ss[1]+ss[2]+ss[3];
        d_chsq [ch] = qq[0]+qq[1]+qq[2]+qq[3];
    }
}

__global__ void k_fin(){
    int i = blockIdx.x*blockDim.x + threadIdx.x;
    if (i < BG_*CG_){
        float mu = d_chsum[i]*(1.0f/HW_);
        float var = d_chsq[i]*(1.0f/HW_) - mu*mu;
        d_mu[i] = mu;
        d_rstd[i] = rsqrtf(var + EPSV);
    }
    if (i < C_){
        float s = 0.f, q = 0.f;
        for (int b = 0; b < B_; b++){ s += d_chsum[b*C_+i]; q += d_chsq[b*C_+i]; }
        const float n = (float)B_*(float)HW_;
        float bm = s/n, bv = q/n - bm*bm;
        d_bm[i] = bm;
        d_rbstd[i] = rsqrtf(bv + EPSV);
    }
}

// ---------------- conv2: grouped 3x3, fused weights1 term1 + mean(x2) ----------------
__global__ void __launch_bounds__(128) k_conv2(const float* __restrict__ b3a){
    __shared__ __align__(16) __half As[32*24];
    __shared__ __align__(16) __half Bs[16*64];
    __shared__ float red[64], x11s[32], b3as[32];
    int y = blockIdx.x, bg = blockIdx.y;
    int t = threadIdx.x, lane = t&31, w = t>>5;
    int mrow = (w&1)*16, nbase = (w>>1)*32;
    float acc[4][4];
    #pragma unroll
    for (int i=0;i<4;i++)
        #pragma unroll
        for (int k=0;k<4;k++) acc[i][k]=0.f;
    if (t<32){ x11s[t]=d_x11[t]; b3as[t]=b3a[t]; }
    if (t<64) red[t]=0.f;
    unsigned a_addr = smem_u32(As) + ((mrow + (lane&15))*24 + (lane>>4)*8)*2;
    unsigned b_base = smem_u32(Bs);
    for (int r=0;r<9;r++){
        int dy=r/3-1, dx=r%3-1, yy=y+dy;
        bool rowok = (yy>=0 && yy<H_);
        int yc = rowok ? yy : 0;
        for (int kc=0;kc<2;kc++){
            if (t<64){
                int row=t>>1, c8=(t&1)*8;
                *(uint4*)&As[row*24+c8] = *(const uint4*)(d_w2t + (r*32+row)*32 + kc*16 + c8);
            }
            {
                int k=t>>3, n0=(t&7)*8;
                const __half* src = d_x16 + ((size_t)(bg*CG_ + kc*16 + k)*H_ + yc)*W_;
                __align__(16) __half tmp[8];
                #pragma unroll
                for (int j=0;j<8;j++){
                    int cx = n0+j+dx;
                    tmp[j] = (rowok && cx>=0 && cx<W_) ? src[cx] : __float2half(0.f);
                }
                unsigned grp = (unsigned)(n0>>3) ^ (unsigned)(k&7);
                *(uint4*)((char*)Bs + k*128 + grp*16) = *(uint4*)tmp;
            }
            __syncthreads();
            unsigned a0,a1,a2,a3; ldsm4(a_addr,a0,a1,a2,a3);
            #pragma unroll
            for (int j=0;j<2;j++){
                unsigned g0 = (unsigned)((nbase>>3) + j*2 + (lane>>4)) ^ (unsigned)(lane&7);
                unsigned b0,b1,b2,b3;
                ldsm4t(b_base + (lane&15)*128 + g0*16, b0,b1,b2,b3);
                mma16816(acc[j*2],   a0,a1,a2,a3, b0,b1);
                mma16816(acc[j*2+1], a0,a1,a2,a3, b2,b3);
            }
            __syncthreads();
        }
    }
    int g=lane>>2, tig=lane&3;
    int o0 = mrow+g, o1 = o0+8;
    float rs0=0.f, rs1=0.f;
    #pragma unroll
    for (int nt=0;nt<4;nt++){
        int n = nbase + nt*8 + tig*2;
        if (n < W_){
            float v0 = acc[nt][0]+b3as[o0], v1 = acc[nt][1]+b3as[o0];
            float v2 = acc[nt][2]+b3as[o1], v3 = acc[nt][3]+b3as[o1];
            atomicAdd(&red[n],   x11s[o0]*v0 + x11s[o1]*v2);
            atomicAdd(&red[n+1], x11s[o0]*v1 + x11s[o1]*v3);
            rs0 += v0+v1; rs1 += v2+v3;
        }
    }
    rs0 += __shfl_xor_sync(~0u,rs0,1); rs0 += __shfl_xor_sync(~0u,rs0,2);
    rs1 += __shfl_xor_sync(~0u,rs1,1); rs1 += __shfl_xor_sync(~0u,rs1,2);
    if (tig==0){
        atomicAdd(&d_m2[bg*CG_+o0], rs0);
        atomicAdd(&d_m2[bg*CG_+o1], rs1);
    }
    __syncthreads();
    if (t < W_) d_w1[(size_t)bg*HW_ + y*W_ + t] = red[t];
}

__global__ void k_x21(const float* __restrict__ gnw, const float* __restrict__ gnb){
    int bg = blockIdx.x, t = threadIdx.x;   // 32 threads
    float v = d_m2[bg*CG_+t]*(1.0f/HW_);
    float m = v;
    #pragma unroll
    for (int s=16;s;s>>=1) m = fmaxf(m, __shfl_xor_sync(~0u,m,s));
    float e = expf(v-m), sum = e;
    #pragma unroll
    for (int s=16;s;s>>=1) sum += __shfl_xor_sync(~0u,sum,s);
    float x21 = e/sum;
    float rs = d_rstd[bg*CG_+t], mu = d_mu[bg*CG_+t];
    d_A1[bg*CG_+t] = x21*gnw[t]*rs;
    float cc = x21*(gnb[t] - gnw[t]*rs*mu);
    #pragma unroll
    for (int s=16;s;s>>=1) cc += __shfl_xor_sync(~0u,cc,s);
    if (t==0) d_C1[bg] = cc;
}

// ---------------- conv4: dense 3x3, 256->256, writes x4 fp16 ----------------
__global__ void __launch_bounds__(256) k_conv4(const float* __restrict__ b3b){
    __shared__ __align__(16) __half As[128*24];
    __shared__ __align__(16) __half Bs[16*64];
    __shared__ float b3bs[128];
    int y = blockIdx.x, b = blockIdx.y, mbase = blockIdx.z*128;
    int t = threadIdx.x, lane = t&31, w = t>>5;
    float acc[8][4];
    #pragma unroll
    for (int i=0;i<8;i++)
        #pragma unroll
        for (int k=0;k<4;k++) acc[i][k]=0.f;
    if (t<128) b3bs[t] = b3b[mbase+t];
    unsigned a_addr = smem_u32(As) + ((w*16 + (lane&15))*24 + (lane>>4)*8)*2;
    unsigned b_base = smem_u32(Bs);
    int arow = t>>1, ac8 = (t&1)*8;
    int bk = t>>4, bn0 = (t&15)*4;
    for (int r=0;r<9;r++){
        int dy=r/3-1, dx=r%3-1, yy=y+dy;
        bool rowok = (yy>=0 && yy<H_);
        int yc = rowok ? yy : 0;
        for (int kc=0;kc<16;kc++){
            *(uint4*)&As[arow*24+ac8] =
                *(const uint4*)(d_w4t + ((size_t)(r*256 + mbase + arow))*256 + kc*16 + ac8);
            {
                const __half* src = d_x16 + ((size_t)(b*C_ + kc*16 + bk)*H_ + yc)*W_;
                __align__(8) __half tmp[4];
                #pragma unroll
                for (int j=0;j<4;j++){
                    int cx = bn0+j+dx;
                    tmp[j] = (rowok && cx>=0 && cx<W_) ? src[cx] : __float2half(0.f);
                }
                unsigned grp = (unsigned)(bn0>>3) ^ (unsigned)(bk&7);
                *(uint2*)((char*)Bs + bk*128 + grp*16 + (bn0&7)*2) = *(uint2*)tmp;
            }
            __syncthreads();
            unsigned a0,a1,a2,a3; ldsm4(a_addr,a0,a1,a2,a3);
            #pragma unroll
            for (int j=0;j<4;j++){
                unsigned g0 = (unsigned)(j*2 + (lane>>4)) ^ (unsigned)(lane&7);
                unsigned b0,b1,b2,b3;
                ldsm4t(b_base + (lane&15)*128 + g0*16, b0,b1,b2,b3);
                mma16816(acc[j*2],   a0,a1,a2,a3, b0,b1);
                mma16816(acc[j*2+1], a0,a1,a2,a3, b2,b3);
            }
            __syncthreads();
        }
    }
    int g=lane>>2, tig=lane&3;
    int o0 = w*16+g, o1 = o0+8;
    #pragma unroll
    for (int nt=0;nt<8;nt++){
        int n = nt*8 + tig*2;
        if (n < W_){
            __half2 lo = __floats2half2_rn(acc[nt][0]+b3bs[o0], acc[nt][1]+b3bs[o0]);
            __half2 hi = __floats2half2_rn(acc[nt][2]+b3bs[o1], acc[nt][3]+b3bs[o1]);
            *(__half2*)&d_x4[((size_t)(b*C_+mbase+o0)*H_+y)*W_ + n] = lo;
            *(__half2*)&d_x4[((size_t)(b*C_+mbase+o1)*H_+y)*W_ + n] = hi;
        }
    }
}

__global__ void __launch_bounds__(224) k_mean4(){
    __shared__ float red[4][56];
    int y = blockIdx.x, b = blockIdx.y;
    int t = threadIdx.x, cl = t/56, j = t%56;
    float s = 0.f;
    for (int c = cl; c < C_; c += 4)
        s += __half2float(d_x4[((size_t)(b*C_+c)*H_+y)*W_ + j]);
    red[cl][j] = s;
    __syncthreads();
    if (cl==0)
        d_s4[(size_t)b*HW_ + y*W_ + j] = (red[0][j]+red[1][j]+red[2][j]+red[3][j])*(1.0f/C_);
}

__global__ void __launch_bounds__(224) k_pass3(const float* __restrict__ x){
    __shared__ float s3red[4][56];
    int y = blockIdx.x, b = blockIdx.y;
    int t = threadIdx.x, cl = t/56, j = t%56;
    float s3acc = 0.f;
    for (int gi=0;gi<2;gi++){
        int g = cl*2+gi, bg = b*G_+g;
        float t2 = 0.f;
        #pragma unroll 4
        for (int ci=0;ci<CG_;ci++){
            int ch = b*C_ + g*CG_ + ci;
            float xv = x[(size_t)ch*HW_ + y*W_ + j];
            float x0 = xv * d_sh[ch*H_+y] * d_sw[ch*W_+j];
            s3acc += x0 * d_rbstd[g*CG_+ci];
            t2 += d_A1[ch]*x0;
        }
        d_w1[(size_t)bg*HW_ + y*W_ + j] += t2 + d_C1[bg];
    }
    s3red[cl][j] = s3acc;
    __syncthreads();
    if (cl==0)
        d_s3[(size_t)b*HW_ + y*W_ + j] =
            (s3red[0][j]+s3red[1][j]+s3red[2][j]+s3red[3][j])*(1.0f/C_);
}

__global__ void __launch_bounds__(256) k_softmax(){
    int row = blockIdx.x;
    float* p = (row < B_) ? (d_s3 + (size_t)row*HW_) : (d_s4 + (size_t)(row-B_)*HW_);
    __shared__ float red[8];
    int t = threadIdx.x, lane = t&31, wid = t>>5;
    float mx = -1e30f;
    for (int i=t;i<HW_;i+=256) mx = fmaxf(mx, p[i]);
    #pragma unroll
    for (int s=16;s;s>>=1) mx = fmaxf(mx, __shfl_xor_sync(~0u,mx,s));
    if (lane==0) red[wid]=mx;
    __syncthreads();
    mx = red[0];
    #pragma unroll
    for (int i=1;i<8;i++) mx = fmaxf(mx, red[i]);
    __syncthreads();
    float sum = 0.f;
    for (int i=t;i<HW_;i+=256){ float e = expf(p[i]-mx); p[i]=e; sum += e; }
    #pragma unroll
    for (int s=16;s;s>>=1) sum += __shfl_xor_sync(~0u,sum,s);
    if (lane==0) red[wid]=sum;
    __syncthreads();
    sum = 0.f;
    #pragma unroll
    for (int i=0;i<8;i++) sum += red[i];
    float inv = 1.0f/sum;
    for (int i=t;i<HW_;i+=256) p[i] *= inv;
}

__global__ void __launch_bounds__(128) k_wfin(const float* __restrict__ x){
    __shared__ float r1s[4], r2s[4];
    int c = blockIdx.x, b = blockIdx.y, ch = b*C_+c;
    int t = threadIdx.x;
    const float* xp  = x + (size_t)ch*HW_;
    const __half* x4p = d_x4 + (size_t)ch*HW_;
    const float* s3p = d_s3 + (size_t)b*HW_;
    const float* s4p = d_s4 + (size_t)b*HW_;
    const float* shp = d_sh + ch*H_;
    const float* swp = d_sw + ch*W_;
    float u = 0.f, t4 = 0.f;
    for (int i=t;i<HW_;i+=128){
        float x0 = xp[i]*shp[i/W_]*swp[i%W_];
        u  += s4p[i]*x0;
        t4 += s3p[i]*__half2float(x4p[i]);
    }
    int lane = t&31, wid = t>>5;
    #pragma unroll
    for (int s=16;s;s>>=1){ u += __shfl_xor_sync(~0u,u,s); t4 += __shfl_xor_sync(~0u,t4,s); }
    if (lane==0){ r1s[wid]=u; r2s[wid]=t4; }
    __syncthreads();
    if (t==0){
        u  = r1s[0]+r1s[1]+r1s[2]+r1s[3];
        t4 = r2s[0]+r2s[1]+r2s[2]+r2s[3];
        float w2 = t4 + d_rbstd[c]*(u - d_bm[c]);
        d_sw2[ch] = sigf(w2);
    }
}

__global__ void __launch_bounds__(256) k_out(const float* __restrict__ x, float* __restrict__ out){
    size_t i = ((size_t)blockIdx.x*256 + threadIdx.x)*4;
    int p = (int)(i % HW_);
    int ch = (int)(i / HW_);
    int b = ch >> 8, c = ch & 255;
    int bg = b*G_ + (c>>5);
    float4 xv = *(const float4*)(x+i);
    const float* w1p = d_w1 + (size_t)bg*HW_ + p;
    float s2 = d_sw2[ch];
    float4 o;
    o.x = xv.x*(sigf(w1p[0]) + s2);
    o.y = xv.y*(sigf(w1p[1]) + s2);
    o.z = xv.z*(sigf(w1p[2]) + s2);
    o.w = xv.w*(sigf(w1p[3]) + s2);
    *(float4*)(out+i) = o;
}

// ---------------- launch ----------------
extern "C" void kernel_launch(void* const* d_in, const int* in_sizes, int n_in,
                              void* d_out, int out_size){
    const float* x   = (const float*)d_in[0];
    const float* w1  = (const float*)d_in[1];
    const float* b1  = (const float*)d_in[2];
    const float* w3a = (const float*)d_in[3];
    const float* b3a = (const float*)d_in[4];
    const float* w3b = (const float*)d_in[5];
    const float* b3b = (const float*)d_in[6];
    const float* gnw = (const float*)d_in[7];
    const float* gnb = (const float*)d_in[8];
    float* out = (float*)d_out;

    k_zero  <<<32, 256>>>();
    k_wprep <<<2304, 256>>>(w3b, w3a);
    k_x11   <<<1, 32>>>(gnb);
    k_rowcol<<<B_*C_, 256>>>(x);
    k_hw    <<<BG_, 128>>>(w1, b1);
    k_stats <<<B_*C_, 128>>>(x);
    k_fin   <<<32, 256>>>();
    k_conv2 <<<dim3(H_, BG_), 128>>>(b3a);
    k_x21   <<<BG_, 32>>>(gnw, gnb);
    k_conv4 <<<dim3(H_, B_, 2), 256>>>(b3b);
    k_mean4 <<<dim3(H_, B_), 224>>>();
    k_pass3 <<<dim3(H_, B_), 224>>>(x);
    k_softmax<<<64, 256>>>();
    k_wfin  <<<dim3(C_, B_), 128>>>(x);
    k_out   <<<25088, 256>>>(x, out);
}

// round 3
// speedup vs baseline: 1.1303x; 1.1303x over previous
#include <cuda_runtime.h>
#include <cuda_fp16.h>
#include <math.h>

#define B_ 32
#define C_ 256
#define H_ 56
#define W_ 56
#define HW_ 3136
#define G_ 8
#define CG_ 32
#define BG_ 256
#define EPSV 1e-5f

// ---------------- static device scratch ----------------
__device__ __half d_x16[(size_t)B_*C_*HW_];   // fp16 x
__device__ __half d_x4 [(size_t)B_*C_*HW_];   // conv4 output
__device__ __half d_w4t[9*256*256];           // w3b -> [r][o][i]
__device__ __half d_w2t[9*32*32];             // w3a -> [r][o][i]
__device__ float d_xhm[BG_*CG_*H_], d_xwm[BG_*CG_*W_];
__device__ float d_sh [BG_*CG_*H_], d_sw [BG_*CG_*W_];
__device__ float d_chsum[BG_*CG_], d_chsq[BG_*CG_];
__device__ float d_mu[BG_*CG_], d_rstd[BG_*CG_];
__device__ float d_bm[C_], d_rbstd[C_];
__device__ float d_x11[CG_];
__device__ float d_m2[BG_*CG_];
__device__ float d_A1[BG_*CG_], d_C1[BG_];
__device__ float d_w1[(size_t)BG_*HW_];
__device__ float d_s3[(size_t)B_*HW_], d_s4[(size_t)B_*HW_];
__device__ float d_sw2[B_*C_];

// ---------------- helpers ----------------
__device__ __forceinline__ unsigned smem_u32(const void* p){
    return (unsigned)__cvta_generic_to_shared(p);
}
__device__ __forceinline__ void ldsm4(unsigned a, unsigned &r0, unsigned &r1, unsigned &r2, unsigned &r3){
    asm volatile("ldmatrix.sync.aligned.m8n8.x4.shared.b16 {%0,%1,%2,%3},[%4];\n"
        : "=r"(r0),"=r"(r1),"=r"(r2),"=r"(r3) : "r"(a));
}
__device__ __forceinline__ void ldsm4t(unsigned a, unsigned &r0, unsigned &r1, unsigned &r2, unsigned &r3){
    asm volatile("ldmatrix.sync.aligned.m8n8.x4.trans.shared.b16 {%0,%1,%2,%3},[%4];\n"
        : "=r"(r0),"=r"(r1),"=r"(r2),"=r"(r3) : "r"(a));
}
__device__ __forceinline__ void mma16816(float* c, unsigned a0, unsigned a1, unsigned a2, unsigned a3,
                                         unsigned b0, unsigned b1){
    asm volatile("mma.sync.aligned.m16n8k16.row.col.f32.f16.f16.f32 "
        "{%0,%1,%2,%3}, {%4,%5,%6,%7}, {%8,%9}, {%0,%1,%2,%3};\n"
        : "+f"(c[0]),"+f"(c[1]),"+f"(c[2]),"+f"(c[3])
        : "r"(a0),"r"(a1),"r"(a2),"r"(a3),"r"(b0),"r"(b1));
}
__device__ __forceinline__ float sigf(float v){ return 1.f/(1.f+expf(-v)); }

// ---------------- small kernels ----------------
__global__ void k_zero(){
    int i = blockIdx.x*blockDim.x + threadIdx.x;
    if (i < BG_*CG_) d_m2[i] = 0.f;
    if (i < B_*HW_)  d_s4[i] = 0.f;
}

__global__ void k_wprep(const float* __restrict__ w3b, const float* __restrict__ w3a){
    int j = blockIdx.x*blockDim.x + threadIdx.x;
    if (j < 256*256*9){
        int o = j/2304, ic = (j/9)%256, r = j%9;
        d_w4t[(r*256+o)*256+ic] = __float2half(w3b[j]);
    }
    if (j < 32*32*9){
        int o = j/288, ic = (j/9)%32, r = j%9;
        d_w2t[(r*32+o)*32+ic] = __float2half(w3a[j]);
    }
}

__global__ void k_x11(const float* __restrict__ gnb){
    int t = threadIdx.x;
    float v = gnb[t], m = v;
    #pragma unroll
    for (int s=16;s;s>>=1) m = fmaxf(m, __shfl_xor_sync(~0u, m, s));
    float e = expf(v-m), sum = e;
    #pragma unroll
    for (int s=16;s;s>>=1) sum += __shfl_xor_sync(~0u, sum, s);
    d_x11[t] = e/sum;
}

__global__ void __launch_bounds__(256) k_rowcol(const float* __restrict__ x){
    __shared__ float tile[HW_];
    int ch = blockIdx.x;
    const float* src = x + (size_t)ch*HW_;
    __half2* dst = (__half2*)(d_x16 + (size_t)ch*HW_);
    for (int i = threadIdx.x*4; i < HW_; i += 1024){
        float4 v = *(const float4*)(src+i);
        tile[i]=v.x; tile[i+1]=v.y; tile[i+2]=v.z; tile[i+3]=v.w;
        dst[i>>1]     = __floats2half2_rn(v.x, v.y);
        dst[(i>>1)+1] = __floats2half2_rn(v.z, v.w);
    }
    __syncthreads();
    int t = threadIdx.x;
    if (t < H_){
        float rs = 0.f, cs = 0.f;
        #pragma unroll 8
        for (int w = 0; w < W_; w++) rs += tile[t*W_ + w];
        #pragma unroll 8
        for (int h = 0; h < H_; h++) cs += tile[h*W_ + t];
        d_xhm[ch*H_ + t] = rs * (1.0f/W_);
        d_xwm[ch*W_ + t] = cs * (1.0f/H_);
    }
}

__global__ void __launch_bounds__(128) k_hw(const float* __restrict__ w1, const float* __restrict__ b1){
    __shared__ float ws[1024], cat[32*112], bs[32];
    int bg = blockIdx.x;
    for (int i = threadIdx.x; i < 1024; i += 128) ws[i] = w1[i];
    if (threadIdx.x < 32) bs[threadIdx.x] = b1[threadIdx.x];
    for (int i = threadIdx.x; i < 32*112; i += 128){
        int c = i/112, p = i%112;
        cat[i] = (p < H_) ? d_xhm[(bg*CG_+c)*H_+p] : d_xwm[(bg*CG_+c)*W_+(p-H_)];
    }
    __syncthreads();
    for (int i = threadIdx.x; i < 32*112; i += 128){
        int o = i/112, p = i%112;
        float acc = bs[o];
        #pragma unroll 8
        for (int c = 0; c < 32; c++) acc += ws[o*32+c]*cat[c*112+p];
        float s = sigf(acc);
        if (p < H_) d_sh[(bg*CG_+o)*H_+p] = s;
        else        d_sw[(bg*CG_+o)*W_+(p-H_)] = s;
    }
}

__global__ void __launch_bounds__(128) k_stats(){
    int ch = blockIdx.x;
    const __half* src = d_x16 + (size_t)ch*HW_;
    const float* shp = d_sh + ch*H_;
    const float* swp = d_sw + ch*W_;
    float s = 0.f, q = 0.f;
    for (int i = threadIdx.x; i < HW_; i += 128){
        float v = __half2float(src[i])*shp[i/W_]*swp[i%W_];
        s += v; q += v*v;
    }
    __shared__ float ss[4], qq[4];
    int lane = threadIdx.x & 31, w = threadIdx.x >> 5;
    #pragma unroll
    for (int o=16;o;o>>=1){ s += __shfl_xor_sync(~0u,s,o); q += __shfl_xor_sync(~0u,q,o); }
    if (lane==0){ ss[w]=s; qq[w]=q; }
    __syncthreads();
    if (threadIdx.x==0){
        d_chsum[ch] = ss[0]+ss[1]+ss[2]+ss[3];
        d_chsq [ch] = qq[0]+qq[1]+qq[2]+qq[3];
    }
}

__global__ void k_fin(){
    int i = blockIdx.x*blockDim.x + threadIdx.x;
    if (i < BG_*CG_){
        float mu = d_chsum[i]*(1.0f/HW_);
        float var = d_chsq[i]*(1.0f/HW_) - mu*mu;
        d_mu[i] = mu;
        d_rstd[i] = rsqrtf(var + EPSV);
    }
    if (i < C_){
        float s = 0.f, q = 0.f;
        for (int b = 0; b < B_; b++){ s += d_chsum[b*C_+i]; q += d_chsq[b*C_+i]; }
        const float n = (float)B_*(float)HW_;
        float bm = s/n, bv = q/n - bm*bm;
        d_bm[i] = bm;
        d_rbstd[i] = rsqrtf(bv + EPSV);
    }
}

// ---------------- conv2: grouped 3x3, fused weights1 term1 + mean(x2) ----------------
__global__ void __launch_bounds__(128) k_conv2(const float* __restrict__ b3a){
    __shared__ __align__(16) __half As[32*24];
    __shared__ __align__(16) __half Bs[16*64];
    __shared__ float red[64], x11s[32], b3as[32];
    int y = blockIdx.x, bg = blockIdx.y;
    int t = threadIdx.x, lane = t&31, w = t>>5;
    int mrow = (w&1)*16, nbase = (w>>1)*32;
    float acc[4][4];
    #pragma unroll
    for (int i=0;i<4;i++)
        #pragma unroll
        for (int k=0;k<4;k++) acc[i][k]=0.f;
    if (t<32){ x11s[t]=d_x11[t]; b3as[t]=b3a[t]; }
    if (t<64) red[t]=0.f;
    unsigned a_addr = smem_u32(As) + ((mrow + (lane&15))*24 + (lane>>4)*8)*2;
    unsigned b_base = smem_u32(Bs);
    for (int r=0;r<9;r++){
        int dy=r/3-1, dx=r%3-1, yy=y+dy;
        bool rowok = (yy>=0 && yy<H_);
        int yc = rowok ? yy : 0;
        for (int kc=0;kc<2;kc++){
            if (t<64){
                int row=t>>1, c8=(t&1)*8;
                *(uint4*)&As[row*24+c8] = *(const uint4*)(d_w2t + (r*32+row)*32 + kc*16 + c8);
            }
            {
                int k=t>>3, n0=(t&7)*8;
                const __half* src = d_x16 + ((size_t)(bg*CG_ + kc*16 + k)*H_ + yc)*W_;
                __align__(16) __half tmp[8];
                #pragma unroll
                for (int j=0;j<8;j++){
                    int cx = n0+j+dx;
                    tmp[j] = (rowok && cx>=0 && cx<W_) ? src[cx] : __float2half(0.f);
                }
                unsigned grp = (unsigned)(n0>>3) ^ (unsigned)(k&7);
                *(uint4*)((char*)Bs + k*128 + grp*16) = *(uint4*)tmp;
            }
            __syncthreads();
            unsigned a0,a1,a2,a3; ldsm4(a_addr,a0,a1,a2,a3);
            #pragma unroll
            for (int j=0;j<2;j++){
                unsigned g0 = (unsigned)((nbase>>3) + j*2 + (lane>>4)) ^ (unsigned)(lane&7);
                unsigned b0,b1,b2,b3;
                ldsm4t(b_base + (lane&15)*128 + g0*16, b0,b1,b2,b3);
                mma16816(acc[j*2],   a0,a1,a2,a3, b0,b1);
                mma16816(acc[j*2+1], a0,a1,a2,a3, b2,b3);
            }
            __syncthreads();
        }
    }
    int g=lane>>2, tig=lane&3;
    int o0 = mrow+g, o1 = o0+8;
    float rs0=0.f, rs1=0.f;
    #pragma unroll
    for (int nt=0;nt<4;nt++){
        int n = nbase + nt*8 + tig*2;
        if (n < W_){
            float v0 = acc[nt][0]+b3as[o0], v1 = acc[nt][1]+b3as[o0];
            float v2 = acc[nt][2]+b3as[o1], v3 = acc[nt][3]+b3as[o1];
            atomicAdd(&red[n],   x11s[o0]*v0 + x11s[o1]*v2);
            atomicAdd(&red[n+1], x11s[o0]*v1 + x11s[o1]*v3);
            rs0 += v0+v1; rs1 += v2+v3;
        }
    }
    rs0 += __shfl_xor_sync(~0u,rs0,1); rs0 += __shfl_xor_sync(~0u,rs0,2);
    rs1 += __shfl_xor_sync(~0u,rs1,1); rs1 += __shfl_xor_sync(~0u,rs1,2);
    if (tig==0){
        atomicAdd(&d_m2[bg*CG_+o0], rs0);
        atomicAdd(&d_m2[bg*CG_+o1], rs1);
    }
    __syncthreads();
    if (t < W_) d_w1[(size_t)bg*HW_ + y*W_ + t] = red[t];
}

__global__ void k_x21(const float* __restrict__ gnw, const float* __restrict__ gnb){
    int bg = blockIdx.x, t = threadIdx.x;   // 32 threads
    float v = d_m2[bg*CG_+t]*(1.0f/HW_);
    float m = v;
    #pragma unroll
    for (int s=16;s;s>>=1) m = fmaxf(m, __shfl_xor_sync(~0u,m,s));
    float e = expf(v-m), sum = e;
    #pragma unroll
    for (int s=16;s;s>>=1) sum += __shfl_xor_sync(~0u,sum,s);
    float x21 = e/sum;
    float rs = d_rstd[bg*CG_+t], mu = d_mu[bg*CG_+t];
    d_A1[bg*CG_+t] = x21*gnw[t]*rs;
    float cc = x21*(gnb[t] - gnw[t]*rs*mu);
    #pragma unroll
    for (int s=16;s;s>>=1) cc += __shfl_xor_sync(~0u,cc,s);
    if (t==0) d_C1[bg] = cc;
}

// ---------------- conv4 v2: dense 3x3 256->256, M=128 N=128 (2 rows), double-buffered,
// fused channel-mean (d_s4 accumulation) ----------------
__global__ void __launch_bounds__(256,2) k_conv4(const float* __restrict__ b3b){
    __shared__ __align__(16) __half As[2][128*24];   // 12 KB
    __shared__ __align__(16) __half Bs[2][16*128];   //  8 KB
    __shared__ float b3bs[128];
    __shared__ float colred[128];
    int yp = blockIdx.x, b = blockIdx.y, mbase = blockIdx.z*128;
    int y0 = yp*2;
    int t = threadIdx.x, lane = t&31, w = t>>5;
    int g = lane>>2, tig = lane&3;
    float acc[16][4];
    #pragma unroll
    for (int i=0;i<16;i++)
        #pragma unroll
        for (int k=0;k<4;k++) acc[i][k]=0.f;
    if (t<128){ b3bs[t] = b3b[mbase+t]; colred[t] = 0.f; }
    int arow = t>>1, ac8 = (t&1)*8;
    int bk = t>>4, bn0 = (t&15)*8;
    int ysel = bn0>>6, bcol = bn0&63;
    unsigned aBase = smem_u32(As), bBase = smem_u32(Bs);
    unsigned aStore = (arow*24+ac8)*2;
    unsigned bStore = bk*256 + ((((unsigned)(bn0>>3)) ^ (unsigned)(bk&7))<<4);
    unsigned aLd = ((w*16+(lane&15))*24 + (lane>>4)*8)*2;

    uint4 ra, rb;
    auto pf = [&](int ks){
        int r = ks>>4, kc = ks&15;
        int dy = r/3-1, dx = r%3-1;
        ra = *(const uint4*)(d_w4t + ((size_t)(r*256 + mbase + arow))*256 + kc*16 + ac8);
        int yy = y0 + ysel + dy;
        bool rowok = (yy>=0 && yy<H_);
        const __half* src = d_x16 + ((size_t)(b*C_ + kc*16 + bk)*H_ + (rowok?yy:0))*W_;
        __align__(16) __half tmp[8];
        #pragma unroll
        for (int j=0;j<8;j++){
            int cx = bcol + j + dx;
            tmp[j] = (rowok && cx>=0 && cx<W_) ? src[cx] : __float2half(0.f);
        }
        rb = *(uint4*)tmp;
    };

    pf(0);
    int p = 0;
    for (int ks=0; ks<144; ks++){
        *(uint4*)((char*)As + p*12288/2 + aStore) = ra;   // 6144B per buffer
        *(uint4*)((char*)Bs + p*4096 + bStore) = rb;
        __syncthreads();
        if (ks < 143) pf(ks+1);
        unsigned a0,a1,a2,a3; ldsm4(aBase + p*6144 + aLd, a0,a1,a2,a3);
        #pragma unroll
        for (int j=0;j<8;j++){
            unsigned g0 = ((unsigned)(j*2 + (lane>>4))) ^ ((unsigned)(lane&7));
            unsigned b0,b1,b2,b3;
            ldsm4t(bBase + p*4096 + (lane&15)*256 + g0*16, b0,b1,b2,b3);
            mma16816(acc[j*2],   a0,a1,a2,a3, b0,b1);
            mma16816(acc[j*2+1], a0,a1,a2,a3, b2,b3);
        }
        p ^= 1;
    }

    int o0 = w*16 + g, o1 = o0 + 8;
    #pragma unroll
    for (int nt=0;nt<16;nt++){
        int n = nt*8 + tig*2;
        int yrow = y0 + (n>>6), col = n&63;
        float v0 = acc[nt][0]+b3bs[o0], v1 = acc[nt][1]+b3bs[o0];
        float v2 = acc[nt][2]+b3bs[o1], v3 = acc[nt][3]+b3bs[o1];
        float s0 = v0+v2, s1 = v1+v3;
        #pragma unroll
        for (int m=4;m<32;m<<=1){ s0 += __shfl_xor_sync(~0u,s0,m); s1 += __shfl_xor_sync(~0u,s1,m); }
        if (col < W_){
            *(__half2*)&d_x4[((size_t)(b*C_+mbase+o0)*H_+yrow)*W_ + col] = __floats2half2_rn(v0,v1);
            *(__half2*)&d_x4[((size_t)(b*C_+mbase+o1)*H_+yrow)*W_ + col] = __floats2half2_rn(v2,v3);
            if (g==0){
                atomicAdd(&colred[n],   s0);
                atomicAdd(&colred[n+1], s1);
            }
        }
    }
    __syncthreads();
    if (t < 128){
        int col = t&63, yr = y0 + (t>>6);
        if (col < W_) atomicAdd(&d_s4[(size_t)b*HW_ + yr*W_ + col], colred[t]);
    }
}

__global__ void __launch_bounds__(224) k_pass3(){
    __shared__ float s3red[4][56];
    int y = blockIdx.x, b = blockIdx.y;
    int t = threadIdx.x, cl = t/56, j = t%56;
    float s3acc = 0.f;
    for (int gi=0;gi<2;gi++){
        int g = cl*2+gi, bg = b*G_+g;
        float t2 = 0.f;
        #pragma unroll 4
        for (int ci=0;ci<CG_;ci++){
            int ch = b*C_ + g*CG_ + ci;
            float xv = __half2float(d_x16[(size_t)ch*HW_ + y*W_ + j]);
            float x0 = xv * d_sh[ch*H_+y] * d_sw[ch*W_+j];
            s3acc += x0 * d_rbstd[g*CG_+ci];
            t2 += d_A1[ch]*x0;
        }
        d_w1[(size_t)bg*HW_ + y*W_ + j] += t2 + d_C1[bg];
    }
    s3red[cl][j] = s3acc;
    __syncthreads();
    if (cl==0)
        d_s3[(size_t)b*HW_ + y*W_ + j] =
            (s3red[0][j]+s3red[1][j]+s3red[2][j]+s3red[3][j])*(1.0f/C_);
}

__global__ void __launch_bounds__(256) k_softmax(){
    int row = blockIdx.x;
    float scale = (row < B_) ? 1.0f : (1.0f/C_);
    float* p = (row < B_) ? (d_s3 + (size_t)row*HW_) : (d_s4 + (size_t)(row-B_)*HW_);
    __shared__ float red[8];
    int t = threadIdx.x, lane = t&31, wid = t>>5;
    float mx = -1e30f;
    for (int i=t;i<HW_;i+=256) mx = fmaxf(mx, p[i]*scale);
    #pragma unroll
    for (int s=16;s;s>>=1) mx = fmaxf(mx, __shfl_xor_sync(~0u,mx,s));
    if (lane==0) red[wid]=mx;
    __syncthreads();
    mx = red[0];
    #pragma unroll
    for (int i=1;i<8;i++) mx = fmaxf(mx, red[i]);
    __syncthreads();
    float sum = 0.f;
    for (int i=t;i<HW_;i+=256){ float e = expf(p[i]*scale-mx); p[i]=e; sum += e; }
    #pragma unroll
    for (int s=16;s;s>>=1) sum += __shfl_xor_sync(~0u,sum,s);
    if (lane==0) red[wid]=sum;
    __syncthreads();
    sum = 0.f;
    #pragma unroll
    for (int i=0;i<8;i++) sum += red[i];
    float inv = 1.0f/sum;
    for (int i=t;i<HW_;i+=256) p[i] *= inv;
}

__global__ void __launch_bounds__(128) k_wfin(){
    __shared__ float r1s[4], r2s[4];
    int c = blockIdx.x, b = blockIdx.y, ch = b*C_+c;
    int t = threadIdx.x;
    const __half* xp  = d_x16 + (size_t)ch*HW_;
    const __half* x4p = d_x4 + (size_t)ch*HW_;
    const float* s3p = d_s3 + (size_t)b*HW_;
    const float* s4p = d_s4 + (size_t)b*HW_;
    const float* shp = d_sh + ch*H_;
    const float* swp = d_sw + ch*W_;
    float u = 0.f, t4 = 0.f;
    for (int i=t;i<HW_;i+=128){
        float x0 = __half2float(xp[i])*shp[i/W_]*swp[i%W_];
        u  += s4p[i]*x0;
        t4 += s3p[i]*__half2float(x4p[i]);
    }
    int lane = t&31, wid = t>>5;
    #pragma unroll
    for (int s=16;s;s>>=1){ u += __shfl_xor_sync(~0u,u,s); t4 += __shfl_xor_sync(~0u,t4,s); }
    if (lane==0){ r1s[wid]=u; r2s[wid]=t4; }
    __syncthreads();
    if (t==0){
        u  = r1s[0]+r1s[1]+r1s[2]+r1s[3];
        t4 = r2s[0]+r2s[1]+r2s[2]+r2s[3];
        float w2 = t4 + d_rbstd[c]*(u - d_bm[c]);
        d_sw2[ch] = sigf(w2);
    }
}

__global__ void __launch_bounds__(256) k_out(const float* __restrict__ x, float* __restrict__ out){
    size_t i = ((size_t)blockIdx.x*256 + threadIdx.x)*4;
    int p = (int)(i % HW_);
    int ch = (int)(i / HW_);
    int b = ch >> 8, c = ch & 255;
    int bg = b*G_ + (c>>5);
    float4 xv = *(const float4*)(x+i);
    const float* w1p = d_w1 + (size_t)bg*HW_ + p;
    float s2 = d_sw2[ch];
    float4 o;
    o.x = xv.x*(sigf(w1p[0]) + s2);
    o.y = xv.y*(sigf(w1p[1]) + s2);
    o.z = xv.z*(sigf(w1p[2]) + s2);
    o.w = xv.w*(sigf(w1p[3]) + s2);
    *(float4*)(out+i) = o;
}

// ---------------- launch ----------------
extern "C" void kernel_launch(void* const* d_in, const int* in_sizes, int n_in,
                              void* d_out, int out_size){
    const float* x   = (const float*)d_in[0];
    const float* w1  = (const float*)d_in[1];
    const float* b1  = (const float*)d_in[2];
    const float* w3a = (const float*)d_in[3];
    const float* b3a = (const float*)d_in[4];
    const float* w3b = (const float*)d_in[5];
    const float* b3b = (const float*)d_in[6];
    const float* gnw = (const float*)d_in[7];
    const float* gnb = (const float*)d_in[8];
    float* out = (float*)d_out;

    k_zero  <<<392, 256>>>();
    k_wprep <<<2304, 256>>>(w3b, w3a);
    k_x11   <<<1, 32>>>(gnb);
    k_rowcol<<<B_*C_, 256>>>(x);
    k_hw    <<<BG_, 128>>>(w1, b1);
    k_stats <<<B_*C_, 128>>>();
    k_fin   <<<32, 256>>>();
    k_conv2 <<<dim3(H_, BG_), 128>>>(b3a);
    k_x21   <<<BG_, 32>>>(gnw, gnb);
    k_conv4 <<<dim3(H_/2, B_, 2), 256>>>(b3b);
    k_pass3 <<<dim3(H_, B_), 224>>>();
    k_softmax<<<64, 256>>>();
    k_wfin  <<<dim3(C_, B_), 128>>>();
    k_out   <<<25088, 256>>>(x, out);
}

// round 4
// speedup vs baseline: 1.4026x; 1.2409x over previous
#include <cuda_runtime.h>
#include <cuda_fp16.h>
#include <math.h>

#define B_ 32
#define C_ 256
#define H_ 56
#define W_ 56
#define HW_ 3136
#define G_ 8
#define CG_ 32
#define BG_ 256
#define EPSV 1e-5f

// ---------------- static device scratch ----------------
__device__ __half d_x16[(size_t)B_*C_*HW_];   // fp16 x, NCHW
__device__ __half d_xT [(size_t)B_*HW_*C_];   // fp16 x, NHWC
__device__ __half d_x4T[(size_t)B_*HW_*C_];   // conv4 output, NHWC
__device__ __half d_w4t[16*9*256*16];         // w3b -> [kc][r][o][ic]
__device__ __half d_w2t[9*32*32];             // w3a -> [r][o][i]
__device__ float d_xhm[BG_*CG_*H_], d_xwm[BG_*CG_*W_];
__device__ float d_sh [BG_*CG_*H_], d_sw [BG_*CG_*W_];
__device__ float d_chsum[BG_*CG_], d_chsq[BG_*CG_];
__device__ float d_mu[BG_*CG_], d_rstd[BG_*CG_];
__device__ float d_bm[C_], d_rbstd[C_];
__device__ float d_x11[CG_];
__device__ float d_m2[BG_*CG_];
__device__ float d_A1[BG_*CG_], d_C1[BG_];
__device__ float d_w1[(size_t)BG_*HW_];
__device__ float d_s3[(size_t)B_*HW_], d_s4[(size_t)B_*HW_];
__device__ float d_t4[B_*C_];
__device__ float d_sw2[B_*C_];

// ---------------- helpers ----------------
__device__ __forceinline__ unsigned smem_u32(const void* p){
    return (unsigned)__cvta_generic_to_shared(p);
}
__device__ __forceinline__ void ldsm4(unsigned a, unsigned &r0, unsigned &r1, unsigned &r2, unsigned &r3){
    asm volatile("ldmatrix.sync.aligned.m8n8.x4.shared.b16 {%0,%1,%2,%3},[%4];\n"
        : "=r"(r0),"=r"(r1),"=r"(r2),"=r"(r3) : "r"(a));
}
__device__ __forceinline__ void ldsm4t(unsigned a, unsigned &r0, unsigned &r1, unsigned &r2, unsigned &r3){
    asm volatile("ldmatrix.sync.aligned.m8n8.x4.trans.shared.b16 {%0,%1,%2,%3},[%4];\n"
        : "=r"(r0),"=r"(r1),"=r"(r2),"=r"(r3) : "r"(a));
}
__device__ __forceinline__ void mma16816(float* c, unsigned a0, unsigned a1, unsigned a2, unsigned a3,
                                         unsigned b0, unsigned b1){
    asm volatile("mma.sync.aligned.m16n8k16.row.col.f32.f16.f16.f32 "
        "{%0,%1,%2,%3}, {%4,%5,%6,%7}, {%8,%9}, {%0,%1,%2,%3};\n"
        : "+f"(c[0]),"+f"(c[1]),"+f"(c[2]),"+f"(c[3])
        : "r"(a0),"r"(a1),"r"(a2),"r"(a3),"r"(b0),"r"(b1));
}
__device__ __forceinline__ float sigf(float v){ return 1.f/(1.f+expf(-v)); }

// ---------------- small kernels ----------------
__global__ void k_zero(){
    int i = blockIdx.x*blockDim.x + threadIdx.x;
    if (i < BG_*CG_) d_m2[i] = 0.f;
    if (i < B_*HW_)  d_s4[i] = 0.f;
    if (i < B_*C_)   d_t4[i] = 0.f;
}

__global__ void k_wprep(const float* __restrict__ w3b, const float* __restrict__ w3a){
    int j = blockIdx.x*blockDim.x + threadIdx.x;
    if (j < 256*256*9){
        int o = j/2304, icF = (j/9)%256, r = j%9;
        int kc = icF>>4, ic = icF&15;
        d_w4t[(((size_t)kc*9 + r)*256 + o)*16 + ic] = __float2half(w3b[j]);
    }
    if (j < 32*32*9){
        int o = j/288, ic = (j/9)%32, r = j%9;
        d_w2t[(r*32+o)*32+ic] = __float2half(w3a[j]);
    }
}

__global__ void k_x11(const float* __restrict__ gnb){
    int t = threadIdx.x;
    float v = gnb[t], m = v;
    #pragma unroll
    for (int s=16;s;s>>=1) m = fmaxf(m, __shfl_xor_sync(~0u, m, s));
    float e = expf(v-m), sum = e;
    #pragma unroll
    for (int s=16;s;s>>=1) sum += __shfl_xor_sync(~0u, sum, s);
    d_x11[t] = e/sum;
}

__global__ void __launch_bounds__(256) k_rowcol(const float* __restrict__ x){
    __shared__ float tile[HW_];
    int ch = blockIdx.x;
    const float* src = x + (size_t)ch*HW_;
    __half2* dst = (__half2*)(d_x16 + (size_t)ch*HW_);
    for (int i = threadIdx.x*4; i < HW_; i += 1024){
        float4 v = *(const float4*)(src+i);
        tile[i]=v.x; tile[i+1]=v.y; tile[i+2]=v.z; tile[i+3]=v.w;
        dst[i>>1]     = __floats2half2_rn(v.x, v.y);
        dst[(i>>1)+1] = __floats2half2_rn(v.z, v.w);
    }
    __syncthreads();
    int t = threadIdx.x;
    if (t < H_){
        float rs = 0.f, cs = 0.f;
        #pragma unroll 8
        for (int w = 0; w < W_; w++) rs += tile[t*W_ + w];
        #pragma unroll 8
        for (int h = 0; h < H_; h++) cs += tile[h*W_ + t];
        d_xhm[ch*H_ + t] = rs * (1.0f/W_);
        d_xwm[ch*W_ + t] = cs * (1.0f/H_);
    }
}

// NCHW fp32 -> NHWC fp16 transpose (16 pixels x 256 channels per block)
__global__ void __launch_bounds__(256) k_tr(const float* __restrict__ x){
    __shared__ __half sm[16*256];
    int b = blockIdx.y, p0 = blockIdx.x*16;
    int t = threadIdx.x;
    const float* src = x + (size_t)(b*C_ + t)*HW_ + p0;
    #pragma unroll
    for (int i=0;i<16;i+=4){
        float4 v = *(const float4*)(src+i);
        sm[(i+0)*256 + t] = __float2half(v.x);
        sm[(i+1)*256 + t] = __float2half(v.y);
        sm[(i+2)*256 + t] = __float2half(v.z);
        sm[(i+3)*256 + t] = __float2half(v.w);
    }
    __syncthreads();
    __half* dst = d_xT + ((size_t)b*HW_ + p0)*256;
    #pragma unroll
    for (int k=0;k<2;k++){
        int idx = t + k*256;
        int px = idx>>5, cc = (idx&31)*8;
        *(uint4*)&dst[(size_t)px*256 + cc] = *(uint4*)&sm[px*256+cc];
    }
}

__global__ void __launch_bounds__(128) k_hw(const float* __restrict__ w1, const float* __restrict__ b1){
    __shared__ float ws[1024], cat[32*112], bs[32];
    int bg = blockIdx.x;
    for (int i = threadIdx.x; i < 1024; i += 128) ws[i] = w1[i];
    if (threadIdx.x < 32) bs[threadIdx.x] = b1[threadIdx.x];
    for (int i = threadIdx.x; i < 32*112; i += 128){
        int c = i/112, p = i%112;
        cat[i] = (p < H_) ? d_xhm[(bg*CG_+c)*H_+p] : d_xwm[(bg*CG_+c)*W_+(p-H_)];
    }
    __syncthreads();
    for (int i = threadIdx.x; i < 32*112; i += 128){
        int o = i/112, p = i%112;
        float acc = bs[o];
        #pragma unroll 8
        for (int c = 0; c < 32; c++) acc += ws[o*32+c]*cat[c*112+p];
        float s = sigf(acc);
        if (p < H_) d_sh[(bg*CG_+o)*H_+p] = s;
        else        d_sw[(bg*CG_+o)*W_+(p-H_)] = s;
    }
}

__global__ void __launch_bounds__(128) k_stats(){
    int ch = blockIdx.x;
    const __half* src = d_x16 + (size_t)ch*HW_;
    const float* shp = d_sh + ch*H_;
    const float* swp = d_sw + ch*W_;
    float s = 0.f, q = 0.f;
    for (int i = threadIdx.x; i < HW_; i += 128){
        float v = __half2float(src[i])*shp[i/W_]*swp[i%W_];
        s += v; q += v*v;
    }
    __shared__ float ss[4], qq[4];
    int lane = threadIdx.x & 31, w = threadIdx.x >> 5;
    #pragma unroll
    for (int o=16;o;o>>=1){ s += __shfl_xor_sync(~0u,s,o); q += __shfl_xor_sync(~0u,q,o); }
    if (lane==0){ ss[w]=s; qq[w]=q; }
    __syncthreads();
    if (threadIdx.x==0){
        d_chsum[ch] = ss[0]+ss[1]+ss[2]+ss[3];
        d_chsq [ch] = qq[0]+qq[1]+qq[2]+qq[3];
    }
}

__global__ void k_fin(){
    int i = blockIdx.x*blockDim.x + threadIdx.x;
    if (i < BG_*CG_){
        float mu = d_chsum[i]*(1.0f/HW_);
        float var = d_chsq[i]*(1.0f/HW_) - mu*mu;
        d_mu[i] = mu;
        d_rstd[i] = rsqrtf(var + EPSV);
    }
    if (i < C_){
        float s = 0.f, q = 0.f;
        for (int b = 0; b < B_; b++){ s += d_chsum[b*C_+i]; q += d_chsq[b*C_+i]; }
        const float n = (float)B_*(float)HW_;
        float bm = s/n, bv = q/n - bm*bm;
        d_bm[i] = bm;
        d_rbstd[i] = rsqrtf(bv + EPSV);
    }
}

// ---------------- conv2: grouped 3x3, fused weights1 term1 + mean(x2) ----------------
__global__ void __launch_bounds__(128) k_conv2(const float* __restrict__ b3a){
    __shared__ __align__(16) __half As[32*24];
    __shared__ __align__(16) __half Bs[16*64];
    __shared__ float red[64], x11s[32], b3as[32];
    int y = blockIdx.x, bg = blockIdx.y;
    int t = threadIdx.x, lane = t&31, w = t>>5;
    int mrow = (w&1)*16, nbase = (w>>1)*32;
    float acc[4][4];
    #pragma unroll
    for (int i=0;i<4;i++)
        #pragma unroll
        for (int k=0;k<4;k++) acc[i][k]=0.f;
    if (t<32){ x11s[t]=d_x11[t]; b3as[t]=b3a[t]; }
    if (t<64) red[t]=0.f;
    unsigned a_addr = smem_u32(As) + ((mrow + (lane&15))*24 + (lane>>4)*8)*2;
    unsigned b_base = smem_u32(Bs);
    for (int r=0;r<9;r++){
        int dy=r/3-1, dx=r%3-1, yy=y+dy;
        bool rowok = (yy>=0 && yy<H_);
        int yc = rowok ? yy : 0;
        for (int kc=0;kc<2;kc++){
            if (t<64){
                int row=t>>1, c8=(t&1)*8;
                *(uint4*)&As[row*24+c8] = *(const uint4*)(d_w2t + (r*32+row)*32 + kc*16 + c8);
            }
            {
                int k=t>>3, n0=(t&7)*8;
                const __half* src = d_x16 + ((size_t)(bg*CG_ + kc*16 + k)*H_ + yc)*W_;
                __align__(16) __half tmp[8];
                #pragma unroll
                for (int j=0;j<8;j++){
                    int cx = n0+j+dx;
                    tmp[j] = (rowok && cx>=0 && cx<W_) ? src[cx] : __float2half(0.f);
                }
                unsigned grp = (unsigned)(n0>>3) ^ (unsigned)(k&7);
                *(uint4*)((char*)Bs + k*128 + grp*16) = *(uint4*)tmp;
            }
            __syncthreads();
            unsigned a0,a1,a2,a3; ldsm4(a_addr,a0,a1,a2,a3);
            #pragma unroll
            for (int j=0;j<2;j++){
                unsigned g0 = (unsigned)((nbase>>3) + j*2 + (lane>>4)) ^ (unsigned)(lane&7);
                unsigned b0,b1,b2,b3;
                ldsm4t(b_base + (lane&15)*128 + g0*16, b0,b1,b2,b3);
                mma16816(acc[j*2],   a0,a1,a2,a3, b0,b1);
                mma16816(acc[j*2+1], a0,a1,a2,a3, b2,b3);
            }
            __syncthreads();
        }
    }
    int g=lane>>2, tig=lane&3;
    int o0 = mrow+g, o1 = o0+8;
    float rs0=0.f, rs1=0.f;
    #pragma unroll
    for (int nt=0;nt<4;nt++){
        int n = nbase + nt*8 + tig*2;
        if (n < W_){
            float v0 = acc[nt][0]+b3as[o0], v1 = acc[nt][1]+b3as[o0];
            float v2 = acc[nt][2]+b3as[o1], v3 = acc[nt][3]+b3as[o1];
            atomicAdd(&red[n],   x11s[o0]*v0 + x11s[o1]*v2);
            atomicAdd(&red[n+1], x11s[o0]*v1 + x11s[o1]*v3);
            rs0 += v0+v1; rs1 += v2+v3;
        }
    }
    rs0 += __shfl_xor_sync(~0u,rs0,1); rs0 += __shfl_xor_sync(~0u,rs0,2);
    rs1 += __shfl_xor_sync(~0u,rs1,1); rs1 += __shfl_xor_sync(~0u,rs1,2);
    if (tig==0){
        atomicAdd(&d_m2[bg*CG_+o0], rs0);
        atomicAdd(&d_m2[bg*CG_+o1], rs1);
    }
    __syncthreads();
    if (t < W_) d_w1[(size_t)bg*HW_ + y*W_ + t] = red[t];
}

__global__ void k_x21(const float* __restrict__ gnw, const float* __restrict__ gnb){
    int bg = blockIdx.x, t = threadIdx.x;   // 32 threads
    float v = d_m2[bg*CG_+t]*(1.0f/HW_);
    float m = v;
    #pragma unroll
    for (int s=16;s;s>>=1) m = fmaxf(m, __shfl_xor_sync(~0u,m,s));
    float e = expf(v-m), sum = e;
    #pragma unroll
    for (int s=16;s;s>>=1) sum += __shfl_xor_sync(~0u,sum,s);
    float x21 = e/sum;
    float rs = d_rstd[bg*CG_+t], mu = d_mu[bg*CG_+t];
    d_A1[bg*CG_+t] = x21*gnw[t]*rs;
    float cc = x21*(gnb[t] - gnw[t]*rs*mu);
    #pragma unroll
    for (int s=16;s;s>>=1) cc += __shfl_xor_sync(~0u,cc,s);
    if (t==0) d_C1[bg] = cc;
}

// ---------------- conv4 v3: NHWC implicit GEMM, 9-tap smem reuse, cp.async pipeline ----------------
// block: (yp, b, z) -> out rows y0..y0+1 (M=128 pixels: 2x64), out channels mbase..mbase+127
// A tile (input): [4 rows][66 cols][16 ch] halves = 8448 B per buffer
// W tile: [9 r][128 o][16 ic] halves = 36864 B per buffer. Double buffered: 90624 B dynamic smem.
#define A_BUF 8448
#define W_BUF 36864
#define W_OFF 16896
__global__ void __launch_bounds__(256,2) k_conv4(const float* __restrict__ b3b){
    extern __shared__ __align__(16) char dsm[];
    __shared__ float b3bs[128];
    __shared__ float colred[128];
    int y0 = blockIdx.x*2, b = blockIdx.y, mbase = blockIdx.z*128;
    int t = threadIdx.x, lane = t&31, w = t>>5;
    unsigned smB = smem_u32(dsm);
    if (t<128){ b3bs[t] = b3b[mbase+t]; colred[t]=0.f; }
    float acc[16][4];
    #pragma unroll
    for (int i=0;i<16;i++){ acc[i][0]=0.f; acc[i][1]=0.f; acc[i][2]=0.f; acc[i][3]=0.f; }

    int colm = (w*16 + (lane&15)) & 63;     // pixel col of this lane's A row
    int yrow_w = w>>2;                       // 0 or 1
    unsigned hi16 = (unsigned)((lane>>4)*16);
    unsigned bo = (unsigned)((((lane&7) + ((lane>>4)<<3))*32) + (((lane>>3)&1)*16));
    const __half* xTb = d_xT + (size_t)b*HW_*256;
    const __half* wkc0 = d_w4t + (size_t)mbase*16;

    // issue cp.async loads of k-chunk kc into buffer pb
    auto issue = [&](int kc, int pb){
        unsigned Ab = smB + (unsigned)(pb*A_BUF);
        for (int ga = t; ga < 528; ga += 256){
            int p = ga>>1, h = ga&1;
            int arow = p/66, acol = p - arow*66;
            int yy = y0 - 1 + arow, cx = acol - 1;
            bool v = (yy>=0 && yy<H_ && cx>=0 && cx<W_);
            const __half* src = xTb + ((size_t)((v?yy:0)*W_ + (v?cx:0)))*256 + kc*16 + h*8;
            unsigned dst = Ab + (unsigned)(p*32 + h*16);
            int ss = v?16:0;
            asm volatile("cp.async.cg.shared.global [%0], [%1], 16, %2;\n"
                         :: "r"(dst), "l"(src), "r"(ss) : "memory");
        }
        unsigned Wb = smB + (unsigned)(W_OFF + pb*W_BUF);
        const __half* wsrc = d_w4t + ((size_t)kc*9*256 + mbase)*16 + t*8;
        #pragma unroll
        for (int r=0;r<9;r++){
            unsigned dst = Wb + (unsigned)(r*4096 + t*16);
            asm volatile("cp.async.cg.shared.global [%0], [%1], 16;\n"
                         :: "r"(dst), "l"(wsrc + (size_t)r*4096) : "memory");
        }
        asm volatile("cp.async.commit_group;\n" ::: "memory");
    };

    issue(0, 0);
    for (int kc=0; kc<16; kc++){
        int pb = kc&1;
        if (kc<15){
            issue(kc+1, pb^1);
            asm volatile("cp.async.wait_group 1;\n" ::: "memory");
        } else {
            asm volatile("cp.async.wait_group 0;\n" ::: "memory");
        }
        __syncthreads();
        unsigned Ab = smB + (unsigned)(pb*A_BUF);
        unsigned Wb = smB + (unsigned)(W_OFF + pb*W_BUF);
        #pragma unroll
        for (int r=0;r<9;r++){
            int dy = r/3 - 1, dx = r - (r/3)*3 - 1;
            unsigned a_addr = Ab + (unsigned)((((yrow_w+1+dy)*66) + colm + 1 + dx)*32) + hi16;
            unsigned a0,a1,a2,a3; ldsm4(a_addr, a0,a1,a2,a3);
            unsigned wr = Wb + (unsigned)(r*4096) + bo;
            #pragma unroll
            for (int j=0;j<8;j++){
                unsigned b0,b1,b2,b3; ldsm4(wr + (unsigned)(j*512), b0,b1,b2,b3);
                mma16816(acc[2*j],   a0,a1,a2,a3, b0,b1);
                mma16816(acc[2*j+1], a0,a1,a2,a3, b2,b3);
            }
        }
        __syncthreads();
    }

    // epilogue: store x4 NHWC + per-pixel channel sums (for mean(x4))
    int pr = lane>>2, c2 = (lane&3)*2;
    int p0 = w*16 + pr;
    int yr = p0>>6, col0 = p0&63;
    size_t pixbase0 = ((size_t)(b*HW_ + (y0+yr)*W_ + col0))*256;
    size_t pixbase1 = ((size_t)(b*HW_ + (y0+yr)*W_ + col0+8))*256;
    float psum0 = 0.f, psum1 = 0.f;
    #pragma unroll
    for (int f=0; f<16; f++){
        int nb = (f>>1)*16 + (f&1)*8;
        int occ = nb + c2;
        float v0 = acc[f][0] + b3bs[occ];
        float v1 = acc[f][1] + b3bs[occ+1];
        float v2 = acc[f][2] + b3bs[occ];
        float v3 = acc[f][3] + b3bs[occ+1];
        psum0 += v0+v1; psum1 += v2+v3;
        if (col0 < W_)   *(__half2*)&d_x4T[pixbase0 + mbase + occ] = __floats2half2_rn(v0,v1);
        if (col0+8 < W_) *(__half2*)&d_x4T[pixbase1 + mbase + occ] = __floats2half2_rn(v2,v3);
    }
    psum0 += __shfl_xor_sync(~0u,psum0,1); psum0 += __shfl_xor_sync(~0u,psum0,2);
    psum1 += __shfl_xor_sync(~0u,psum1,1); psum1 += __shfl_xor_sync(~0u,psum1,2);
    if ((lane&3)==0){
        if (col0 < W_)   atomicAdd(&colred[yr*64 + col0], psum0);
        if (col0+8 < W_) atomicAdd(&colred[yr*64 + col0+8], psum1);
    }
    __syncthreads();
    if (t < 128){
        int yy = t>>6, cc = t&63;
        if (cc < W_) atomicAdd(&d_s4[(size_t)b*HW_ + (y0+yy)*W_ + cc], colred[t]);
    }
}

__global__ void __launch_bounds__(224) k_pass3(){
    __shared__ float s3red[4][56];
    int y = blockIdx.x, b = blockIdx.y;
    int t = threadIdx.x, cl = t/56, j = t%56;
    float s3acc = 0.f;
    for (int gi=0;gi<2;gi++){
        int g = cl*2+gi, bg = b*G_+g;
        float t2 = 0.f;
        #pragma unroll 4
        for (int ci=0;ci<CG_;ci++){
            int ch = b*C_ + g*CG_ + ci;
            float xv = __half2float(d_x16[(size_t)ch*HW_ + y*W_ + j]);
            float x0 = xv * d_sh[ch*H_+y] * d_sw[ch*W_+j];
            s3acc += x0 * d_rbstd[g*CG_+ci];
            t2 += d_A1[ch]*x0;
        }
        d_w1[(size_t)bg*HW_ + y*W_ + j] += t2 + d_C1[bg];
    }
    s3red[cl][j] = s3acc;
    __syncthreads();
    if (cl==0)
        d_s3[(size_t)b*HW_ + y*W_ + j] =
            (s3red[0][j]+s3red[1][j]+s3red[2][j]+s3red[3][j])*(1.0f/C_);
}

__global__ void __launch_bounds__(256) k_softmax(){
    int row = blockIdx.x;
    float scale = (row < B_) ? 1.0f : (1.0f/C_);
    float* p = (row < B_) ? (d_s3 + (size_t)row*HW_) : (d_s4 + (size_t)(row-B_)*HW_);
    __shared__ float red[8];
    int t = threadIdx.x, lane = t&31, wid = t>>5;
    float mx = -1e30f;
    for (int i=t;i<HW_;i+=256) mx = fmaxf(mx, p[i]*scale);
    #pragma unroll
    for (int s=16;s;s>>=1) mx = fmaxf(mx, __shfl_xor_sync(~0u,mx,s));
    if (lane==0) red[wid]=mx;
    __syncthreads();
    mx = red[0];
    #pragma unroll
    for (int i=1;i<8;i++) mx = fmaxf(mx, red[i]);
    __syncthreads();
    float sum = 0.f;
    for (int i=t;i<HW_;i+=256){ float e = expf(p[i]*scale-mx); p[i]=e; sum += e; }
    #pragma unroll
    for (int s=16;s;s>>=1) sum += __shfl_xor_sync(~0u,sum,s);
    if (lane==0) red[wid]=sum;
    __syncthreads();
    sum = 0.f;
    #pragma unroll
    for (int i=0;i<8;i++) sum += red[i];
    float inv = 1.0f/sum;
    for (int i=t;i<HW_;i+=256) p[i] *= inv;
}

// t4[b][c] = sum_i s3[b][i] * x4T[b][i][c]   (coalesced over channels)
__global__ void __launch_bounds__(256) k_t4(){
    int b = blockIdx.y, i0 = blockIdx.x*224;
    int t = threadIdx.x;
    const float* s3p = d_s3 + (size_t)b*HW_ + i0;
    const __half* xp = d_x4T + ((size_t)b*HW_ + i0)*256 + t;
    float acc = 0.f;
    for (int i=0;i<224;i++)
        acc += s3p[i]*__half2float(xp[(size_t)i*256]);
    atomicAdd(&d_t4[b*C_ + t], acc);
}

__global__ void __launch_bounds__(128) k_wfin(){
    __shared__ float r1s[4];
    int c = blockIdx.x, b = blockIdx.y, ch = b*C_+c;
    int t = threadIdx.x;
    const __half* xp  = d_x16 + (size_t)ch*HW_;
    const float* s4p = d_s4 + (size_t)b*HW_;
    const float* shp = d_sh + ch*H_;
    const float* swp = d_sw + ch*W_;
    float u = 0.f;
    for (int i=t;i<HW_;i+=128){
        float x0 = __half2float(xp[i])*shp[i/W_]*swp[i%W_];
        u += s4p[i]*x0;
    }
    int lane = t&31, wid = t>>5;
    #pragma unroll
    for (int s=16;s;s>>=1) u += __shfl_xor_sync(~0u,u,s);
    if (lane==0) r1s[wid]=u;
    __syncthreads();
    if (t==0){
        u = r1s[0]+r1s[1]+r1s[2]+r1s[3];
        float w2 = d_t4[ch] + d_rbstd[c]*(u - d_bm[c]);
        d_sw2[ch] = sigf(w2);
    }
}

__global__ void __launch_bounds__(256) k_out(const float* __restrict__ x, float* __restrict__ out){
    size_t i = ((size_t)blockIdx.x*256 + threadIdx.x)*4;
    int p = (int)(i % HW_);
    int ch = (int)(i / HW_);
    int b = ch >> 8, c = ch & 255;
    int bg = b*G_ + (c>>5);
    float4 xv = *(const float4*)(x+i);
    const float* w1p = d_w1 + (size_t)bg*HW_ + p;
    float s2 = d_sw2[ch];
    float4 o;
    o.x = xv.x*(sigf(w1p[0]) + s2);
    o.y = xv.y*(sigf(w1p[1]) + s2);
    o.z = xv.z*(sigf(w1p[2]) + s2);
    o.w = xv.w*(sigf(w1p[3]) + s2);
    *(float4*)(out+i) = o;
}

// ---------------- launch ----------------
extern "C" void kernel_launch(void* const* d_in, const int* in_sizes, int n_in,
                              void* d_out, int out_size){
    const float* x   = (const float*)d_in[0];
    const float* w1  = (const float*)d_in[1];
    const float* b1  = (const float*)d_in[2];
    const float* w3a = (const float*)d_in[3];
    const float* b3a = (const float*)d_in[4];
    const float* w3b = (const float*)d_in[5];
    const float* b3b = (const float*)d_in[6];
    const float* gnw = (const float*)d_in[7];
    const float* gnb = (const float*)d_in[8];
    float* out = (float*)d_out;

    static bool attr_done = false;
    if (!attr_done){
        cudaFuncSetAttribute(k_conv4, cudaFuncAttributeMaxDynamicSharedMemorySize, 2*(A_BUF+W_BUF));
        attr_done = true;
    }

    k_zero  <<<392, 256>>>();
    k_wprep <<<2304, 256>>>(w3b, w3a);
    k_x11   <<<1, 32>>>(gnb);
    k_rowcol<<<B_*C_, 256>>>(x);
    k_tr    <<<dim3(196, B_), 256>>>(x);
    k_hw    <<<BG_, 128>>>(w1, b1);
    k_stats <<<B_*C_, 128>>>();
    k_fin   <<<32, 256>>>();
    k_conv2 <<<dim3(H_, BG_), 128>>>(b3a);
    k_x21   <<<BG_, 32>>>(gnw, gnb);
    k_conv4 <<<dim3(H_/2, B_, 2), 256, 2*(A_BUF+W_BUF)>>>(b3b);
    k_pass3 <<<dim3(H_, B_), 224>>>();
    k_softmax<<<64, 256>>>();
    k_t4    <<<dim3(14, B_), 256>>>();
    k_wfin  <<<dim3(C_, B_), 128>>>();
    k_out   <<<25088, 256>>>(x, out);
}

// round 5
// speedup vs baseline: 1.7102x; 1.2193x over previous
#include <cuda_runtime.h>
#include <cuda_fp16.h>
#include <math.h>

#define B_ 32
#define C_ 256
#define H_ 56
#define W_ 56
#define HW_ 3136
#define G_ 8
#define CG_ 32
#define BG_ 256
#define EPSV 1e-5f

// ---------------- static device scratch ----------------
__device__ __half d_x16[(size_t)B_*C_*HW_];   // fp16 x, NCHW
__device__ __half d_xT [(size_t)B_*HW_*C_];   // fp16 x, NHWC
__device__ __half d_x4T[(size_t)B_*HW_*C_];   // conv4 output, NHWC
__device__ __half d_w4t[16*9*256*16];         // w3b -> [kc][r][o][ic]
__device__ __half d_w2t[9*32*32];             // w3a -> [r][o][i]
__device__ float d_xhm[BG_*CG_*H_], d_xwm[BG_*CG_*W_];
__device__ float d_sh [BG_*CG_*H_], d_sw [BG_*CG_*W_];
__device__ float d_chsum[BG_*CG_], d_chsq[BG_*CG_];
__device__ float d_mu[BG_*CG_], d_rstd[BG_*CG_];
__device__ float d_bm[C_], d_rbstd[C_];
__device__ float d_x11[CG_];
__device__ float d_m2[BG_*CG_];
__device__ float d_A1[BG_*CG_], d_C1[BG_];
__device__ float d_w1[(size_t)BG_*HW_];
__device__ float d_s3[(size_t)B_*HW_], d_s4[(size_t)B_*HW_];
__device__ float d_t4[B_*C_];
__device__ float d_sw2[B_*C_];

// ---------------- helpers ----------------
__device__ __forceinline__ unsigned smem_u32(const void* p){
    return (unsigned)__cvta_generic_to_shared(p);
}
__device__ __forceinline__ void ldsm4(unsigned a, unsigned &r0, unsigned &r1, unsigned &r2, unsigned &r3){
    asm volatile("ldmatrix.sync.aligned.m8n8.x4.shared.b16 {%0,%1,%2,%3},[%4];\n"
        : "=r"(r0),"=r"(r1),"=r"(r2),"=r"(r3) : "r"(a));
}
__device__ __forceinline__ void ldsm4t(unsigned a, unsigned &r0, unsigned &r1, unsigned &r2, unsigned &r3){
    asm volatile("ldmatrix.sync.aligned.m8n8.x4.trans.shared.b16 {%0,%1,%2,%3},[%4];\n"
        : "=r"(r0),"=r"(r1),"=r"(r2),"=r"(r3) : "r"(a));
}
__device__ __forceinline__ void mma16816(float* c, unsigned a0, unsigned a1, unsigned a2, unsigned a3,
                                         unsigned b0, unsigned b1){
    asm volatile("mma.sync.aligned.m16n8k16.row.col.f32.f16.f16.f32 "
        "{%0,%1,%2,%3}, {%4,%5,%6,%7}, {%8,%9}, {%0,%1,%2,%3};\n"
        : "+f"(c[0]),"+f"(c[1]),"+f"(c[2]),"+f"(c[3])
        : "r"(a0),"r"(a1),"r"(a2),"r"(a3),"r"(b0),"r"(b1));
}
__device__ __forceinline__ float sigf(float v){ return 1.f/(1.f+expf(-v)); }

// ---------------- small kernels ----------------
__global__ void k_zero(){
    int i = blockIdx.x*blockDim.x + threadIdx.x;
    if (i < BG_*CG_) d_m2[i] = 0.f;
    if (i < B_*HW_)  d_s4[i] = 0.f;
    if (i < B_*C_)   d_t4[i] = 0.f;
}

__global__ void k_wprep(const float* __restrict__ w3b, const float* __restrict__ w3a){
    int j = blockIdx.x*blockDim.x + threadIdx.x;
    if (j < 256*256*9){
        int o = j/2304, icF = (j/9)%256, r = j%9;
        int kc = icF>>4, ic = icF&15;
        d_w4t[(((size_t)kc*9 + r)*256 + o)*16 + ic] = __float2half(w3b[j]);
    }
    if (j < 32*32*9){
        int o = j/288, ic = (j/9)%32, r = j%9;
        d_w2t[(r*32+o)*32+ic] = __float2half(w3a[j]);
    }
}

__global__ void k_x11(const float* __restrict__ gnb){
    int t = threadIdx.x;
    float v = gnb[t], m = v;
    #pragma unroll
    for (int s=16;s;s>>=1) m = fmaxf(m, __shfl_xor_sync(~0u, m, s));
    float e = expf(v-m), sum = e;
    #pragma unroll
    for (int s=16;s;s>>=1) sum += __shfl_xor_sync(~0u, sum, s);
    d_x11[t] = e/sum;
}

__global__ void __launch_bounds__(256) k_rowcol(const float* __restrict__ x){
    __shared__ float tile[HW_];
    int ch = blockIdx.x;
    const float* src = x + (size_t)ch*HW_;
    __half2* dst = (__half2*)(d_x16 + (size_t)ch*HW_);
    for (int i = threadIdx.x*4; i < HW_; i += 1024){
        float4 v = *(const float4*)(src+i);
        tile[i]=v.x; tile[i+1]=v.y; tile[i+2]=v.z; tile[i+3]=v.w;
        dst[i>>1]     = __floats2half2_rn(v.x, v.y);
        dst[(i>>1)+1] = __floats2half2_rn(v.z, v.w);
    }
    __syncthreads();
    int t = threadIdx.x;
    if (t < H_){
        float rs = 0.f, cs = 0.f;
        #pragma unroll 8
        for (int w = 0; w < W_; w++) rs += tile[t*W_ + w];
        #pragma unroll 8
        for (int h = 0; h < H_; h++) cs += tile[h*W_ + t];
        d_xhm[ch*H_ + t] = rs * (1.0f/W_);
        d_xwm[ch*W_ + t] = cs * (1.0f/H_);
    }
}

// NCHW fp32 -> NHWC fp16 transpose (16 pixels x 256 channels per block)
__global__ void __launch_bounds__(256) k_tr(const float* __restrict__ x){
    __shared__ __half sm[16*256];
    int b = blockIdx.y, p0 = blockIdx.x*16;
    int t = threadIdx.x;
    const float* src = x + (size_t)(b*C_ + t)*HW_ + p0;
    #pragma unroll
    for (int i=0;i<16;i+=4){
        float4 v = *(const float4*)(src+i);
        sm[(i+0)*256 + t] = __float2half(v.x);
        sm[(i+1)*256 + t] = __float2half(v.y);
        sm[(i+2)*256 + t] = __float2half(v.z);
        sm[(i+3)*256 + t] = __float2half(v.w);
    }
    __syncthreads();
    __half* dst = d_xT + ((size_t)b*HW_ + p0)*256;
    #pragma unroll
    for (int k=0;k<2;k++){
        int idx = t + k*256;
        int px = idx>>5, cc = (idx&31)*8;
        *(uint4*)&dst[(size_t)px*256 + cc] = *(uint4*)&sm[px*256+cc];
    }
}

__global__ void __launch_bounds__(128) k_hw(const float* __restrict__ w1, const float* __restrict__ b1){
    __shared__ float ws[1024], cat[32*112], bs[32];
    int bg = blockIdx.x;
    for (int i = threadIdx.x; i < 1024; i += 128) ws[i] = w1[i];
    if (threadIdx.x < 32) bs[threadIdx.x] = b1[threadIdx.x];
    for (int i = threadIdx.x; i < 32*112; i += 128){
        int c = i/112, p = i%112;
        cat[i] = (p < H_) ? d_xhm[(bg*CG_+c)*H_+p] : d_xwm[(bg*CG_+c)*W_+(p-H_)];
    }
    __syncthreads();
    for (int i = threadIdx.x; i < 32*112; i += 128){
        int o = i/112, p = i%112;
        float acc = bs[o];
        #pragma unroll 8
        for (int c = 0; c < 32; c++) acc += ws[o*32+c]*cat[c*112+p];
        float s = sigf(acc);
        if (p < H_) d_sh[(bg*CG_+o)*H_+p] = s;
        else        d_sw[(bg*CG_+o)*W_+(p-H_)] = s;
    }
}

__global__ void __launch_bounds__(128) k_stats(){
    int ch = blockIdx.x;
    const __half* src = d_x16 + (size_t)ch*HW_;
    const float* shp = d_sh + ch*H_;
    const float* swp = d_sw + ch*W_;
    float s = 0.f, q = 0.f;
    for (int i = threadIdx.x; i < HW_; i += 128){
        float v = __half2float(src[i])*shp[i/W_]*swp[i%W_];
        s += v; q += v*v;
    }
    __shared__ float ss[4], qq[4];
    int lane = threadIdx.x & 31, w = threadIdx.x >> 5;
    #pragma unroll
    for (int o=16;o;o>>=1){ s += __shfl_xor_sync(~0u,s,o); q += __shfl_xor_sync(~0u,q,o); }
    if (lane==0){ ss[w]=s; qq[w]=q; }
    __syncthreads();
    if (threadIdx.x==0){
        d_chsum[ch] = ss[0]+ss[1]+ss[2]+ss[3];
        d_chsq [ch] = qq[0]+qq[1]+qq[2]+qq[3];
    }
}

__global__ void k_fin(){
    int i = blockIdx.x*blockDim.x + threadIdx.x;
    if (i < BG_*CG_){
        float mu = d_chsum[i]*(1.0f/HW_);
        float var = d_chsq[i]*(1.0f/HW_) - mu*mu;
        d_mu[i] = mu;
        d_rstd[i] = rsqrtf(var + EPSV);
    }
    if (i < C_){
        float s = 0.f, q = 0.f;
        for (int b = 0; b < B_; b++){ s += d_chsum[b*C_+i]; q += d_chsq[b*C_+i]; }
        const float n = (float)B_*(float)HW_;
        float bm = s/n, bv = q/n - bm*bm;
        d_bm[i] = bm;
        d_rbstd[i] = rsqrtf(bv + EPSV);
    }
}

// ---------------- conv2: grouped 3x3, fused weights1 term1 + mean(x2) ----------------
__global__ void __launch_bounds__(128) k_conv2(const float* __restrict__ b3a){
    __shared__ __align__(16) __half As[32*24];
    __shared__ __align__(16) __half Bs[16*64];
    __shared__ float red[64], x11s[32], b3as[32];
    int y = blockIdx.x, bg = blockIdx.y;
    int t = threadIdx.x, lane = t&31, w = t>>5;
    int mrow = (w&1)*16, nbase = (w>>1)*32;
    float acc[4][4];
    #pragma unroll
    for (int i=0;i<4;i++)
        #pragma unroll
        for (int k=0;k<4;k++) acc[i][k]=0.f;
    if (t<32){ x11s[t]=d_x11[t]; b3as[t]=b3a[t]; }
    if (t<64) red[t]=0.f;
    unsigned a_addr = smem_u32(As) + ((mrow + (lane&15))*24 + (lane>>4)*8)*2;
    unsigned b_base = smem_u32(Bs);
    for (int r=0;r<9;r++){
        int dy=r/3-1, dx=r%3-1, yy=y+dy;
        bool rowok = (yy>=0 && yy<H_);
        int yc = rowok ? yy : 0;
        for (int kc=0;kc<2;kc++){
            if (t<64){
                int row=t>>1, c8=(t&1)*8;
                *(uint4*)&As[row*24+c8] = *(const uint4*)(d_w2t + (r*32+row)*32 + kc*16 + c8);
            }
            {
                int k=t>>3, n0=(t&7)*8;
                const __half* src = d_x16 + ((size_t)(bg*CG_ + kc*16 + k)*H_ + yc)*W_;
                __align__(16) __half tmp[8];
                #pragma unroll
                for (int j=0;j<8;j++){
                    int cx = n0+j+dx;
                    tmp[j] = (rowok && cx>=0 && cx<W_) ? src[cx] : __float2half(0.f);
                }
                unsigned grp = (unsigned)(n0>>3) ^ (unsigned)(k&7);
                *(uint4*)((char*)Bs + k*128 + grp*16) = *(uint4*)tmp;
            }
            __syncthreads();
            unsigned a0,a1,a2,a3; ldsm4(a_addr,a0,a1,a2,a3);
            #pragma unroll
            for (int j=0;j<2;j++){
                unsigned g0 = (unsigned)((nbase>>3) + j*2 + (lane>>4)) ^ (unsigned)(lane&7);
                unsigned b0,b1,b2,b3;
                ldsm4t(b_base + (lane&15)*128 + g0*16, b0,b1,b2,b3);
                mma16816(acc[j*2],   a0,a1,a2,a3, b0,b1);
                mma16816(acc[j*2+1], a0,a1,a2,a3, b2,b3);
            }
            __syncthreads();
        }
    }
    int g=lane>>2, tig=lane&3;
    int o0 = mrow+g, o1 = o0+8;
    float rs0=0.f, rs1=0.f;
    #pragma unroll
    for (int nt=0;nt<4;nt++){
        int n = nbase + nt*8 + tig*2;
        if (n < W_){
            float v0 = acc[nt][0]+b3as[o0], v1 = acc[nt][1]+b3as[o0];
            float v2 = acc[nt][2]+b3as[o1], v3 = acc[nt][3]+b3as[o1];
            atomicAdd(&red[n],   x11s[o0]*v0 + x11s[o1]*v2);
            atomicAdd(&red[n+1], x11s[o0]*v1 + x11s[o1]*v3);
            rs0 += v0+v1; rs1 += v2+v3;
        }
    }
    rs0 += __shfl_xor_sync(~0u,rs0,1); rs0 += __shfl_xor_sync(~0u,rs0,2);
    rs1 += __shfl_xor_sync(~0u,rs1,1); rs1 += __shfl_xor_sync(~0u,rs1,2);
    if (tig==0){
        atomicAdd(&d_m2[bg*CG_+o0], rs0);
        atomicAdd(&d_m2[bg*CG_+o1], rs1);
    }
    __syncthreads();
    if (t < W_) d_w1[(size_t)bg*HW_ + y*W_ + t] = red[t];
}

__global__ void k_x21(const float* __restrict__ gnw, const float* __restrict__ gnb){
    int bg = blockIdx.x, t = threadIdx.x;   // 32 threads
    float v = d_m2[bg*CG_+t]*(1.0f/HW_);
    float m = v;
    #pragma unroll
    for (int s=16;s;s>>=1) m = fmaxf(m, __shfl_xor_sync(~0u,m,s));
    float e = expf(v-m), sum = e;
    #pragma unroll
    for (int s=16;s;s>>=1) sum += __shfl_xor_sync(~0u,sum,s);
    float x21 = e/sum;
    float rs = d_rstd[bg*CG_+t], mu = d_mu[bg*CG_+t];
    d_A1[bg*CG_+t] = x21*gnw[t]*rs;
    float cc = x21*(gnb[t] - gnw[t]*rs*mu);
    #pragma unroll
    for (int s=16;s;s>>=1) cc += __shfl_xor_sync(~0u,cc,s);
    if (t==0) d_C1[bg] = cc;
}

// ---------------- conv4 v4: NHWC implicit GEMM, M=256 pixels (4 rows), N=128, K=16x(9x16)
// A tile: [6 rows][66 cols][16 ch] = 12672 B/buf; W tile: [9 r][128 o][16 ic] = 36864 B/buf
// double buffered: 99072 B dynamic smem, 1 block/SM
#define A_BUF 12672
#define W_BUF 36864
#define W_OFF 25344
__global__ void __launch_bounds__(256) k_conv4(const float* __restrict__ b3b){
    extern __shared__ __align__(16) char dsm[];
    __shared__ float b3bs[128];
    __shared__ float colred[256];
    int y0 = blockIdx.x*4, b = blockIdx.y, mbase = blockIdx.z*128;
    int t = threadIdx.x, lane = t&31, w = t>>5;
    unsigned smB = smem_u32(dsm);
    if (t<128) b3bs[t] = b3b[mbase+t];
    colred[t] = 0.f;
    float acc[2][16][4];
    #pragma unroll
    for (int tt=0;tt<2;tt++)
        #pragma unroll
        for (int i=0;i<16;i++){ acc[tt][i][0]=0.f; acc[tt][i][1]=0.f; acc[tt][i][2]=0.f; acc[tt][i][3]=0.f; }

    int colm = (w*16 + (lane&15)) & 63;     // pixel col (same for both tiles)
    int yw0 = w>>2;                          // tile0 row (0/1), tile1 = yw0+2
    unsigned hi16 = (unsigned)((lane>>4)*16);
    unsigned bo = (unsigned)((((lane&7) + ((lane>>4)<<3))*32) + (((lane>>3)&1)*16));
    const __half* xTb = d_xT + (size_t)b*HW_*256;

    auto issue = [&](int kc, int pb){
        unsigned Ab = smB + (unsigned)(pb*A_BUF);
        for (int ga = t; ga < 792; ga += 256){
            int p = ga>>1, h = ga&1;
            int arow = p/66, acol = p - arow*66;
            int yy = y0 - 1 + arow, cx = acol - 1;
            bool v = (yy>=0 && yy<H_ && cx>=0 && cx<W_);
            const __half* src = xTb + ((size_t)((v?yy:0)*W_ + (v?cx:0)))*256 + kc*16 + h*8;
            unsigned dst = Ab + (unsigned)(p*32 + h*16);
            int ss = v?16:0;
            asm volatile("cp.async.cg.shared.global [%0], [%1], 16, %2;\n"
                         :: "r"(dst), "l"(src), "r"(ss) : "memory");
        }
        unsigned Wb = smB + (unsigned)(W_OFF + pb*W_BUF);
        const __half* wsrc = d_w4t + ((size_t)kc*9*256 + mbase)*16 + t*8;
        #pragma unroll
        for (int r=0;r<9;r++){
            unsigned dst = Wb + (unsigned)(r*4096 + t*16);
            asm volatile("cp.async.cg.shared.global [%0], [%1], 16;\n"
                         :: "r"(dst), "l"(wsrc + (size_t)r*4096) : "memory");
        }
        asm volatile("cp.async.commit_group;\n" ::: "memory");
    };

    issue(0, 0);
    for (int kc=0; kc<16; kc++){
        int pb = kc&1;
        if (kc<15){
            issue(kc+1, pb^1);
            asm volatile("cp.async.wait_group 1;\n" ::: "memory");
        } else {
            asm volatile("cp.async.wait_group 0;\n" ::: "memory");
        }
        __syncthreads();
        unsigned Ab = smB + (unsigned)(pb*A_BUF);
        unsigned Wb = smB + (unsigned)(W_OFF + pb*W_BUF);
        #pragma unroll
        for (int r=0;r<9;r++){
            int dy = r/3 - 1, dx = r - (r/3)*3 - 1;
            unsigned arow_off = (unsigned)((colm + 1 + dx)*32) + hi16;
            unsigned a0,a1,a2,a3, c0,c1,c2,c3;
            ldsm4(Ab + (unsigned)((yw0+1+dy)*66*32) + arow_off, a0,a1,a2,a3);
            ldsm4(Ab + (unsigned)((yw0+3+dy)*66*32) + arow_off, c0,c1,c2,c3);
            unsigned wr = Wb + (unsigned)(r*4096) + bo;
            #pragma unroll
            for (int j=0;j<8;j++){
                unsigned b0,b1,b2,b3; ldsm4(wr + (unsigned)(j*512), b0,b1,b2,b3);
                mma16816(acc[0][2*j],   a0,a1,a2,a3, b0,b1);
                mma16816(acc[0][2*j+1], a0,a1,a2,a3, b2,b3);
                mma16816(acc[1][2*j],   c0,c1,c2,c3, b0,b1);
                mma16816(acc[1][2*j+1], c0,c1,c2,c3, b2,b3);
            }
        }
        __syncthreads();
    }

    // epilogue: store x4 NHWC + per-pixel channel sums (for mean(x4))
    int pr = lane>>2, c2 = (lane&3)*2;
    #pragma unroll
    for (int tt=0; tt<2; tt++){
        int p0 = tt*128 + w*16 + pr;
        int yr = p0>>6, col0 = p0&63;
        size_t pixbase0 = ((size_t)(b*HW_ + (y0+yr)*W_ + col0))*256;
        size_t pixbase1 = ((size_t)(b*HW_ + (y0+yr)*W_ + col0+8))*256;
        float psum0 = 0.f, psum1 = 0.f;
        #pragma unroll
        for (int f=0; f<16; f++){
            int occ = (f>>1)*16 + (f&1)*8 + c2;
            float v0 = acc[tt][f][0] + b3bs[occ];
            float v1 = acc[tt][f][1] + b3bs[occ+1];
            float v2 = acc[tt][f][2] + b3bs[occ];
            float v3 = acc[tt][f][3] + b3bs[occ+1];
            psum0 += v0+v1; psum1 += v2+v3;
            if (col0 < W_)   *(__half2*)&d_x4T[pixbase0 + mbase + occ] = __floats2half2_rn(v0,v1);
            if (col0+8 < W_) *(__half2*)&d_x4T[pixbase1 + mbase + occ] = __floats2half2_rn(v2,v3);
        }
        psum0 += __shfl_xor_sync(~0u,psum0,1); psum0 += __shfl_xor_sync(~0u,psum0,2);
        psum1 += __shfl_xor_sync(~0u,psum1,1); psum1 += __shfl_xor_sync(~0u,psum1,2);
        if ((lane&3)==0){
            if (col0 < W_)   atomicAdd(&colred[p0],   psum0);
            if (col0+8 < W_) atomicAdd(&colred[p0+8], psum1);
        }
    }
    __syncthreads();
    {
        int yy = t>>6, cc = t&63;
        if (cc < W_) atomicAdd(&d_s4[(size_t)b*HW_ + (y0+yy)*W_ + cc], colred[t]);
    }
}

__global__ void __launch_bounds__(224) k_pass3(){
    __shared__ float s3red[4][56];
    int y = blockIdx.x, b = blockIdx.y;
    int t = threadIdx.x, cl = t/56, j = t%56;
    float s3acc = 0.f;
    for (int gi=0;gi<2;gi++){
        int g = cl*2+gi, bg = b*G_+g;
        float t2 = 0.f;
        #pragma unroll 4
        for (int ci=0;ci<CG_;ci++){
            int ch = b*C_ + g*CG_ + ci;
            float xv = __half2float(d_x16[(size_t)ch*HW_ + y*W_ + j]);
            float x0 = xv * d_sh[ch*H_+y] * d_sw[ch*W_+j];
            s3acc += x0 * d_rbstd[g*CG_+ci];
            t2 += d_A1[ch]*x0;
        }
        d_w1[(size_t)bg*HW_ + y*W_ + j] += t2 + d_C1[bg];
    }
    s3red[cl][j] = s3acc;
    __syncthreads();
    if (cl==0)
        d_s3[(size_t)b*HW_ + y*W_ + j] =
            (s3red[0][j]+s3red[1][j]+s3red[2][j]+s3red[3][j])*(1.0f/C_);
}

__global__ void __launch_bounds__(256) k_softmax(){
    int row = blockIdx.x;
    float scale = (row < B_) ? 1.0f : (1.0f/C_);
    float* p = (row < B_) ? (d_s3 + (size_t)row*HW_) : (d_s4 + (size_t)(row-B_)*HW_);
    __shared__ float red[8];
    int t = threadIdx.x, lane = t&31, wid = t>>5;
    float mx = -1e30f;
    for (int i=t;i<HW_;i+=256) mx = fmaxf(mx, p[i]*scale);
    #pragma unroll
    for (int s=16;s;s>>=1) mx = fmaxf(mx, __shfl_xor_sync(~0u,mx,s));
    if (lane==0) red[wid]=mx;
    __syncthreads();
    mx = red[0];
    #pragma unroll
    for (int i=1;i<8;i++) mx = fmaxf(mx, red[i]);
    __syncthreads();
    float sum = 0.f;
    for (int i=t;i<HW_;i+=256){ float e = expf(p[i]*scale-mx); p[i]=e; sum += e; }
    #pragma unroll
    for (int s=16;s;s>>=1) sum += __shfl_xor_sync(~0u,sum,s);
    if (lane==0) red[wid]=sum;
    __syncthreads();
    sum = 0.f;
    #pragma unroll
    for (int i=0;i<8;i++) sum += red[i];
    float inv = 1.0f/sum;
    for (int i=t;i<HW_;i+=256) p[i] *= inv;
}

// t4[b][c] = sum_i s3[b][i] * x4T[b][i][c]   (coalesced over channels)
__global__ void __launch_bounds__(256) k_t4(){
    int b = blockIdx.y, i0 = blockIdx.x*224;
    int t = threadIdx.x;
    const float* s3p = d_s3 + (size_t)b*HW_ + i0;
    const __half* xp = d_x4T + ((size_t)b*HW_ + i0)*256 + t;
    float acc = 0.f;
    for (int i=0;i<224;i++)
        acc += s3p[i]*__half2float(xp[(size_t)i*256]);
    atomicAdd(&d_t4[b*C_ + t], acc);
}

__global__ void __launch_bounds__(128) k_wfin(){
    __shared__ float r1s[4];
    int c = blockIdx.x, b = blockIdx.y, ch = b*C_+c;
    int t = threadIdx.x;
    const __half* xp  = d_x16 + (size_t)ch*HW_;
    const float* s4p = d_s4 + (size_t)b*HW_;
    const float* shp = d_sh + ch*H_;
    const float* swp = d_sw + ch*W_;
    float u = 0.f;
    for (int i=t;i<HW_;i+=128){
        float x0 = __half2float(xp[i])*shp[i/W_]*swp[i%W_];
        u += s4p[i]*x0;
    }
    int lane = t&31, wid = t>>5;
    #pragma unroll
    for (int s=16;s;s>>=1) u += __shfl_xor_sync(~0u,u,s);
    if (lane==0) r1s[wid]=u;
    __syncthreads();
    if (t==0){
        u = r1s[0]+r1s[1]+r1s[2]+r1s[3];
        float w2 = d_t4[ch] + d_rbstd[c]*(u - d_bm[c]);
        d_sw2[ch] = sigf(w2);
    }
}

__global__ void __launch_bounds__(256) k_out(const float* __restrict__ x, float* __restrict__ out){
    size_t i = ((size_t)blockIdx.x*256 + threadIdx.x)*4;
    int p = (int)(i % HW_);
    int ch = (int)(i / HW_);
    int b = ch >> 8, c = ch & 255;
    int bg = b*G_ + (c>>5);
    float4 xv = *(const float4*)(x+i);
    const float* w1p = d_w1 + (size_t)bg*HW_ + p;
    float s2 = d_sw2[ch];
    float4 o;
    o.x = xv.x*(sigf(w1p[0]) + s2);
    o.y = xv.y*(sigf(w1p[1]) + s2);
    o.z = xv.z*(sigf(w1p[2]) + s2);
    o.w = xv.w*(sigf(w1p[3]) + s2);
    *(float4*)(out+i) = o;
}

// ---------------- launch ----------------
extern "C" void kernel_launch(void* const* d_in, const int* in_sizes, int n_in,
                              void* d_out, int out_size){
    const float* x   = (const float*)d_in[0];
    const float* w1  = (const float*)d_in[1];
    const float* b1  = (const float*)d_in[2];
    const float* w3a = (const float*)d_in[3];
    const float* b3a = (const float*)d_in[4];
    const float* w3b = (const float*)d_in[5];
    const float* b3b = (const float*)d_in[6];
    const float* gnw = (const float*)d_in[7];
    const float* gnb = (const float*)d_in[8];
    float* out = (float*)d_out;

    cudaFuncSetAttribute(k_conv4, cudaFuncAttributeMaxDynamicSharedMemorySize, 2*(A_BUF+W_BUF));

    // conv4 placed at launch slot 4 (the ncu-profiled slot) — deps: w4t, xT, s4-zero
    k_zero  <<<392, 256>>>();
    k_wprep <<<2304, 256>>>(w3b, w3a);
    k_tr    <<<dim3(196, B_), 256>>>(x);
    k_conv4 <<<dim3(H_/4, B_, 2), 256, 2*(A_BUF+W_BUF)>>>(b3b);
    k_x11   <<<1, 32>>>(gnb);
    k_rowcol<<<B_*C_, 256>>>(x);
    k_hw    <<<BG_, 128>>>(w1, b1);
    k_stats <<<B_*C_, 128>>>();
    k_fin   <<<32, 256>>>();
    k_conv2 <<<dim3(H_, BG_), 128>>>(b3a);
    k_x21   <<<BG_, 32>>>(gnw, gnb);
    k_pass3 <<<dim3(H_, B_), 224>>>();
    k_softmax<<<64, 256>>>();
    k_t4    <<<dim3(14, B_), 256>>>();
    k_wfin  <<<dim3(C_, B_), 128>>>();
    k_out   <<<25088, 256>>>(x, out);
}

// round 6
// speedup vs baseline: 1.8560x; 1.0852x over previous
#include <cuda_runtime.h>
#include <cuda_fp16.h>
#include <math.h>

#define B_ 32
#define C_ 256
#define H_ 56
#define W_ 56
#define HW_ 3136
#define G_ 8
#define CG_ 32
#define BG_ 256
#define EPSV 1e-5f

// ---------------- static device scratch ----------------
__device__ __half d_x16[(size_t)B_*C_*HW_];   // fp16 x, NCHW
__device__ __half d_xT [(size_t)B_*HW_*C_];   // fp16 x, NHWC
__device__ __half d_x4T[(size_t)B_*HW_*C_];   // conv4 output, NHWC
__device__ __half d_w4t[16*9*256*16];         // w3b -> [kc][r][o][ic]
__device__ __half d_w2t[9*32*32];             // w3a -> [r][o][i]
__device__ float d_xhm[BG_*CG_*H_], d_xwm[BG_*CG_*W_];
__device__ float d_sh [BG_*CG_*H_], d_sw [BG_*CG_*W_];
__device__ float d_chsum[BG_*CG_], d_chsq[BG_*CG_];
__device__ float d_mu[BG_*CG_], d_rstd[BG_*CG_];
__device__ float d_bm[C_], d_rbstd[C_];
__device__ float d_x11[CG_];
__device__ float d_m2[BG_*CG_];
__device__ float d_A1[BG_*CG_], d_C1[BG_];
__device__ float d_w1[(size_t)BG_*HW_];
__device__ float d_s3[(size_t)B_*HW_], d_s4[(size_t)B_*HW_];
__device__ float d_t4[B_*C_];
__device__ float d_sw2[B_*C_];

// ---------------- helpers ----------------
__device__ __forceinline__ unsigned smem_u32(const void* p){
    return (unsigned)__cvta_generic_to_shared(p);
}
__device__ __forceinline__ void ldsm4(unsigned a, unsigned &r0, unsigned &r1, unsigned &r2, unsigned &r3){
    asm volatile("ldmatrix.sync.aligned.m8n8.x4.shared.b16 {%0,%1,%2,%3},[%4];\n"
        : "=r"(r0),"=r"(r1),"=r"(r2),"=r"(r3) : "r"(a));
}
__device__ __forceinline__ void ldsm4t(unsigned a, unsigned &r0, unsigned &r1, unsigned &r2, unsigned &r3){
    asm volatile("ldmatrix.sync.aligned.m8n8.x4.trans.shared.b16 {%0,%1,%2,%3},[%4];\n"
        : "=r"(r0),"=r"(r1),"=r"(r2),"=r"(r3) : "r"(a));
}
__device__ __forceinline__ void mma16816(float* c, unsigned a0, unsigned a1, unsigned a2, unsigned a3,
                                         unsigned b0, unsigned b1){
    asm volatile("mma.sync.aligned.m16n8k16.row.col.f32.f16.f16.f32 "
        "{%0,%1,%2,%3}, {%4,%5,%6,%7}, {%8,%9}, {%0,%1,%2,%3};\n"
        : "+f"(c[0]),"+f"(c[1]),"+f"(c[2]),"+f"(c[3])
        : "r"(a0),"r"(a1),"r"(a2),"r"(a3),"r"(b0),"r"(b1));
}
__device__ __forceinline__ float sigf(float v){ return 1.f/(1.f+expf(-v)); }

// ---------------- small kernels ----------------
__global__ void k_zero(){
    int i = blockIdx.x*blockDim.x + threadIdx.x;
    if (i < BG_*CG_) d_m2[i] = 0.f;
    if (i < B_*HW_)  d_s4[i] = 0.f;
    if (i < B_*C_)   d_t4[i] = 0.f;
}

__global__ void k_wprep(const float* __restrict__ w3b, const float* __restrict__ w3a){
    int j = blockIdx.x*blockDim.x + threadIdx.x;
    if (j < 256*256*9){
        int o = j/2304, icF = (j/9)%256, r = j%9;
        int kc = icF>>4, ic = icF&15;
        d_w4t[(((size_t)kc*9 + r)*256 + o)*16 + ic] = __float2half(w3b[j]);
    }
    if (j < 32*32*9){
        int o = j/288, ic = (j/9)%32, r = j%9;
        d_w2t[(r*32+o)*32+ic] = __float2half(w3a[j]);
    }
}

__global__ void k_x11(const float* __restrict__ gnb){
    int t = threadIdx.x;
    float v = gnb[t], m = v;
    #pragma unroll
    for (int s=16;s;s>>=1) m = fmaxf(m, __shfl_xor_sync(~0u, m, s));
    float e = expf(v-m), sum = e;
    #pragma unroll
    for (int s=16;s;s>>=1) sum += __shfl_xor_sync(~0u, sum, s);
    d_x11[t] = e/sum;
}

__global__ void __launch_bounds__(256) k_rowcol(const float* __restrict__ x){
    __shared__ float tile[HW_];
    int ch = blockIdx.x;
    const float* src = x + (size_t)ch*HW_;
    __half2* dst = (__half2*)(d_x16 + (size_t)ch*HW_);
    for (int i = threadIdx.x*4; i < HW_; i += 1024){
        float4 v = *(const float4*)(src+i);
        tile[i]=v.x; tile[i+1]=v.y; tile[i+2]=v.z; tile[i+3]=v.w;
        dst[i>>1]     = __floats2half2_rn(v.x, v.y);
        dst[(i>>1)+1] = __floats2half2_rn(v.z, v.w);
    }
    __syncthreads();
    int t = threadIdx.x;
    if (t < H_){
        float rs = 0.f, cs = 0.f;
        #pragma unroll 8
        for (int w = 0; w < W_; w++) rs += tile[t*W_ + w];
        #pragma unroll 8
        for (int h = 0; h < H_; h++) cs += tile[h*W_ + t];
        d_xhm[ch*H_ + t] = rs * (1.0f/W_);
        d_xwm[ch*W_ + t] = cs * (1.0f/H_);
    }
}

// NCHW fp32 -> NHWC fp16 transpose (16 pixels x 256 channels per block)
__global__ void __launch_bounds__(256) k_tr(const float* __restrict__ x){
    __shared__ __half sm[16*256];
    int b = blockIdx.y, p0 = blockIdx.x*16;
    int t = threadIdx.x;
    const float* src = x + (size_t)(b*C_ + t)*HW_ + p0;
    #pragma unroll
    for (int i=0;i<16;i+=4){
        float4 v = *(const float4*)(src+i);
        sm[(i+0)*256 + t] = __float2half(v.x);
        sm[(i+1)*256 + t] = __float2half(v.y);
        sm[(i+2)*256 + t] = __float2half(v.z);
        sm[(i+3)*256 + t] = __float2half(v.w);
    }
    __syncthreads();
    __half* dst = d_xT + ((size_t)b*HW_ + p0)*256;
    #pragma unroll
    for (int k=0;k<2;k++){
        int idx = t + k*256;
        int px = idx>>5, cc = (idx&31)*8;
        *(uint4*)&dst[(size_t)px*256 + cc] = *(uint4*)&sm[px*256+cc];
    }
}

__global__ void __launch_bounds__(128) k_hw(const float* __restrict__ w1, const float* __restrict__ b1){
    __shared__ float ws[1024], cat[32*112], bs[32];
    int bg = blockIdx.x;
    for (int i = threadIdx.x; i < 1024; i += 128) ws[i] = w1[i];
    if (threadIdx.x < 32) bs[threadIdx.x] = b1[threadIdx.x];
    for (int i = threadIdx.x; i < 32*112; i += 128){
        int c = i/112, p = i%112;
        cat[i] = (p < H_) ? d_xhm[(bg*CG_+c)*H_+p] : d_xwm[(bg*CG_+c)*W_+(p-H_)];
    }
    __syncthreads();
    for (int i = threadIdx.x; i < 32*112; i += 128){
        int o = i/112, p = i%112;
        float acc = bs[o];
        #pragma unroll 8
        for (int c = 0; c < 32; c++) acc += ws[o*32+c]*cat[c*112+p];
        float s = sigf(acc);
        if (p < H_) d_sh[(bg*CG_+o)*H_+p] = s;
        else        d_sw[(bg*CG_+o)*W_+(p-H_)] = s;
    }
}

__global__ void __launch_bounds__(128) k_stats(){
    int ch = blockIdx.x;
    const __half* src = d_x16 + (size_t)ch*HW_;
    const float* shp = d_sh + ch*H_;
    const float* swp = d_sw + ch*W_;
    float s = 0.f, q = 0.f;
    for (int i = threadIdx.x; i < HW_; i += 128){
        float v = __half2float(src[i])*shp[i/W_]*swp[i%W_];
        s += v; q += v*v;
    }
    __shared__ float ss[4], qq[4];
    int lane = threadIdx.x & 31, w = threadIdx.x >> 5;
    #pragma unroll
    for (int o=16;o;o>>=1){ s += __shfl_xor_sync(~0u,s,o); q += __shfl_xor_sync(~0u,q,o); }
    if (lane==0){ ss[w]=s; qq[w]=q; }
    __syncthreads();
    if (threadIdx.x==0){
        d_chsum[ch] = ss[0]+ss[1]+ss[2]+ss[3];
        d_chsq [ch] = qq[0]+qq[1]+qq[2]+qq[3];
    }
}

__global__ void k_fin(){
    int i = blockIdx.x*blockDim.x + threadIdx.x;
    if (i < BG_*CG_){
        float mu = d_chsum[i]*(1.0f/HW_);
        float var = d_chsq[i]*(1.0f/HW_) - mu*mu;
        d_mu[i] = mu;
        d_rstd[i] = rsqrtf(var + EPSV);
    }
    if (i < C_){
        float s = 0.f, q = 0.f;
        for (int b = 0; b < B_; b++){ s += d_chsum[b*C_+i]; q += d_chsq[b*C_+i]; }
        const float n = (float)B_*(float)HW_;
        float bm = s/n, bv = q/n - bm*bm;
        d_bm[i] = bm;
        d_rbstd[i] = rsqrtf(bv + EPSV);
    }
}

// ---------------- conv2 v2: grouped 3x3, 2 output rows per block, fused w1 term1 + mean(x2) ----------------
__global__ void __launch_bounds__(256) k_conv2(const float* __restrict__ b3a){
    __shared__ __align__(16) __half As[32*24];
    __shared__ __align__(16) __half Bs[16*128];
    __shared__ float red[128], x11s[32], b3as[32];
    int y0 = blockIdx.x*2, bg = blockIdx.y;
    int t = threadIdx.x, lane = t&31, w = t>>5;
    int mrow = (w&1)*16, nbase = (w>>1)*32;   // w>>1 in 0..3 -> 32-pixel segment of 128
    float acc[4][4];
    #pragma unroll
    for (int i=0;i<4;i++)
        #pragma unroll
        for (int k=0;k<4;k++) acc[i][k]=0.f;
    if (t<32){ x11s[t]=d_x11[t]; b3as[t]=b3a[t]; }
    if (t<128) red[t]=0.f;
    unsigned a_addr = smem_u32(As) + ((mrow + (lane&15))*24 + (lane>>4)*8)*2;
    unsigned b_base = smem_u32(Bs);
    int bk = t>>4, bn0 = (t&15)*8;
    int byr = bn0>>6, bcb = bn0&63;
    for (int r=0;r<9;r++){
        int dy=r/3-1, dx=r%3-1;
        for (int kc=0;kc<2;kc++){
            if (t<64){
                int row=t>>1, c8=(t&1)*8;
                *(uint4*)&As[row*24+c8] = *(const uint4*)(d_w2t + (r*32+row)*32 + kc*16 + c8);
            }
            {
                int yy = y0 + byr + dy;
                bool rowok = (yy>=0 && yy<H_);
                const __half* src = d_x16 + ((size_t)(bg*CG_ + kc*16 + bk)*H_ + (rowok?yy:0))*W_;
                __align__(16) __half tmp[8];
                #pragma unroll
                for (int j=0;j<8;j++){
                    int cx = bcb+j+dx;
                    tmp[j] = (rowok && cx>=0 && cx<W_) ? src[cx] : __float2half(0.f);
                }
                unsigned grp = (unsigned)(bn0>>3) ^ (unsigned)(bk&7);
                *(uint4*)((char*)Bs + bk*256 + grp*16) = *(uint4*)tmp;
            }
            __syncthreads();
            unsigned a0,a1,a2,a3; ldsm4(a_addr,a0,a1,a2,a3);
            #pragma unroll
            for (int j=0;j<2;j++){
                unsigned g0 = (unsigned)((nbase>>3) + j*2 + (lane>>4)) ^ (unsigned)(lane&7);
                unsigned b0,b1,b2,b3;
                ldsm4t(b_base + (lane&15)*256 + g0*16, b0,b1,b2,b3);
                mma16816(acc[j*2],   a0,a1,a2,a3, b0,b1);
                mma16816(acc[j*2+1], a0,a1,a2,a3, b2,b3);
            }
            __syncthreads();
        }
    }
    int g=lane>>2, tig=lane&3;
    int o0 = mrow+g, o1 = o0+8;
    float rs0=0.f, rs1=0.f;
    #pragma unroll
    for (int nt=0;nt<4;nt++){
        int n = nbase + nt*8 + tig*2;
        int col = n&63;
        if (col < W_){
            float v0 = acc[nt][0]+b3as[o0], v1 = acc[nt][1]+b3as[o0];
            float v2 = acc[nt][2]+b3as[o1], v3 = acc[nt][3]+b3as[o1];
            atomicAdd(&red[n],   x11s[o0]*v0 + x11s[o1]*v2);
            atomicAdd(&red[n+1], x11s[o0]*v1 + x11s[o1]*v3);
            rs0 += v0+v1; rs1 += v2+v3;
        }
    }
    rs0 += __shfl_xor_sync(~0u,rs0,1); rs0 += __shfl_xor_sync(~0u,rs0,2);
    rs1 += __shfl_xor_sync(~0u,rs1,1); rs1 += __shfl_xor_sync(~0u,rs1,2);
    if (tig==0){
        atomicAdd(&d_m2[bg*CG_+o0], rs0);
        atomicAdd(&d_m2[bg*CG_+o1], rs1);
    }
    __syncthreads();
    if (t < 128){
        int yr = y0 + (t>>6), col = t&63;
        if (col < W_) d_w1[(size_t)bg*HW_ + yr*W_ + col] = red[t];
    }
}

__global__ void k_x21(const float* __restrict__ gnw, const float* __restrict__ gnb){
    int bg = blockIdx.x, t = threadIdx.x;   // 32 threads
    float v = d_m2[bg*CG_+t]*(1.0f/HW_);
    float m = v;
    #pragma unroll
    for (int s=16;s;s>>=1) m = fmaxf(m, __shfl_xor_sync(~0u,m,s));
    float e = expf(v-m), sum = e;
    #pragma unroll
    for (int s=16;s;s>>=1) sum += __shfl_xor_sync(~0u,sum,s);
    float x21 = e/sum;
    float rs = d_rstd[bg*CG_+t], mu = d_mu[bg*CG_+t];
    d_A1[bg*CG_+t] = x21*gnw[t]*rs;
    float cc = x21*(gnb[t] - gnw[t]*rs*mu);
    #pragma unroll
    for (int s=16;s;s>>=1) cc += __shfl_xor_sync(~0u,cc,s);
    if (t==0) d_C1[bg] = cc;
}

// ---------------- conv4 v5: NHWC implicit GEMM, M=256 px, N=128, warp grid 4Mx2N,
// XOR-swizzled smem (conflict-free ldsm), cp.async double buffer ----------------
#define A_BUF 12672
#define W_BUF 36864
#define W_OFF 25344
__global__ void __launch_bounds__(256) k_conv4(const float* __restrict__ b3b){
    extern __shared__ __align__(16) char dsm[];
    __shared__ float b3bs[128];
    __shared__ float colred[256];
    int y0 = blockIdx.x*4, b = blockIdx.y, mbase = blockIdx.z*128;
    int t = threadIdx.x, lane = t&31, w = t>>5;
    int wm = w&3, wn = w>>2;
    unsigned smB = smem_u32(dsm);
    if (t<128) b3bs[t] = b3b[mbase+t];
    colred[t] = 0.f;
    float acc[4][8][4];
    #pragma unroll
    for (int f=0;f<4;f++)
        #pragma unroll
        for (int j=0;j<8;j++){ acc[f][j][0]=0.f; acc[f][j][1]=0.f; acc[f][j][2]=0.f; acc[f][j][3]=0.f; }

    int o_l = wn*64 + (lane&7) + ((lane>>4)<<3);
    unsigned bo = (unsigned)(o_l*32 + ((((lane>>3)&1) ^ ((o_l>>2)&1))<<4));
    const __half* xTb = d_xT + (size_t)b*HW_*256;
    int wo_ = t>>1, wh_ = t&1;
    unsigned wdst = (unsigned)(wo_*32 + ((wh_ ^ ((wo_>>2)&1))<<4));

    auto issue = [&](int kc, int pb){
        unsigned Ab = smB + (unsigned)(pb*A_BUF);
        for (int ga = t; ga < 792; ga += 256){
            int p = ga>>1, h = ga&1;
            int arow = p/66, acol = p - arow*66;
            int yy = y0 - 1 + arow, cx = acol - 1;
            bool v = (yy>=0 && yy<H_ && cx>=0 && cx<W_);
            const __half* src = xTb + ((size_t)((v?yy:0)*W_ + (v?cx:0)))*256 + kc*16 + h*8;
            unsigned dst = Ab + (unsigned)(p*32 + ((h ^ ((p>>2)&1))<<4));
            int ss = v?16:0;
            asm volatile("cp.async.cg.shared.global [%0], [%1], 16, %2;\n"
                         :: "r"(dst), "l"(src), "r"(ss) : "memory");
        }
        unsigned Wb = smB + (unsigned)(W_OFF + pb*W_BUF);
        const __half* wsrc = d_w4t + ((size_t)kc*9*256 + mbase)*16 + t*8;
        #pragma unroll
        for (int r=0;r<9;r++){
            unsigned dst = Wb + (unsigned)(r*4096) + wdst;
            asm volatile("cp.async.cg.shared.global [%0], [%1], 16;\n"
                         :: "r"(dst), "l"(wsrc + (size_t)r*4096) : "memory");
        }
        asm volatile("cp.async.commit_group;\n" ::: "memory");
    };

    issue(0, 0);
    for (int kc=0; kc<16; kc++){
        int pb = kc&1;
        if (kc<15){
            issue(kc+1, pb^1);
            asm volatile("cp.async.wait_group 1;\n" ::: "memory");
        } else {
            asm volatile("cp.async.wait_group 0;\n" ::: "memory");
        }
        __syncthreads();
        unsigned Ab = smB + (unsigned)(pb*A_BUF);
        unsigned Wb = smB + (unsigned)(W_OFF + pb*W_BUF);
        #pragma unroll
        for (int r=0;r<9;r++){
            int dy = r/3 - 1, dx = r - (r/3)*3 - 1;
            unsigned wr = Wb + (unsigned)(r*4096) + bo;
            unsigned Wf[4][4];
            #pragma unroll
            for (int j=0;j<4;j++)
                ldsm4(wr + (unsigned)(j*512), Wf[j][0],Wf[j][1],Wf[j][2],Wf[j][3]);
            int rowbase = (wm+1+dy)*66 + 1 + dx;
            #pragma unroll
            for (int f=0;f<4;f++){
                unsigned P = (unsigned)(rowbase + f*16 + (lane&15));
                unsigned a_addr = Ab + P*32 + ((((unsigned)(lane>>4)) ^ ((P>>2)&1))<<4);
                unsigned a0,a1,a2,a3; ldsm4(a_addr, a0,a1,a2,a3);
                #pragma unroll
                for (int j=0;j<4;j++){
                    mma16816(acc[f][2*j],   a0,a1,a2,a3, Wf[j][0],Wf[j][1]);
                    mma16816(acc[f][2*j+1], a0,a1,a2,a3, Wf[j][2],Wf[j][3]);
                }
            }
        }
        __syncthreads();
    }

    // epilogue: x4T NHWC stores + per-pixel channel sums
    int pr = lane>>2, c2 = (lane&3)*2;
    size_t ybase = (size_t)b*HW_ + (size_t)(y0+wm)*W_;
    #pragma unroll
    for (int f=0;f<4;f++){
        int p0 = f*16 + pr, p1 = p0 + 8;
        float ps0 = 0.f, ps1 = 0.f;
        #pragma unroll
        for (int jj=0;jj<8;jj++){
            int chl = wn*64 + (jj>>1)*16 + (jj&1)*8 + c2;
            float v0 = acc[f][jj][0]+b3bs[chl], v1 = acc[f][jj][1]+b3bs[chl+1];
            float v2 = acc[f][jj][2]+b3bs[chl], v3 = acc[f][jj][3]+b3bs[chl+1];
            ps0 += v0+v1; ps1 += v2+v3;
            if (p0 < W_) *(__half2*)&d_x4T[(ybase+p0)*256 + mbase + chl] = __floats2half2_rn(v0,v1);
            if (p1 < W_) *(__half2*)&d_x4T[(ybase+p1)*256 + mbase + chl] = __floats2half2_rn(v2,v3);
        }
        ps0 += __shfl_xor_sync(~0u,ps0,1); ps0 += __shfl_xor_sync(~0u,ps0,2);
        ps1 += __shfl_xor_sync(~0u,ps1,1); ps1 += __shfl_xor_sync(~0u,ps1,2);
        if ((lane&3)==0){
            if (p0 < W_) atomicAdd(&colred[wm*64+p0], ps0);
            if (p1 < W_) atomicAdd(&colred[wm*64+p1], ps1);
        }
    }
    __syncthreads();
    {
        int yy = t>>6, cc = t&63;
        if (cc < W_) atomicAdd(&d_s4[(size_t)b*HW_ + (y0+yy)*W_ + cc], colred[t]);
    }
}

__global__ void __launch_bounds__(224) k_pass3(){
    __shared__ float s3red[4][56];
    int y = blockIdx.x, b = blockIdx.y;
    int t = threadIdx.x, cl = t/56, j = t%56;
    float s3acc = 0.f;
    for (int gi=0;gi<2;gi++){
        int g = cl*2+gi, bg = b*G_+g;
        float t2 = 0.f;
        #pragma unroll 4
        for (int ci=0;ci<CG_;ci++){
            int ch = b*C_ + g*CG_ + ci;
            float xv = __half2float(d_x16[(size_t)ch*HW_ + y*W_ + j]);
            float x0 = xv * d_sh[ch*H_+y] * d_sw[ch*W_+j];
            s3acc += x0 * d_rbstd[g*CG_+ci];
            t2 += d_A1[ch]*x0;
        }
        d_w1[(size_t)bg*HW_ + y*W_ + j] += t2 + d_C1[bg];
    }
    s3red[cl][j] = s3acc;
    __syncthreads();
    if (cl==0)
        d_s3[(size_t)b*HW_ + y*W_ + j] =
            (s3red[0][j]+s3red[1][j]+s3red[2][j]+s3red[3][j])*(1.0f/C_);
}

__global__ void __launch_bounds__(256) k_softmax(){
    int row = blockIdx.x;
    float scale = (row < B_) ? 1.0f : (1.0f/C_);
    float* p = (row < B_) ? (d_s3 + (size_t)row*HW_) : (d_s4 + (size_t)(row-B_)*HW_);
    __shared__ float red[8];
    int t = threadIdx.x, lane = t&31, wid = t>>5;
    float mx = -1e30f;
    for (int i=t;i<HW_;i+=256) mx = fmaxf(mx, p[i]*scale);
    #pragma unroll
    for (int s=16;s;s>>=1) mx = fmaxf(mx, __shfl_xor_sync(~0u,mx,s));
    if (lane==0) red[wid]=mx;
    __syncthreads();
    mx = red[0];
    #pragma unroll
    for (int i=1;i<8;i++) mx = fmaxf(mx, red[i]);
    __syncthreads();
    float sum = 0.f;
    for (int i=t;i<HW_;i+=256){ float e = expf(p[i]*scale-mx); p[i]=e; sum += e; }
    #pragma unroll
    for (int s=16;s;s>>=1) sum += __shfl_xor_sync(~0u,sum,s);
    if (lane==0) red[wid]=sum;
    __syncthreads();
    sum = 0.f;
    #pragma unroll
    for (int i=0;i<8;i++) sum += red[i];
    float inv = 1.0f/sum;
    for (int i=t;i<HW_;i+=256) p[i] *= inv;
}

// t4[b][c] = sum_i s3[b][i] * x4T[b][i][c]
__global__ void __launch_bounds__(256) k_t4(){
    int b = blockIdx.y, i0 = blockIdx.x*224;
    int t = threadIdx.x;
    const float* s3p = d_s3 + (size_t)b*HW_ + i0;
    const __half* xp = d_x4T + ((size_t)b*HW_ + i0)*256 + t;
    float acc = 0.f;
    for (int i=0;i<224;i++)
        acc += s3p[i]*__half2float(xp[(size_t)i*256]);
    atomicAdd(&d_t4[b*C_ + t], acc);
}

__global__ void __launch_bounds__(128) k_wfin(){
    __shared__ float r1s[4];
    int c = blockIdx.x, b = blockIdx.y, ch = b*C_+c;
    int t = threadIdx.x;
    const __half* xp  = d_x16 + (size_t)ch*HW_;
    const float* s4p = d_s4 + (size_t)b*HW_;
    const float* shp = d_sh + ch*H_;
    const float* swp = d_sw + ch*W_;
    float u = 0.f;
    for (int i=t;i<HW_;i+=128){
        float x0 = __half2float(xp[i])*shp[i/W_]*swp[i%W_];
        u += s4p[i]*x0;
    }
    int lane = t&31, wid = t>>5;
    #pragma unroll
    for (int s=16;s;s>>=1) u += __shfl_xor_sync(~0u,u,s);
    if (lane==0) r1s[wid]=u;
    __syncthreads();
    if (t==0){
        u = r1s[0]+r1s[1]+r1s[2]+r1s[3];
        float w2 = d_t4[ch] + d_rbstd[c]*(u - d_bm[c]);
        d_sw2[ch] = sigf(w2);
    }
}

__global__ void __launch_bounds__(256) k_out(const float* __restrict__ x, float* __restrict__ out){
    size_t i = ((size_t)blockIdx.x*256 + threadIdx.x)*4;
    int p = (int)(i % HW_);
    int ch = (int)(i / HW_);
    int b = ch >> 8, c = ch & 255;
    int bg = b*G_ + (c>>5);
    float4 xv = *(const float4*)(x+i);
    const float* w1p = d_w1 + (size_t)bg*HW_ + p;
    float s2 = d_sw2[ch];
    float4 o;
    o.x = xv.x*(sigf(w1p[0]) + s2);
    o.y = xv.y*(sigf(w1p[1]) + s2);
    o.z = xv.z*(sigf(w1p[2]) + s2);
    o.w = xv.w*(sigf(w1p[3]) + s2);
    *(float4*)(out+i) = o;
}

// ---------------- launch ----------------
extern "C" void kernel_launch(void* const* d_in, const int* in_sizes, int n_in,
                              void* d_out, int out_size){
    const float* x   = (const float*)d_in[0];
    const float* w1  = (const float*)d_in[1];
    const float* b1  = (const float*)d_in[2];
    const float* w3a = (const float*)d_in[3];
    const float* b3a = (const float*)d_in[4];
    const float* w3b = (const float*)d_in[5];
    const float* b3b = (const float*)d_in[6];
    const float* gnw = (const float*)d_in[7];
    const float* gnb = (const float*)d_in[8];
    float* out = (float*)d_out;

    cudaFuncSetAttribute(k_conv4, cudaFuncAttributeMaxDynamicSharedMemorySize, 2*(A_BUF+W_BUF));

    // conv4 kept at launch index 3 (the ncu-profiled slot)
    k_zero  <<<392, 256>>>();
    k_wprep <<<2304, 256>>>(w3b, w3a);
    k_tr    <<<dim3(196, B_), 256>>>(x);
    k_conv4 <<<dim3(H_/4, B_, 2), 256, 2*(A_BUF+W_BUF)>>>(b3b);
    k_x11   <<<1, 32>>>(gnb);
    k_rowcol<<<B_*C_, 256>>>(x);
    k_hw    <<<BG_, 128>>>(w1, b1);
    k_stats <<<B_*C_, 128>>>();
    k_fin   <<<32, 256>>>();
    k_conv2 <<<dim3(H_/2, BG_), 256>>>(b3a);
    k_x21   <<<BG_, 32>>>(gnw, gnb);
    k_pass3 <<<dim3(H_, B_), 224>>>();
    k_softmax<<<64, 256>>>();
    k_t4    <<<dim3(14, B_), 256>>>();
    k_wfin  <<<dim3(C_, B_), 128>>>();
    k_out   <<<25088, 256>>>(x, out);
}

// round 7
// speedup vs baseline: 2.4636x; 1.3274x over previous
#include <cuda_runtime.h>
#include <cuda_fp16.h>
#include <math.h>

#define B_ 32
#define C_ 256
#define H_ 56
#define W_ 56
#define HW_ 3136
#define G_ 8
#define CG_ 32
#define BG_ 256
#define EPSV 1e-5f

// ---------------- static device scratch ----------------
__device__ __half d_x16[(size_t)B_*C_*HW_];   // fp16 x, NCHW
__device__ __half d_xT [(size_t)B_*HW_*C_];   // fp16 x, NHWC
__device__ __half d_x4T[(size_t)B_*HW_*C_];   // conv4 output, NHWC
__device__ __half d_w4t[16*9*256*16];         // w3b -> [kc][r][o][ic]
__device__ __half d_w2t[9*32*32];             // w3a -> [r][o][i]
__device__ float d_xhm[BG_*CG_*H_], d_xwm[BG_*CG_*W_];
__device__ float d_sh [BG_*CG_*H_], d_sw [BG_*CG_*W_];
__device__ float d_chsum[BG_*CG_], d_chsq[BG_*CG_];
__device__ float d_mu[BG_*CG_], d_rstd[BG_*CG_];
__device__ float d_bm[C_], d_rbstd[C_];
__device__ float d_x11[CG_];
__device__ float d_m2[BG_*CG_];
__device__ float d_A1[BG_*CG_], d_C1[BG_];
__device__ float d_w1[(size_t)BG_*HW_];
__device__ float d_s3[(size_t)B_*HW_], d_s4[(size_t)B_*HW_];
__device__ float d_t4[B_*C_];
__device__ float d_sw2[B_*C_];

// ---------------- helpers ----------------
__device__ __forceinline__ unsigned smem_u32(const void* p){
    return (unsigned)__cvta_generic_to_shared(p);
}
__device__ __forceinline__ void ldsm4(unsigned a, unsigned &r0, unsigned &r1, unsigned &r2, unsigned &r3){
    asm volatile("ldmatrix.sync.aligned.m8n8.x4.shared.b16 {%0,%1,%2,%3},[%4];\n"
        : "=r"(r0),"=r"(r1),"=r"(r2),"=r"(r3) : "r"(a));
}
__device__ __forceinline__ void mma16816(float* c, unsigned a0, unsigned a1, unsigned a2, unsigned a3,
                                         unsigned b0, unsigned b1){
    asm volatile("mma.sync.aligned.m16n8k16.row.col.f32.f16.f16.f32 "
        "{%0,%1,%2,%3}, {%4,%5,%6,%7}, {%8,%9}, {%0,%1,%2,%3};\n"
        : "+f"(c[0]),"+f"(c[1]),"+f"(c[2]),"+f"(c[3])
        : "r"(a0),"r"(a1),"r"(a2),"r"(a3),"r"(b0),"r"(b1));
}
__device__ __forceinline__ float sigf(float v){ return 1.f/(1.f+expf(-v)); }

// ---------------- small kernels ----------------
__global__ void k_zero(){
    int i = blockIdx.x*blockDim.x + threadIdx.x;
    if (i < BG_*CG_) d_m2[i] = 0.f;
    if (i < B_*HW_)  d_s4[i] = 0.f;
    if (i < B_*C_)   d_t4[i] = 0.f;
}

__global__ void k_wprep(const float* __restrict__ w3b, const float* __restrict__ w3a){
    int j = blockIdx.x*blockDim.x + threadIdx.x;
    if (j < 256*256*9){
        int o = j/2304, icF = (j/9)%256, r = j%9;
        int kc = icF>>4, ic = icF&15;
        d_w4t[(((size_t)kc*9 + r)*256 + o)*16 + ic] = __float2half(w3b[j]);
    }
    if (j < 32*32*9){
        int o = j/288, ic = (j/9)%32, r = j%9;
        d_w2t[(r*32+o)*32+ic] = __float2half(w3a[j]);
    }
}

__global__ void k_x11(const float* __restrict__ gnb){
    int t = threadIdx.x;
    float v = gnb[t], m = v;
    #pragma unroll
    for (int s=16;s;s>>=1) m = fmaxf(m, __shfl_xor_sync(~0u, m, s));
    float e = expf(v-m), sum = e;
    #pragma unroll
    for (int s=16;s;s>>=1) sum += __shfl_xor_sync(~0u, sum, s);
    d_x11[t] = e/sum;
}

__global__ void __launch_bounds__(256) k_rowcol(const float* __restrict__ x){
    __shared__ float tile[HW_];
    int ch = blockIdx.x;
    const float* src = x + (size_t)ch*HW_;
    __half2* dst = (__half2*)(d_x16 + (size_t)ch*HW_);
    for (int i = threadIdx.x*4; i < HW_; i += 1024){
        float4 v = *(const float4*)(src+i);
        tile[i]=v.x; tile[i+1]=v.y; tile[i+2]=v.z; tile[i+3]=v.w;
        dst[i>>1]     = __floats2half2_rn(v.x, v.y);
        dst[(i>>1)+1] = __floats2half2_rn(v.z, v.w);
    }
    __syncthreads();
    int t = threadIdx.x;
    if (t < H_){
        float rs = 0.f, cs = 0.f;
        #pragma unroll 8
        for (int w = 0; w < W_; w++) rs += tile[t*W_ + w];
        #pragma unroll 8
        for (int h = 0; h < H_; h++) cs += tile[h*W_ + t];
        d_xhm[ch*H_ + t] = rs * (1.0f/W_);
        d_xwm[ch*W_ + t] = cs * (1.0f/H_);
    }
}

// NCHW fp32 -> NHWC fp16 transpose
__global__ void __launch_bounds__(256) k_tr(const float* __restrict__ x){
    __shared__ __half sm[16*256];
    int b = blockIdx.y, p0 = blockIdx.x*16;
    int t = threadIdx.x;
    const float* src = x + (size_t)(b*C_ + t)*HW_ + p0;
    #pragma unroll
    for (int i=0;i<16;i+=4){
        float4 v = *(const float4*)(src+i);
        sm[(i+0)*256 + t] = __float2half(v.x);
        sm[(i+1)*256 + t] = __float2half(v.y);
        sm[(i+2)*256 + t] = __float2half(v.z);
        sm[(i+3)*256 + t] = __float2half(v.w);
    }
    __syncthreads();
    __half* dst = d_xT + ((size_t)b*HW_ + p0)*256;
    #pragma unroll
    for (int k=0;k<2;k++){
        int idx = t + k*256;
        int px = idx>>5, cc = (idx&31)*8;
        *(uint4*)&dst[(size_t)px*256 + cc] = *(uint4*)&sm[px*256+cc];
    }
}

__global__ void __launch_bounds__(128) k_hw(const float* __restrict__ w1, const float* __restrict__ b1){
    __shared__ float ws[1024], cat[32*112], bs[32];
    int bg = blockIdx.x;
    for (int i = threadIdx.x; i < 1024; i += 128) ws[i] = w1[i];
    if (threadIdx.x < 32) bs[threadIdx.x] = b1[threadIdx.x];
    for (int i = threadIdx.x; i < 32*112; i += 128){
        int c = i/112, p = i%112;
        cat[i] = (p < H_) ? d_xhm[(bg*CG_+c)*H_+p] : d_xwm[(bg*CG_+c)*W_+(p-H_)];
    }
    __syncthreads();
    for (int i = threadIdx.x; i < 32*112; i += 128){
        int o = i/112, p = i%112;
        float acc = bs[o];
        #pragma unroll 8
        for (int c = 0; c < 32; c++) acc += ws[o*32+c]*cat[c*112+p];
        float s = sigf(acc);
        if (p < H_) d_sh[(bg*CG_+o)*H_+p] = s;
        else        d_sw[(bg*CG_+o)*W_+(p-H_)] = s;
    }
}

__global__ void __launch_bounds__(128) k_stats(){
    int ch = blockIdx.x;
    const __half* src = d_x16 + (size_t)ch*HW_;
    const float* shp = d_sh + ch*H_;
    const float* swp = d_sw + ch*W_;
    float s = 0.f, q = 0.f;
    for (int i = threadIdx.x; i < HW_; i += 128){
        float v = __half2float(src[i])*shp[i/W_]*swp[i%W_];
        s += v; q += v*v;
    }
    __shared__ float ss[4], qq[4];
    int lane = threadIdx.x & 31, w = threadIdx.x >> 5;
    #pragma unroll
    for (int o=16;o;o>>=1){ s += __shfl_xor_sync(~0u,s,o); q += __shfl_xor_sync(~0u,q,o); }
    if (lane==0){ ss[w]=s; qq[w]=q; }
    __syncthreads();
    if (threadIdx.x==0){
        d_chsum[ch] = ss[0]+ss[1]+ss[2]+ss[3];
        d_chsq [ch] = qq[0]+qq[1]+qq[2]+qq[3];
    }
}

__global__ void k_fin(){
    int i = blockIdx.x*blockDim.x + threadIdx.x;
    if (i < BG_*CG_){
        float mu = d_chsum[i]*(1.0f/HW_);
        float var = d_chsq[i]*(1.0f/HW_) - mu*mu;
        d_mu[i] = mu;
        d_rstd[i] = rsqrtf(var + EPSV);
    }
    if (i < C_){
        float s = 0.f, q = 0.f;
        for (int b = 0; b < B_; b++){ s += d_chsum[b*C_+i]; q += d_chsq[b*C_+i]; }
        const float n = (float)B_*(float)HW_;
        float bm = s/n, bv = q/n - bm*bm;
        d_bm[i] = bm;
        d_rbstd[i] = rsqrtf(bv + EPSV);
    }
}

// ---------------- conv2 v3: NHWC grouped 3x3, whole-tap smem staging, 1 sync ----------------
// block: (yq, bg) -> rows y0..y0+3 of group bg. A: [6 rows][66 px][32 ch] stride 80B; W: [9][32 o][32 ic] stride 80B
#define A2_BUF 31680
#define W2_OFF 31680
#define C2_DYN (31680+23040)
__global__ void __launch_bounds__(256) k_conv2(const float* __restrict__ b3a){
    extern __shared__ __align__(16) char dsm2[];
    __shared__ float red[256], x11s[32], b3as[32];
    int y0 = blockIdx.x*4, bg = blockIdx.y;
    int b = bg>>3, g = bg&7;
    int t = threadIdx.x, lane = t&31, w = t>>5;
    int wm = w&3, wn = w>>2;
    unsigned smB = smem_u32(dsm2);
    if (t<32){ x11s[t]=d_x11[t]; b3as[t]=b3a[t]; }
    red[t] = 0.f;

    // stage A (1584 chunks) and W (1152 chunks)
    const __half* xTb = d_xT + (size_t)b*HW_*256 + g*32;
    for (int ga = t; ga < 1584; ga += 256){
        int p = ga>>2, h = ga&3;
        int arow = p/66, acol = p - arow*66;
        int yy = y0 - 1 + arow, cx = acol - 1;
        bool v = (yy>=0 && yy<H_ && cx>=0 && cx<W_);
        const __half* src = xTb + ((size_t)((v?yy:0)*W_ + (v?cx:0)))*256 + h*8;
        unsigned dst = smB + (unsigned)(p*80 + h*16);
        int ss = v?16:0;
        asm volatile("cp.async.cg.shared.global [%0], [%1], 16, %2;\n"
                     :: "r"(dst), "l"(src), "r"(ss) : "memory");
    }
    for (int ga = t; ga < 1152; ga += 256){
        int r = ga>>7, rem = ga&127, o = rem>>2, h = rem&3;
        const __half* src = d_w2t + (r*32+o)*32 + h*8;
        unsigned dst = smB + (unsigned)(W2_OFF + r*2560 + o*80 + h*16);
        asm volatile("cp.async.cg.shared.global [%0], [%1], 16;\n"
                     :: "r"(dst), "l"(src) : "memory");
    }
    asm volatile("cp.async.commit_group;\ncp.async.wait_group 0;\n" ::: "memory");
    __syncthreads();

    float acc[4][2][4];
    #pragma unroll
    for (int f=0;f<4;f++)
        #pragma unroll
        for (int j=0;j<2;j++){ acc[f][j][0]=0.f; acc[f][j][1]=0.f; acc[f][j][2]=0.f; acc[f][j][3]=0.f; }

    int o_l = wn*16 + (lane&7) + ((lane>>4)<<3);
    unsigned wofs = (unsigned)(W2_OFF + o_l*80 + ((lane>>3)&1)*16);
    #pragma unroll
    for (int r=0;r<9;r++){
        int dy = r/3 - 1, dx = r - (r/3)*3 - 1;
        int rowbase = (wm+1+dy)*66 + 1 + dx;
        #pragma unroll
        for (int kc=0;kc<2;kc++){
            unsigned b0,b1,b2,b3;
            ldsm4(smB + wofs + (unsigned)(r*2560 + kc*32), b0,b1,b2,b3);
            #pragma unroll
            for (int f=0;f<4;f++){
                int P = rowbase + f*16 + (lane&15);
                unsigned a0,a1,a2,a3;
                ldsm4(smB + (unsigned)(P*80 + kc*32 + (lane>>4)*16), a0,a1,a2,a3);
                mma16816(acc[f][0], a0,a1,a2,a3, b0,b1);
                mma16816(acc[f][1], a0,a1,a2,a3, b2,b3);
            }
        }
    }

    // epilogue
    int pr = lane>>2, c2 = (lane&3)*2;
    float m2a[4] = {0.f,0.f,0.f,0.f};
    #pragma unroll
    for (int f=0;f<4;f++){
        int p0 = f*16 + pr, p1 = p0 + 8;
        float w0 = 0.f, w1v = 0.f;
        #pragma unroll
        for (int jj=0;jj<2;jj++){
            int chl = wn*16 + jj*8 + c2;
            float bb0 = b3as[chl], bb1 = b3as[chl+1];
            float v0 = acc[f][jj][0]+bb0, v1 = acc[f][jj][1]+bb1;
            float v2 = acc[f][jj][2]+bb0, v3 = acc[f][jj][3]+bb1;
            if (p0 < W_){ w0  += x11s[chl]*v0 + x11s[chl+1]*v1; m2a[jj*2] += v0; m2a[jj*2+1] += v1; }
            if (p1 < W_){ w1v += x11s[chl]*v2 + x11s[chl+1]*v3; m2a[jj*2] += v2; m2a[jj*2+1] += v3; }
        }
        w0  += __shfl_xor_sync(~0u,w0,1);  w0  += __shfl_xor_sync(~0u,w0,2);
        w1v += __shfl_xor_sync(~0u,w1v,1); w1v += __shfl_xor_sync(~0u,w1v,2);
        if ((lane&3)==0){
            if (p0 < W_) atomicAdd(&red[wm*64+p0], w0);
            if (p1 < W_) atomicAdd(&red[wm*64+p1], w1v);
        }
    }
    #pragma unroll
    for (int k=0;k<4;k++){
        m2a[k] += __shfl_xor_sync(~0u,m2a[k],4);
        m2a[k] += __shfl_xor_sync(~0u,m2a[k],8);
        m2a[k] += __shfl_xor_sync(~0u,m2a[k],16);
    }
    if (pr==0 && (lane>>3)==0){
        #pragma unroll
        for (int k=0;k<4;k++){
            int chl = wn*16 + (k>>1)*8 + c2 + (k&1);
            atomicAdd(&d_m2[bg*CG_ + chl], m2a[k]);
        }
    }
    __syncthreads();
    {
        int yr = y0 + (t>>6), col = t&63;
        if (col < W_) d_w1[(size_t)bg*HW_ + yr*W_ + col] = red[t];
    }
}

__global__ void k_x21(const float* __restrict__ gnw, const float* __restrict__ gnb){
    int bg = blockIdx.x, t = threadIdx.x;
    float v = d_m2[bg*CG_+t]*(1.0f/HW_);
    float m = v;
    #pragma unroll
    for (int s=16;s;s>>=1) m = fmaxf(m, __shfl_xor_sync(~0u,m,s));
    float e = expf(v-m), sum = e;
    #pragma unroll
    for (int s=16;s;s>>=1) sum += __shfl_xor_sync(~0u,sum,s);
    float x21 = e/sum;
    float rs = d_rstd[bg*CG_+t], mu = d_mu[bg*CG_+t];
    d_A1[bg*CG_+t] = x21*gnw[t]*rs;
    float cc = x21*(gnb[t] - gnw[t]*rs*mu);
    #pragma unroll
    for (int s=16;s;s>>=1) cc += __shfl_xor_sync(~0u,cc,s);
    if (t==0) d_C1[bg] = cc;
}

// ---------------- conv4 v6: NHWC implicit GEMM, M=256 px, N=64 (2 CTAs/SM), swizzled smem ----------------
#define A_BUF 12672
#define W_BUF 18432
#define W_OFF 25344
__global__ void __launch_bounds__(256,2) k_conv4(const float* __restrict__ b3b){
    extern __shared__ __align__(16) char dsm[];
    __shared__ float b3bs[64];
    __shared__ float colred[256];
    int y0 = blockIdx.x*4, b = blockIdx.y, mbase = blockIdx.z*64;
    int t = threadIdx.x, lane = t&31, w = t>>5;
    int wm = w&3, wn = w>>2;
    unsigned smB = smem_u32(dsm);
    if (t<64) b3bs[t] = b3b[mbase+t];
    colred[t] = 0.f;
    float acc[4][4][4];
    #pragma unroll
    for (int f=0;f<4;f++)
        #pragma unroll
        for (int j=0;j<4;j++){ acc[f][j][0]=0.f; acc[f][j][1]=0.f; acc[f][j][2]=0.f; acc[f][j][3]=0.f; }

    int o_l = wn*32 + (lane&7) + ((lane>>4)<<3);
    unsigned bo = (unsigned)(o_l*32 + ((((lane>>3)&1) ^ ((o_l>>2)&1))<<4));
    const __half* xTb = d_xT + (size_t)b*HW_*256;

    auto issue = [&](int kc, int pb){
        unsigned Ab = smB + (unsigned)(pb*A_BUF);
        for (int ga = t; ga < 792; ga += 256){
            int p = ga>>1, h = ga&1;
            int arow = p/66, acol = p - arow*66;
            int yy = y0 - 1 + arow, cx = acol - 1;
            bool v = (yy>=0 && yy<H_ && cx>=0 && cx<W_);
            const __half* src = xTb + ((size_t)((v?yy:0)*W_ + (v?cx:0)))*256 + kc*16 + h*8;
            unsigned dst = Ab + (unsigned)(p*32 + ((h ^ ((p>>2)&1))<<4));
            int ss = v?16:0;
            asm volatile("cp.async.cg.shared.global [%0], [%1], 16, %2;\n"
                         :: "r"(dst), "l"(src), "r"(ss) : "memory");
        }
        unsigned Wb = smB + (unsigned)(W_OFF + pb*W_BUF);
        for (int ga = t; ga < 1152; ga += 256){
            int r = ga>>7, rem = ga&127, o = rem>>1, h = rem&1;
            const __half* src = d_w4t + ((size_t)(kc*9+r)*256 + mbase + o)*16 + h*8;
            unsigned dst = Wb + (unsigned)(r*2048 + o*32 + ((h ^ ((o>>2)&1))<<4));
            asm volatile("cp.async.cg.shared.global [%0], [%1], 16;\n"
                         :: "r"(dst), "l"(src) : "memory");
        }
        asm volatile("cp.async.commit_group;\n" ::: "memory");
    };

    issue(0, 0);
    for (int kc=0; kc<16; kc++){
        int pb = kc&1;
        if (kc<15){
            issue(kc+1, pb^1);
            asm volatile("cp.async.wait_group 1;\n" ::: "memory");
        } else {
            asm volatile("cp.async.wait_group 0;\n" ::: "memory");
        }
        __syncthreads();
        unsigned Ab = smB + (unsigned)(pb*A_BUF);
        unsigned Wb = smB + (unsigned)(W_OFF + pb*W_BUF);
        #pragma unroll
        for (int r=0;r<9;r++){
            int dy = r/3 - 1, dx = r - (r/3)*3 - 1;
            unsigned wr = Wb + (unsigned)(r*2048) + bo;
            unsigned Wf[2][4];
            #pragma unroll
            for (int j=0;j<2;j++)
                ldsm4(wr + (unsigned)(j*512), Wf[j][0],Wf[j][1],Wf[j][2],Wf[j][3]);
            int rowbase = (wm+1+dy)*66 + 1 + dx;
            #pragma unroll
            for (int f=0;f<4;f++){
                unsigned P = (unsigned)(rowbase + f*16 + (lane&15));
                unsigned a_addr = Ab + P*32 + ((((unsigned)(lane>>4)) ^ ((P>>2)&1))<<4);
                unsigned a0,a1,a2,a3; ldsm4(a_addr, a0,a1,a2,a3);
                #pragma unroll
                for (int j=0;j<2;j++){
                    mma16816(acc[f][2*j],   a0,a1,a2,a3, Wf[j][0],Wf[j][1]);
                    mma16816(acc[f][2*j+1], a0,a1,a2,a3, Wf[j][2],Wf[j][3]);
                }
            }
        }
        __syncthreads();
    }

    int pr = lane>>2, c2 = (lane&3)*2;
    size_t ybase = (size_t)b*HW_ + (size_t)(y0+wm)*W_;
    #pragma unroll
    for (int f=0;f<4;f++){
        int p0 = f*16 + pr, p1 = p0 + 8;
        float ps0 = 0.f, ps1 = 0.f;
        #pragma unroll
        for (int jj=0;jj<4;jj++){
            int chl = wn*32 + (jj>>1)*16 + (jj&1)*8 + c2;
            float v0 = acc[f][jj][0]+b3bs[chl], v1 = acc[f][jj][1]+b3bs[chl+1];
            float v2 = acc[f][jj][2]+b3bs[chl], v3 = acc[f][jj][3]+b3bs[chl+1];
            ps0 += v0+v1; ps1 += v2+v3;
            if (p0 < W_) *(__half2*)&d_x4T[(ybase+p0)*256 + mbase + chl] = __floats2half2_rn(v0,v1);
            if (p1 < W_) *(__half2*)&d_x4T[(ybase+p1)*256 + mbase + chl] = __floats2half2_rn(v2,v3);
        }
        ps0 += __shfl_xor_sync(~0u,ps0,1); ps0 += __shfl_xor_sync(~0u,ps0,2);
        ps1 += __shfl_xor_sync(~0u,ps1,1); ps1 += __shfl_xor_sync(~0u,ps1,2);
        if ((lane&3)==0){
            if (p0 < W_) atomicAdd(&colred[wm*64+p0], ps0);
            if (p1 < W_) atomicAdd(&colred[wm*64+p1], ps1);
        }
    }
    __syncthreads();
    {
        int yy = t>>6, cc = t&63;
        if (cc < W_) atomicAdd(&d_s4[(size_t)b*HW_ + (y0+yy)*W_ + cc], colred[t]);
    }
}

__global__ void __launch_bounds__(224) k_pass3(){
    __shared__ float s3red[4][56];
    int y = blockIdx.x, b = blockIdx.y;
    int t = threadIdx.x, cl = t/56, j = t%56;
    float s3acc = 0.f;
    for (int gi=0;gi<2;gi++){
        int g = cl*2+gi, bg = b*G_+g;
        float t2 = 0.f;
        #pragma unroll 4
        for (int ci=0;ci<CG_;ci++){
            int ch = b*C_ + g*CG_ + ci;
            float xv = __half2float(d_x16[(size_t)ch*HW_ + y*W_ + j]);
            float x0 = xv * d_sh[ch*H_+y] * d_sw[ch*W_+j];
            s3acc += x0 * d_rbstd[g*CG_+ci];
            t2 += d_A1[ch]*x0;
        }
        d_w1[(size_t)bg*HW_ + y*W_ + j] += t2 + d_C1[bg];
    }
    s3red[cl][j] = s3acc;
    __syncthreads();
    if (cl==0)
        d_s3[(size_t)b*HW_ + y*W_ + j] =
            (s3red[0][j]+s3red[1][j]+s3red[2][j]+s3red[3][j])*(1.0f/C_);
}

__global__ void __launch_bounds__(256) k_softmax(){
    int row = blockIdx.x;
    float scale = (row < B_) ? 1.0f : (1.0f/C_);
    float* p = (row < B_) ? (d_s3 + (size_t)row*HW_) : (d_s4 + (size_t)(row-B_)*HW_);
    __shared__ float red[8];
    int t = threadIdx.x, lane = t&31, wid = t>>5;
    float mx = -1e30f;
    for (int i=t;i<HW_;i+=256) mx = fmaxf(mx, p[i]*scale);
    #pragma unroll
    for (int s=16;s;s>>=1) mx = fmaxf(mx, __shfl_xor_sync(~0u,mx,s));
    if (lane==0) red[wid]=mx;
    __syncthreads();
    mx = red[0];
    #pragma unroll
    for (int i=1;i<8;i++) mx = fmaxf(mx, red[i]);
    __syncthreads();
    float sum = 0.f;
    for (int i=t;i<HW_;i+=256){ float e = expf(p[i]*scale-mx); p[i]=e; sum += e; }
    #pragma unroll
    for (int s=16;s;s>>=1) sum += __shfl_xor_sync(~0u,sum,s);
    if (lane==0) red[wid]=sum;
    __syncthreads();
    sum = 0.f;
    #pragma unroll
    for (int i=0;i<8;i++) sum += red[i];
    float inv = 1.0f/sum;
    for (int i=t;i<HW_;i+=256) p[i] *= inv;
}

__global__ void __launch_bounds__(256) k_t4(){
    int b = blockIdx.y, i0 = blockIdx.x*224;
    int t = threadIdx.x;
    const float* s3p = d_s3 + (size_t)b*HW_ + i0;
    const __half* xp = d_x4T + ((size_t)b*HW_ + i0)*256 + t;
    float acc = 0.f;
    for (int i=0;i<224;i++)
        acc += s3p[i]*__half2float(xp[(size_t)i*256]);
    atomicAdd(&d_t4[b*C_ + t], acc);
}

__global__ void __launch_bounds__(128) k_wfin(){
    __shared__ float r1s[4];
    int c = blockIdx.x, b = blockIdx.y, ch = b*C_+c;
    int t = threadIdx.x;
    const __half* xp  = d_x16 + (size_t)ch*HW_;
    const float* s4p = d_s4 + (size_t)b*HW_;
    const float* shp = d_sh + ch*H_;
    const float* swp = d_sw + ch*W_;
    float u = 0.f;
    for (int i=t;i<HW_;i+=128){
        float x0 = __half2float(xp[i])*shp[i/W_]*swp[i%W_];
        u += s4p[i]*x0;
    }
    int lane = t&31, wid = t>>5;
    #pragma unroll
    for (int s=16;s;s>>=1) u += __shfl_xor_sync(~0u,u,s);
    if (lane==0) r1s[wid]=u;
    __syncthreads();
    if (t==0){
        u = r1s[0]+r1s[1]+r1s[2]+r1s[3];
        float w2 = d_t4[ch] + d_rbstd[c]*(u - d_bm[c]);
        d_sw2[ch] = sigf(w2);
    }
}

__global__ void __launch_bounds__(256) k_out(const float* __restrict__ x, float* __restrict__ out){
    size_t i = ((size_t)blockIdx.x*256 + threadIdx.x)*4;
    int p = (int)(i % HW_);
    int ch = (int)(i / HW_);
    int b = ch >> 8, c = ch & 255;
    int bg = b*G_ + (c>>5);
    float4 xv = *(const float4*)(x+i);
    const float* w1p = d_w1 + (size_t)bg*HW_ + p;
    float s2 = d_sw2[ch];
    float4 o;
    o.x = xv.x*(sigf(w1p[0]) + s2);
    o.y = xv.y*(sigf(w1p[1]) + s2);
    o.z = xv.z*(sigf(w1p[2]) + s2);
    o.w = xv.w*(sigf(w1p[3]) + s2);
    *(float4*)(out+i) = o;
}

// ---------------- launch ----------------
extern "C" void kernel_launch(void* const* d_in, const int* in_sizes, int n_in,
                              void* d_out, int out_size){
    const float* x   = (const float*)d_in[0];
    const float* w1  = (const float*)d_in[1];
    const float* b1  = (const float*)d_in[2];
    const float* w3a = (const float*)d_in[3];
    const float* b3a = (const float*)d_in[4];
    const float* w3b = (const float*)d_in[5];
    const float* b3b = (const float*)d_in[6];
    const float* gnw = (const float*)d_in[7];
    const float* gnb = (const float*)d_in[8];
    float* out = (float*)d_out;

    cudaFuncSetAttribute(k_conv4, cudaFuncAttributeMaxDynamicSharedMemorySize, 2*(A_BUF+W_BUF));
    cudaFuncSetAttribute(k_conv2, cudaFuncAttributeMaxDynamicSharedMemorySize, C2_DYN);

    k_zero  <<<392, 256>>>();
    k_wprep <<<2304, 256>>>(w3b, w3a);
    k_tr    <<<dim3(196, B_), 256>>>(x);
    k_conv4 <<<dim3(H_/4, B_, 4), 256, 2*(A_BUF+W_BUF)>>>(b3b);
    k_x11   <<<1, 32>>>(gnb);
    k_rowcol<<<B_*C_, 256>>>(x);
    k_hw    <<<BG_, 128>>>(w1, b1);
    k_stats <<<B_*C_, 128>>>();
    k_fin   <<<32, 256>>>();
    k_conv2 <<<dim3(H_/4, BG_), 256, C2_DYN>>>(b3a);
    k_x21   <<<BG_, 32>>>(gnw, gnb);
    k_pass3 <<<dim3(H_, B_), 224>>>();
    k_softmax<<<64, 256>>>();
    k_t4    <<<dim3(14, B_), 256>>>();
    k_wfin  <<<dim3(C_, B_), 128>>>();
    k_out   <<<25088, 256>>>(x, out);
}

// round 8
// speedup vs baseline: 2.5969x; 1.0541x over previous
#include <cuda_runtime.h>
#include <cuda_fp16.h>
#include <math.h>

#define B_ 32
#define C_ 256
#define H_ 56
#define W_ 56
#define HW_ 3136
#define G_ 8
#define CG_ 32
#define BG_ 256
#define EPSV 1e-5f

// ---------------- static device scratch ----------------
__device__ __half d_x16[(size_t)B_*C_*HW_];   // fp16 x, NCHW
__device__ __half d_xT [(size_t)B_*HW_*C_];   // fp16 x, NHWC
__device__ __half d_x4T[(size_t)B_*HW_*C_];   // conv4 output, NHWC
__device__ __half d_w4t[16*9*256*16];         // w3b -> [kc][r][o][ic]
__device__ __half d_w2t[9*32*32];             // w3a -> [r][o][i]
__device__ float d_xhm[BG_*CG_*H_], d_xwm[BG_*CG_*W_];
__device__ float d_sh [BG_*CG_*H_], d_sw [BG_*CG_*W_];
__device__ float d_chsum[BG_*CG_], d_chsq[BG_*CG_];
__device__ float d_mu[BG_*CG_], d_rstd[BG_*CG_];
__device__ float d_bm[C_], d_rbstd[C_];
__device__ float d_x11[CG_];
__device__ float d_m2[BG_*CG_];
__device__ float d_A1[BG_*CG_], d_C1[BG_];
__device__ float d_w1[(size_t)BG_*HW_];
__device__ float d_s3[(size_t)B_*HW_], d_s4[(size_t)B_*HW_];
__device__ float d_t4[B_*C_];
__device__ float d_sw2[B_*C_];

// ---------------- helpers ----------------
__device__ __forceinline__ unsigned smem_u32(const void* p){
    return (unsigned)__cvta_generic_to_shared(p);
}
__device__ __forceinline__ void ldsm4(unsigned a, unsigned &r0, unsigned &r1, unsigned &r2, unsigned &r3){
    asm volatile("ldmatrix.sync.aligned.m8n8.x4.shared.b16 {%0,%1,%2,%3},[%4];\n"
        : "=r"(r0),"=r"(r1),"=r"(r2),"=r"(r3) : "r"(a));
}
__device__ __forceinline__ void mma16816(float* c, unsigned a0, unsigned a1, unsigned a2, unsigned a3,
                                         unsigned b0, unsigned b1){
    asm volatile("mma.sync.aligned.m16n8k16.row.col.f32.f16.f16.f32 "
        "{%0,%1,%2,%3}, {%4,%5,%6,%7}, {%8,%9}, {%0,%1,%2,%3};\n"
        : "+f"(c[0]),"+f"(c[1]),"+f"(c[2]),"+f"(c[3])
        : "r"(a0),"r"(a1),"r"(a2),"r"(a3),"r"(b0),"r"(b1));
}
__device__ __forceinline__ float sigf(float v){ return 1.f/(1.f+expf(-v)); }

// ---------------- small kernels ----------------
__global__ void k_zero(){
    int i = blockIdx.x*blockDim.x + threadIdx.x;
    if (i < BG_*CG_) d_m2[i] = 0.f;
    if (i < B_*HW_)  d_s4[i] = 0.f;
    if (i < B_*C_)   d_t4[i] = 0.f;
}

__global__ void k_wprep(const float* __restrict__ w3b, const float* __restrict__ w3a){
    int j = blockIdx.x*blockDim.x + threadIdx.x;
    if (j < 256*256*9){
        int o = j/2304, icF = (j/9)%256, r = j%9;
        int kc = icF>>4, ic = icF&15;
        d_w4t[(((size_t)kc*9 + r)*256 + o)*16 + ic] = __float2half(w3b[j]);
    }
    if (j < 32*32*9){
        int o = j/288, ic = (j/9)%32, r = j%9;
        d_w2t[(r*32+o)*32+ic] = __float2half(w3a[j]);
    }
}

__global__ void k_x11(const float* __restrict__ gnb){
    int t = threadIdx.x;
    float v = gnb[t], m = v;
    #pragma unroll
    for (int s=16;s;s>>=1) m = fmaxf(m, __shfl_xor_sync(~0u, m, s));
    float e = expf(v-m), sum = e;
    #pragma unroll
    for (int s=16;s;s>>=1) sum += __shfl_xor_sync(~0u, sum, s);
    d_x11[t] = e/sum;
}

__global__ void __launch_bounds__(256) k_rowcol(const float* __restrict__ x){
    __shared__ float tile[HW_];
    int ch = blockIdx.x;
    const float* src = x + (size_t)ch*HW_;
    __half2* dst = (__half2*)(d_x16 + (size_t)ch*HW_);
    for (int i = threadIdx.x*4; i < HW_; i += 1024){
        float4 v = *(const float4*)(src+i);
        tile[i]=v.x; tile[i+1]=v.y; tile[i+2]=v.z; tile[i+3]=v.w;
        dst[i>>1]     = __floats2half2_rn(v.x, v.y);
        dst[(i>>1)+1] = __floats2half2_rn(v.z, v.w);
    }
    __syncthreads();
    int t = threadIdx.x;
    if (t < H_){
        float rs = 0.f, cs = 0.f;
        #pragma unroll 8
        for (int w = 0; w < W_; w++) rs += tile[t*W_ + w];
        #pragma unroll 8
        for (int h = 0; h < H_; h++) cs += tile[h*W_ + t];
        d_xhm[ch*H_ + t] = rs * (1.0f/W_);
        d_xwm[ch*W_ + t] = cs * (1.0f/H_);
    }
}

// NCHW fp32 -> NHWC fp16 transpose
__global__ void __launch_bounds__(256) k_tr(const float* __restrict__ x){
    __shared__ __half sm[16*256];
    int b = blockIdx.y, p0 = blockIdx.x*16;
    int t = threadIdx.x;
    const float* src = x + (size_t)(b*C_ + t)*HW_ + p0;
    #pragma unroll
    for (int i=0;i<16;i+=4){
        float4 v = *(const float4*)(src+i);
        sm[(i+0)*256 + t] = __float2half(v.x);
        sm[(i+1)*256 + t] = __float2half(v.y);
        sm[(i+2)*256 + t] = __float2half(v.z);
        sm[(i+3)*256 + t] = __float2half(v.w);
    }
    __syncthreads();
    __half* dst = d_xT + ((size_t)b*HW_ + p0)*256;
    #pragma unroll
    for (int k=0;k<2;k++){
        int idx = t + k*256;
        int px = idx>>5, cc = (idx&31)*8;
        *(uint4*)&dst[(size_t)px*256 + cc] = *(uint4*)&sm[px*256+cc];
    }
}

__global__ void __launch_bounds__(128) k_hw(const float* __restrict__ w1, const float* __restrict__ b1){
    __shared__ float ws[1024], cat[32*112], bs[32];
    int bg = blockIdx.x;
    for (int i = threadIdx.x; i < 1024; i += 128) ws[i] = w1[i];
    if (threadIdx.x < 32) bs[threadIdx.x] = b1[threadIdx.x];
    for (int i = threadIdx.x; i < 32*112; i += 128){
        int c = i/112, p = i%112;
        cat[i] = (p < H_) ? d_xhm[(bg*CG_+c)*H_+p] : d_xwm[(bg*CG_+c)*W_+(p-H_)];
    }
    __syncthreads();
    for (int i = threadIdx.x; i < 32*112; i += 128){
        int o = i/112, p = i%112;
        float acc = bs[o];
        #pragma unroll 8
        for (int c = 0; c < 32; c++) acc += ws[o*32+c]*cat[c*112+p];
        float s = sigf(acc);
        if (p < H_) d_sh[(bg*CG_+o)*H_+p] = s;
        else        d_sw[(bg*CG_+o)*W_+(p-H_)] = s;
    }
}

__global__ void __launch_bounds__(128) k_stats(){
    int ch = blockIdx.x;
    const __half* src = d_x16 + (size_t)ch*HW_;
    const float* shp = d_sh + ch*H_;
    const float* swp = d_sw + ch*W_;
    float s = 0.f, q = 0.f;
    for (int i = threadIdx.x; i < HW_; i += 128){
        float v = __half2float(src[i])*shp[i/W_]*swp[i%W_];
        s += v; q += v*v;
    }
    __shared__ float ss[4], qq[4];
    int lane = threadIdx.x & 31, w = threadIdx.x >> 5;
    #pragma unroll
    for (int o=16;o;o>>=1){ s += __shfl_xor_sync(~0u,s,o); q += __shfl_xor_sync(~0u,q,o); }
    if (lane==0){ ss[w]=s; qq[w]=q; }
    __syncthreads();
    if (threadIdx.x==0){
        d_chsum[ch] = ss[0]+ss[1]+ss[2]+ss[3];
        d_chsq [ch] = qq[0]+qq[1]+qq[2]+qq[3];
    }
}

__global__ void k_fin(){
    int i = blockIdx.x*blockDim.x + threadIdx.x;
    if (i < BG_*CG_){
        float mu = d_chsum[i]*(1.0f/HW_);
        float var = d_chsq[i]*(1.0f/HW_) - mu*mu;
        d_mu[i] = mu;
        d_rstd[i] = rsqrtf(var + EPSV);
    }
    if (i < C_){
        float s = 0.f, q = 0.f;
        for (int b = 0; b < B_; b++){ s += d_chsum[b*C_+i]; q += d_chsq[b*C_+i]; }
        const float n = (float)B_*(float)HW_;
        float bm = s/n, bv = q/n - bm*bm;
        d_bm[i] = bm;
        d_rbstd[i] = rsqrtf(bv + EPSV);
    }
}

// ---------------- conv2 v3: NHWC grouped 3x3, whole-tap smem staging, 1 sync ----------------
#define A2_BUF 31680
#define W2_OFF 31680
#define C2_DYN (31680+23040)
__global__ void __launch_bounds__(256) k_conv2(const float* __restrict__ b3a){
    extern __shared__ __align__(16) char dsm2[];
    __shared__ float red[256], x11s[32], b3as[32];
    int y0 = blockIdx.x*4, bg = blockIdx.y;
    int b = bg>>3, g = bg&7;
    int t = threadIdx.x, lane = t&31, w = t>>5;
    int wm = w&3, wn = w>>2;
    unsigned smB = smem_u32(dsm2);
    if (t<32){ x11s[t]=d_x11[t]; b3as[t]=b3a[t]; }
    red[t] = 0.f;

    const __half* xTb = d_xT + (size_t)b*HW_*256 + g*32;
    for (int ga = t; ga < 1584; ga += 256){
        int p = ga>>2, h = ga&3;
        int arow = p/66, acol = p - arow*66;
        int yy = y0 - 1 + arow, cx = acol - 1;
        bool v = (yy>=0 && yy<H_ && cx>=0 && cx<W_);
        const __half* src = xTb + ((size_t)((v?yy:0)*W_ + (v?cx:0)))*256 + h*8;
        unsigned dst = smB + (unsigned)(p*80 + h*16);
        int ss = v?16:0;
        asm volatile("cp.async.cg.shared.global [%0], [%1], 16, %2;\n"
                     :: "r"(dst), "l"(src), "r"(ss) : "memory");
    }
    for (int ga = t; ga < 1152; ga += 256){
        int r = ga>>7, rem = ga&127, o = rem>>2, h = rem&3;
        const __half* src = d_w2t + (r*32+o)*32 + h*8;
        unsigned dst = smB + (unsigned)(W2_OFF + r*2560 + o*80 + h*16);
        asm volatile("cp.async.cg.shared.global [%0], [%1], 16;\n"
                     :: "r"(dst), "l"(src) : "memory");
    }
    asm volatile("cp.async.commit_group;\ncp.async.wait_group 0;\n" ::: "memory");
    __syncthreads();

    float acc[4][2][4];
    #pragma unroll
    for (int f=0;f<4;f++)
        #pragma unroll
        for (int j=0;j<2;j++){ acc[f][j][0]=0.f; acc[f][j][1]=0.f; acc[f][j][2]=0.f; acc[f][j][3]=0.f; }

    int o_l = wn*16 + (lane&7) + ((lane>>4)<<3);
    unsigned wofs = (unsigned)(W2_OFF + o_l*80 + ((lane>>3)&1)*16);
    #pragma unroll
    for (int r=0;r<9;r++){
        int dy = r/3 - 1, dx = r - (r/3)*3 - 1;
        int rowbase = (wm+1+dy)*66 + 1 + dx;
        #pragma unroll
        for (int kc=0;kc<2;kc++){
            unsigned b0,b1,b2,b3;
            ldsm4(smB + wofs + (unsigned)(r*2560 + kc*32), b0,b1,b2,b3);
            #pragma unroll
            for (int f=0;f<4;f++){
                int P = rowbase + f*16 + (lane&15);
                unsigned a0,a1,a2,a3;
                ldsm4(smB + (unsigned)(P*80 + kc*32 + (lane>>4)*16), a0,a1,a2,a3);
                mma16816(acc[f][0], a0,a1,a2,a3, b0,b1);
                mma16816(acc[f][1], a0,a1,a2,a3, b2,b3);
            }
        }
    }

    int pr = lane>>2, c2 = (lane&3)*2;
    float m2a[4] = {0.f,0.f,0.f,0.f};
    #pragma unroll
    for (int f=0;f<4;f++){
        int p0 = f*16 + pr, p1 = p0 + 8;
        float w0 = 0.f, w1v = 0.f;
        #pragma unroll
        for (int jj=0;jj<2;jj++){
            int chl = wn*16 + jj*8 + c2;
            float bb0 = b3as[chl], bb1 = b3as[chl+1];
            float v0 = acc[f][jj][0]+bb0, v1 = acc[f][jj][1]+bb1;
            float v2 = acc[f][jj][2]+bb0, v3 = acc[f][jj][3]+bb1;
            if (p0 < W_){ w0  += x11s[chl]*v0 + x11s[chl+1]*v1; m2a[jj*2] += v0; m2a[jj*2+1] += v1; }
            if (p1 < W_){ w1v += x11s[chl]*v2 + x11s[chl+1]*v3; m2a[jj*2] += v2; m2a[jj*2+1] += v3; }
        }
        w0  += __shfl_xor_sync(~0u,w0,1);  w0  += __shfl_xor_sync(~0u,w0,2);
        w1v += __shfl_xor_sync(~0u,w1v,1); w1v += __shfl_xor_sync(~0u,w1v,2);
        if ((lane&3)==0){
            if (p0 < W_) atomicAdd(&red[wm*64+p0], w0);
            if (p1 < W_) atomicAdd(&red[wm*64+p1], w1v);
        }
    }
    #pragma unroll
    for (int k=0;k<4;k++){
        m2a[k] += __shfl_xor_sync(~0u,m2a[k],4);
        m2a[k] += __shfl_xor_sync(~0u,m2a[k],8);
        m2a[k] += __shfl_xor_sync(~0u,m2a[k],16);
    }
    if (pr==0 && (lane>>3)==0){
        #pragma unroll
        for (int k=0;k<4;k++){
            int chl = wn*16 + (k>>1)*8 + c2 + (k&1);
            atomicAdd(&d_m2[bg*CG_ + chl], m2a[k]);
        }
    }
    __syncthreads();
    {
        int yr = y0 + (t>>6), col = t&63;
        if (col < W_) d_w1[(size_t)bg*HW_ + yr*W_ + col] = red[t];
    }
}

__global__ void k_x21(const float* __restrict__ gnw, const float* __restrict__ gnb){
    int bg = blockIdx.x, t = threadIdx.x;
    float v = d_m2[bg*CG_+t]*(1.0f/HW_);
    float m = v;
    #pragma unroll
    for (int s=16;s;s>>=1) m = fmaxf(m, __shfl_xor_sync(~0u,m,s));
    float e = expf(v-m), sum = e;
    #pragma unroll
    for (int s=16;s;s>>=1) sum += __shfl_xor_sync(~0u,sum,s);
    float x21 = e/sum;
    float rs = d_rstd[bg*CG_+t], mu = d_mu[bg*CG_+t];
    d_A1[bg*CG_+t] = x21*gnw[t]*rs;
    float cc = x21*(gnb[t] - gnw[t]*rs*mu);
    #pragma unroll
    for (int s=16;s;s>>=1) cc += __shfl_xor_sync(~0u,cc,s);
    if (t==0) d_C1[bg] = cc;
}

// ---------------- conv4 v6: NHWC implicit GEMM, M=256 px, N=64 (2 CTAs/SM), swizzled smem ----------------
#define A_BUF 12672
#define W_BUF 18432
#define W_OFF 25344
__global__ void __launch_bounds__(256,2) k_conv4(const float* __restrict__ b3b){
    extern __shared__ __align__(16) char dsm[];
    __shared__ float b3bs[64];
    __shared__ float colred[256];
    int y0 = blockIdx.x*4, b = blockIdx.y, mbase = blockIdx.z*64;
    int t = threadIdx.x, lane = t&31, w = t>>5;
    int wm = w&3, wn = w>>2;
    unsigned smB = smem_u32(dsm);
    if (t<64) b3bs[t] = b3b[mbase+t];
    colred[t] = 0.f;
    float acc[4][4][4];
    #pragma unroll
    for (int f=0;f<4;f++)
        #pragma unroll
        for (int j=0;j<4;j++){ acc[f][j][0]=0.f; acc[f][j][1]=0.f; acc[f][j][2]=0.f; acc[f][j][3]=0.f; }

    int o_l = wn*32 + (lane&7) + ((lane>>4)<<3);
    unsigned bo = (unsigned)(o_l*32 + ((((lane>>3)&1) ^ ((o_l>>2)&1))<<4));
    const __half* xTb = d_xT + (size_t)b*HW_*256;

    auto issue = [&](int kc, int pb){
        unsigned Ab = smB + (unsigned)(pb*A_BUF);
        for (int ga = t; ga < 792; ga += 256){
            int p = ga>>1, h = ga&1;
            int arow = p/66, acol = p - arow*66;
            int yy = y0 - 1 + arow, cx = acol - 1;
            bool v = (yy>=0 && yy<H_ && cx>=0 && cx<W_);
            const __half* src = xTb + ((size_t)((v?yy:0)*W_ + (v?cx:0)))*256 + kc*16 + h*8;
            unsigned dst = Ab + (unsigned)(p*32 + ((h ^ ((p>>2)&1))<<4));
            int ss = v?16:0;
            asm volatile("cp.async.cg.shared.global [%0], [%1], 16, %2;\n"
                         :: "r"(dst), "l"(src), "r"(ss) : "memory");
        }
        unsigned Wb = smB + (unsigned)(W_OFF + pb*W_BUF);
        for (int ga = t; ga < 1152; ga += 256){
            int r = ga>>7, rem = ga&127, o = rem>>1, h = rem&1;
            const __half* src = d_w4t + ((size_t)(kc*9+r)*256 + mbase + o)*16 + h*8;
            unsigned dst = Wb + (unsigned)(r*2048 + o*32 + ((h ^ ((o>>2)&1))<<4));
            asm volatile("cp.async.cg.shared.global [%0], [%1], 16;\n"
                         :: "r"(dst), "l"(src) : "memory");
        }
        asm volatile("cp.async.commit_group;\n" ::: "memory");
    };

    issue(0, 0);
    for (int kc=0; kc<16; kc++){
        int pb = kc&1;
        if (kc<15){
            issue(kc+1, pb^1);
            asm volatile("cp.async.wait_group 1;\n" ::: "memory");
        } else {
            asm volatile("cp.async.wait_group 0;\n" ::: "memory");
        }
        __syncthreads();
        unsigned Ab = smB + (unsigned)(pb*A_BUF);
        unsigned Wb = smB + (unsigned)(W_OFF + pb*W_BUF);
        #pragma unroll
        for (int r=0;r<9;r++){
            int dy = r/3 - 1, dx = r - (r/3)*3 - 1;
            unsigned wr = Wb + (unsigned)(r*2048) + bo;
            unsigned Wf[2][4];
            #pragma unroll
            for (int j=0;j<2;j++)
                ldsm4(wr + (unsigned)(j*512), Wf[j][0],Wf[j][1],Wf[j][2],Wf[j][3]);
            int rowbase = (wm+1+dy)*66 + 1 + dx;
            #pragma unroll
            for (int f=0;f<4;f++){
                unsigned P = (unsigned)(rowbase + f*16 + (lane&15));
                unsigned a_addr = Ab + P*32 + ((((unsigned)(lane>>4)) ^ ((P>>2)&1))<<4);
                unsigned a0,a1,a2,a3; ldsm4(a_addr, a0,a1,a2,a3);
                #pragma unroll
                for (int j=0;j<2;j++){
                    mma16816(acc[f][2*j],   a0,a1,a2,a3, Wf[j][0],Wf[j][1]);
                    mma16816(acc[f][2*j+1], a0,a1,a2,a3, Wf[j][2],Wf[j][3]);
                }
            }
        }
        __syncthreads();
    }

    int pr = lane>>2, c2 = (lane&3)*2;
    size_t ybase = (size_t)b*HW_ + (size_t)(y0+wm)*W_;
    #pragma unroll
    for (int f=0;f<4;f++){
        int p0 = f*16 + pr, p1 = p0 + 8;
        float ps0 = 0.f, ps1 = 0.f;
        #pragma unroll
        for (int jj=0;jj<4;jj++){
            int chl = wn*32 + (jj>>1)*16 + (jj&1)*8 + c2;
            float v0 = acc[f][jj][0]+b3bs[chl], v1 = acc[f][jj][1]+b3bs[chl+1];
            float v2 = acc[f][jj][2]+b3bs[chl], v3 = acc[f][jj][3]+b3bs[chl+1];
            ps0 += v0+v1; ps1 += v2+v3;
            if (p0 < W_) *(__half2*)&d_x4T[(ybase+p0)*256 + mbase + chl] = __floats2half2_rn(v0,v1);
            if (p1 < W_) *(__half2*)&d_x4T[(ybase+p1)*256 + mbase + chl] = __floats2half2_rn(v2,v3);
        }
        ps0 += __shfl_xor_sync(~0u,ps0,1); ps0 += __shfl_xor_sync(~0u,ps0,2);
        ps1 += __shfl_xor_sync(~0u,ps1,1); ps1 += __shfl_xor_sync(~0u,ps1,2);
        if ((lane&3)==0){
            if (p0 < W_) atomicAdd(&colred[wm*64+p0], ps0);
            if (p1 < W_) atomicAdd(&colred[wm*64+p1], ps1);
        }
    }
    __syncthreads();
    {
        int yy = t>>6, cc = t&63;
        if (cc < W_) atomicAdd(&d_s4[(size_t)b*HW_ + (y0+yy)*W_ + cc], colred[t]);
    }
}

__global__ void __launch_bounds__(224) k_pass3(){
    __shared__ float s3red[4][56];
    int y = blockIdx.x, b = blockIdx.y;
    int t = threadIdx.x, cl = t/56, j = t%56;
    float s3acc = 0.f;
    for (int gi=0;gi<2;gi++){
        int g = cl*2+gi, bg = b*G_+g;
        float t2 = 0.f;
        #pragma unroll 4
        for (int ci=0;ci<CG_;ci++){
            int ch = b*C_ + g*CG_ + ci;
            float xv = __half2float(d_x16[(size_t)ch*HW_ + y*W_ + j]);
            float x0 = xv * d_sh[ch*H_+y] * d_sw[ch*W_+j];
            s3acc += x0 * d_rbstd[g*CG_+ci];
            t2 += d_A1[ch]*x0;
        }
        d_w1[(size_t)bg*HW_ + y*W_ + j] += t2 + d_C1[bg];
    }
    s3red[cl][j] = s3acc;
    __syncthreads();
    if (cl==0)
        d_s3[(size_t)b*HW_ + y*W_ + j] =
            (s3red[0][j]+s3red[1][j]+s3red[2][j]+s3red[3][j])*(1.0f/C_);
}

__global__ void __launch_bounds__(256) k_softmax(){
    int row = blockIdx.x;
    float scale = (row < B_) ? 1.0f : (1.0f/C_);
    float* p = (row < B_) ? (d_s3 + (size_t)row*HW_) : (d_s4 + (size_t)(row-B_)*HW_);
    __shared__ float red[8];
    int t = threadIdx.x, lane = t&31, wid = t>>5;
    float mx = -1e30f;
    for (int i=t;i<HW_;i+=256) mx = fmaxf(mx, p[i]*scale);
    #pragma unroll
    for (int s=16;s;s>>=1) mx = fmaxf(mx, __shfl_xor_sync(~0u,mx,s));
    if (lane==0) red[wid]=mx;
    __syncthreads();
    mx = red[0];
    #pragma unroll
    for (int i=1;i<8;i++) mx = fmaxf(mx, red[i]);
    __syncthreads();
    float sum = 0.f;
    for (int i=t;i<HW_;i+=256){ float e = expf(p[i]*scale-mx); p[i]=e; sum += e; }
    #pragma unroll
    for (int s=16;s;s>>=1) sum += __shfl_xor_sync(~0u,sum,s);
    if (lane==0) red[wid]=sum;
    __syncthreads();
    sum = 0.f;
    #pragma unroll
    for (int i=0;i<8;i++) sum += red[i];
    float inv = 1.0f/sum;
    for (int i=t;i<HW_;i+=256) p[i] *= inv;
}

__global__ void __launch_bounds__(256) k_t4(){
    int b = blockIdx.y, i0 = blockIdx.x*224;
    int t = threadIdx.x;
    const float* s3p = d_s3 + (size_t)b*HW_ + i0;
    const __half* xp = d_x4T + ((size_t)b*HW_ + i0)*256 + t;
    float acc = 0.f;
    for (int i=0;i<224;i++)
        acc += s3p[i]*__half2float(xp[(size_t)i*256]);
    atomicAdd(&d_t4[b*C_ + t], acc);
}

__global__ void __launch_bounds__(128) k_wfin(){
    __shared__ float r1s[4];
    int c = blockIdx.x, b = blockIdx.y, ch = b*C_+c;
    int t = threadIdx.x;
    const __half* xp  = d_x16 + (size_t)ch*HW_;
    const float* s4p = d_s4 + (size_t)b*HW_;
    const float* shp = d_sh + ch*H_;
    const float* swp = d_sw + ch*W_;
    float u = 0.f;
    for (int i=t;i<HW_;i+=128){
        float x0 = __half2float(xp[i])*shp[i/W_]*swp[i%W_];
        u += s4p[i]*x0;
    }
    int lane = t&31, wid = t>>5;
    #pragma unroll
    for (int s=16;s;s>>=1) u += __shfl_xor_sync(~0u,u,s);
    if (lane==0) r1s[wid]=u;
    __syncthreads();
    if (t==0){
        u = r1s[0]+r1s[1]+r1s[2]+r1s[3];
        float w2 = d_t4[ch] + d_rbstd[c]*(u - d_bm[c]);
        d_sw2[ch] = sigf(w2);
    }
}

__global__ void __launch_bounds__(256) k_out(const float* __restrict__ x, float* __restrict__ out){
    size_t i = ((size_t)blockIdx.x*256 + threadIdx.x)*4;
    int p = (int)(i % HW_);
    int ch = (int)(i / HW_);
    int b = ch >> 8, c = ch & 255;
    int bg = b*G_ + (c>>5);
    float4 xv = *(const float4*)(x+i);
    const float* w1p = d_w1 + (size_t)bg*HW_ + p;
    float s2 = d_sw2[ch];
    float4 o;
    o.x = xv.x*(sigf(w1p[0]) + s2);
    o.y = xv.y*(sigf(w1p[1]) + s2);
    o.z = xv.z*(sigf(w1p[2]) + s2);
    o.w = xv.w*(sigf(w1p[3]) + s2);
    *(float4*)(out+i) = o;
}

// ---------------- launch: two-stream fork/join DAG ----------------
extern "C" void kernel_launch(void* const* d_in, const int* in_sizes, int n_in,
                              void* d_out, int out_size){
    const float* x   = (const float*)d_in[0];
    const float* w1  = (const float*)d_in[1];
    const float* b1  = (const float*)d_in[2];
    const float* w3a = (const float*)d_in[3];
    const float* b3a = (const float*)d_in[4];
    const float* w3b = (const float*)d_in[5];
    const float* b3b = (const float*)d_in[6];
    const float* gnw = (const float*)d_in[7];
    const float* gnb = (const float*)d_in[8];
    float* out = (float*)d_out;

    // streams/events created once, on the (uncaptured) correctness call
    static cudaStream_t s1 = nullptr;
    static cudaEvent_t ev0 = nullptr, ev1 = nullptr;
    if (!s1){
        cudaStreamCreateWithFlags(&s1, cudaStreamNonBlocking);
        cudaEventCreateWithFlags(&ev0, cudaEventDisableTiming);
        cudaEventCreateWithFlags(&ev1, cudaEventDisableTiming);
        cudaFuncSetAttribute(k_conv4, cudaFuncAttributeMaxDynamicSharedMemorySize, 2*(A_BUF+W_BUF));
        cudaFuncSetAttribute(k_conv2, cudaFuncAttributeMaxDynamicSharedMemorySize, C2_DYN);
    }

    // s0 prologue
    k_zero  <<<392, 256>>>();
    k_wprep <<<2304, 256>>>(w3b, w3a);
    k_tr    <<<dim3(196, B_), 256>>>(x);
    cudaEventRecord(ev0, 0);

    // s1: gating/GN/conv2/pass3 chain (overlaps conv4)
    cudaStreamWaitEvent(s1, ev0, 0);
    k_x11   <<<1, 32, 0, s1>>>(gnb);
    k_rowcol<<<B_*C_, 256, 0, s1>>>(x);
    k_hw    <<<BG_, 128, 0, s1>>>(w1, b1);
    k_stats <<<B_*C_, 128, 0, s1>>>();
    k_fin   <<<32, 256, 0, s1>>>();
    k_conv2 <<<dim3(H_/4, BG_), 256, C2_DYN, s1>>>(b3a);
    k_x21   <<<BG_, 32, 0, s1>>>(gnw, gnb);
    k_pass3 <<<dim3(H_, B_), 224, 0, s1>>>();
    cudaEventRecord(ev1, s1);

    // s0: conv4 concurrently
    k_conv4 <<<dim3(H_/4, B_, 4), 256, 2*(A_BUF+W_BUF)>>>(b3b);

    // join + epilogue
    cudaStreamWaitEvent(0, ev1, 0);
    k_softmax<<<64, 256>>>();
    k_t4    <<<dim3(14, B_), 256>>>();
    k_wfin  <<<dim3(C_, B_), 128>>>();
    k_out   <<<25088, 256>>>(x, out);
}

// round 9
// speedup vs baseline: 2.5974x; 1.0002x over previous
#include <cuda_runtime.h>
#include <cuda_fp16.h>
#include <math.h>

#define B_ 32
#define C_ 256
#define H_ 56
#define W_ 56
#define HW_ 3136
#define G_ 8
#define CG_ 32
#define BG_ 256
#define EPSV 1e-5f

// ---------------- static device scratch ----------------
__device__ __half d_x16[(size_t)B_*C_*HW_];   // fp16 x, NCHW
__device__ __half d_xT [(size_t)B_*HW_*C_];   // fp16 x, NHWC
__device__ __half d_x4T[(size_t)B_*HW_*C_];   // conv4 output, NHWC
__device__ __half d_w4t[16*9*256*16];         // w3b -> [kc][r][o][ic]
__device__ __half d_w2t[9*32*32];             // w3a -> [r][o][i]
__device__ float d_xhm[BG_*CG_*H_], d_xwm[BG_*CG_*W_];
__device__ float d_sh [BG_*CG_*H_], d_sw [BG_*CG_*W_];
__device__ float d_chsum[BG_*CG_], d_chsq[BG_*CG_];
__device__ float d_mu[BG_*CG_], d_rstd[BG_*CG_];
__device__ float d_bm[C_], d_rbstd[C_];
__device__ float d_x11[CG_];
__device__ float d_m2[BG_*CG_];
__device__ float d_A1[BG_*CG_], d_C1[BG_];
__device__ float d_w1[(size_t)BG_*HW_];
__device__ float d_s3[(size_t)B_*HW_], d_s4[(size_t)B_*HW_];
__device__ float d_t4[B_*C_];
__device__ float d_sw2[B_*C_];

// ---------------- helpers ----------------
__device__ __forceinline__ unsigned smem_u32(const void* p){
    return (unsigned)__cvta_generic_to_shared(p);
}
__device__ __forceinline__ void ldsm4(unsigned a, unsigned &r0, unsigned &r1, unsigned &r2, unsigned &r3){
    asm volatile("ldmatrix.sync.aligned.m8n8.x4.shared.b16 {%0,%1,%2,%3},[%4];\n"
        : "=r"(r0),"=r"(r1),"=r"(r2),"=r"(r3) : "r"(a));
}
__device__ __forceinline__ void mma16816(float* c, unsigned a0, unsigned a1, unsigned a2, unsigned a3,
                                         unsigned b0, unsigned b1){
    asm volatile("mma.sync.aligned.m16n8k16.row.col.f32.f16.f16.f32 "
        "{%0,%1,%2,%3}, {%4,%5,%6,%7}, {%8,%9}, {%0,%1,%2,%3};\n"
        : "+f"(c[0]),"+f"(c[1]),"+f"(c[2]),"+f"(c[3])
        : "r"(a0),"r"(a1),"r"(a2),"r"(a3),"r"(b0),"r"(b1));
}
__device__ __forceinline__ float sigf(float v){ return 1.f/(1.f+expf(-v)); }

// ---------------- small kernels ----------------
__global__ void k_zero(){
    int i = blockIdx.x*blockDim.x + threadIdx.x;
    if (i < BG_*CG_) d_m2[i] = 0.f;
    if (i < B_*HW_)  d_s4[i] = 0.f;
    if (i < B_*C_)   d_t4[i] = 0.f;
}

__global__ void k_wprep(const float* __restrict__ w3b, const float* __restrict__ w3a){
    int j = blockIdx.x*blockDim.x + threadIdx.x;
    if (j < 256*256*9){
        int o = j/2304, icF = (j/9)%256, r = j%9;
        int kc = icF>>4, ic = icF&15;
        d_w4t[(((size_t)kc*9 + r)*256 + o)*16 + ic] = __float2half(w3b[j]);
    }
    if (j < 32*32*9){
        int o = j/288, ic = (j/9)%32, r = j%9;
        d_w2t[(r*32+o)*32+ic] = __float2half(w3a[j]);
    }
}

__global__ void k_x11(const float* __restrict__ gnb){
    int t = threadIdx.x;
    float v = gnb[t], m = v;
    #pragma unroll
    for (int s=16;s;s>>=1) m = fmaxf(m, __shfl_xor_sync(~0u, m, s));
    float e = expf(v-m), sum = e;
    #pragma unroll
    for (int s=16;s;s>>=1) sum += __shfl_xor_sync(~0u, sum, s);
    d_x11[t] = e/sum;
}

__global__ void __launch_bounds__(256) k_rowcol(const float* __restrict__ x){
    __shared__ float tile[HW_];
    int ch = blockIdx.x;
    const float* src = x + (size_t)ch*HW_;
    __half2* dst = (__half2*)(d_x16 + (size_t)ch*HW_);
    for (int i = threadIdx.x*4; i < HW_; i += 1024){
        float4 v = *(const float4*)(src+i);
        tile[i]=v.x; tile[i+1]=v.y; tile[i+2]=v.z; tile[i+3]=v.w;
        dst[i>>1]     = __floats2half2_rn(v.x, v.y);
        dst[(i>>1)+1] = __floats2half2_rn(v.z, v.w);
    }
    __syncthreads();
    int t = threadIdx.x;
    if (t < H_){
        float rs = 0.f, cs = 0.f;
        #pragma unroll 8
        for (int w = 0; w < W_; w++) rs += tile[t*W_ + w];
        #pragma unroll 8
        for (int h = 0; h < H_; h++) cs += tile[h*W_ + t];
        d_xhm[ch*H_ + t] = rs * (1.0f/W_);
        d_xwm[ch*W_ + t] = cs * (1.0f/H_);
    }
}

// NCHW fp32 -> NHWC fp16 transpose
__global__ void __launch_bounds__(256) k_tr(const float* __restrict__ x){
    __shared__ __half sm[16*256];
    int b = blockIdx.y, p0 = blockIdx.x*16;
    int t = threadIdx.x;
    const float* src = x + (size_t)(b*C_ + t)*HW_ + p0;
    #pragma unroll
    for (int i=0;i<16;i+=4){
        float4 v = *(const float4*)(src+i);
        sm[(i+0)*256 + t] = __float2half(v.x);
        sm[(i+1)*256 + t] = __float2half(v.y);
        sm[(i+2)*256 + t] = __float2half(v.z);
        sm[(i+3)*256 + t] = __float2half(v.w);
    }
    __syncthreads();
    __half* dst = d_xT + ((size_t)b*HW_ + p0)*256;
    #pragma unroll
    for (int k=0;k<2;k++){
        int idx = t + k*256;
        int px = idx>>5, cc = (idx&31)*8;
        *(uint4*)&dst[(size_t)px*256 + cc] = *(uint4*)&sm[px*256+cc];
    }
}

__global__ void __launch_bounds__(128) k_hw(const float* __restrict__ w1, const float* __restrict__ b1){
    __shared__ float ws[1024], cat[32*112], bs[32];
    int bg = blockIdx.x;
    for (int i = threadIdx.x; i < 1024; i += 128) ws[i] = w1[i];
    if (threadIdx.x < 32) bs[threadIdx.x] = b1[threadIdx.x];
    for (int i = threadIdx.x; i < 32*112; i += 128){
        int c = i/112, p = i%112;
        cat[i] = (p < H_) ? d_xhm[(bg*CG_+c)*H_+p] : d_xwm[(bg*CG_+c)*W_+(p-H_)];
    }
    __syncthreads();
    for (int i = threadIdx.x; i < 32*112; i += 128){
        int o = i/112, p = i%112;
        float acc = bs[o];
        #pragma unroll 8
        for (int c = 0; c < 32; c++) acc += ws[o*32+c]*cat[c*112+p];
        float s = sigf(acc);
        if (p < H_) d_sh[(bg*CG_+o)*H_+p] = s;
        else        d_sw[(bg*CG_+o)*W_+(p-H_)] = s;
    }
}

__global__ void __launch_bounds__(128) k_stats(){
    int ch = blockIdx.x;
    const __half* src = d_x16 + (size_t)ch*HW_;
    const float* shp = d_sh + ch*H_;
    const float* swp = d_sw + ch*W_;
    float s = 0.f, q = 0.f;
    for (int i = threadIdx.x; i < HW_; i += 128){
        float v = __half2float(src[i])*shp[i/W_]*swp[i%W_];
        s += v; q += v*v;
    }
    __shared__ float ss[4], qq[4];
    int lane = threadIdx.x & 31, w = threadIdx.x >> 5;
    #pragma unroll
    for (int o=16;o;o>>=1){ s += __shfl_xor_sync(~0u,s,o); q += __shfl_xor_sync(~0u,q,o); }
    if (lane==0){ ss[w]=s; qq[w]=q; }
    __syncthreads();
    if (threadIdx.x==0){
        d_chsum[ch] = ss[0]+ss[1]+ss[2]+ss[3];
        d_chsq [ch] = qq[0]+qq[1]+qq[2]+qq[3];
    }
}

__global__ void k_fin(){
    int i = blockIdx.x*blockDim.x + threadIdx.x;
    if (i < BG_*CG_){
        float mu = d_chsum[i]*(1.0f/HW_);
        float var = d_chsq[i]*(1.0f/HW_) - mu*mu;
        d_mu[i] = mu;
        d_rstd[i] = rsqrtf(var + EPSV);
    }
    if (i < C_){
        float s = 0.f, q = 0.f;
        for (int b = 0; b < B_; b++){ s += d_chsum[b*C_+i]; q += d_chsq[b*C_+i]; }
        const float n = (float)B_*(float)HW_;
        float bm = s/n, bv = q/n - bm*bm;
        d_bm[i] = bm;
        d_rbstd[i] = rsqrtf(bv + EPSV);
    }
}

// ---------------- conv2 v3: NHWC grouped 3x3, whole-tap smem staging, 1 sync ----------------
#define W2_OFF 31680
#define C2_DYN (31680+23040)
__global__ void __launch_bounds__(256) k_conv2(const float* __restrict__ b3a){
    extern __shared__ __align__(16) char dsm2[];
    __shared__ float red[256], x11s[32], b3as[32];
    int y0 = blockIdx.x*4, bg = blockIdx.y;
    int b = bg>>3, g = bg&7;
    int t = threadIdx.x, lane = t&31, w = t>>5;
    int wm = w&3, wn = w>>2;
    unsigned smB = smem_u32(dsm2);
    if (t<32){ x11s[t]=d_x11[t]; b3as[t]=b3a[t]; }
    red[t] = 0.f;

    const __half* xTb = d_xT + (size_t)b*HW_*256 + g*32;
    for (int ga = t; ga < 1584; ga += 256){
        int p = ga>>2, h = ga&3;
        int arow = p/66, acol = p - arow*66;
        int yy = y0 - 1 + arow, cx = acol - 1;
        bool v = (yy>=0 && yy<H_ && cx>=0 && cx<W_);
        const __half* src = xTb + ((size_t)((v?yy:0)*W_ + (v?cx:0)))*256 + h*8;
        unsigned dst = smB + (unsigned)(p*80 + h*16);
        int ss = v?16:0;
        asm volatile("cp.async.cg.shared.global [%0], [%1], 16, %2;\n"
                     :: "r"(dst), "l"(src), "r"(ss) : "memory");
    }
    for (int ga = t; ga < 1152; ga += 256){
        int r = ga>>7, rem = ga&127, o = rem>>2, h = rem&3;
        const __half* src = d_w2t + (r*32+o)*32 + h*8;
        unsigned dst = smB + (unsigned)(W2_OFF + r*2560 + o*80 + h*16);
        asm volatile("cp.async.cg.shared.global [%0], [%1], 16;\n"
                     :: "r"(dst), "l"(src) : "memory");
    }
    asm volatile("cp.async.commit_group;\ncp.async.wait_group 0;\n" ::: "memory");
    __syncthreads();

    float acc[4][2][4];
    #pragma unroll
    for (int f=0;f<4;f++)
        #pragma unroll
        for (int j=0;j<2;j++){ acc[f][j][0]=0.f; acc[f][j][1]=0.f; acc[f][j][2]=0.f; acc[f][j][3]=0.f; }

    int o_l = wn*16 + (lane&7) + ((lane>>4)<<3);
    unsigned wofs = (unsigned)(W2_OFF + o_l*80 + ((lane>>3)&1)*16);
    #pragma unroll
    for (int r=0;r<9;r++){
        int dy = r/3 - 1, dx = r - (r/3)*3 - 1;
        int rowbase = (wm+1+dy)*66 + 1 + dx;
        #pragma unroll
        for (int kc=0;kc<2;kc++){
            unsigned b0,b1,b2,b3;
            ldsm4(smB + wofs + (unsigned)(r*2560 + kc*32), b0,b1,b2,b3);
            #pragma unroll
            for (int f=0;f<4;f++){
                int P = rowbase + f*16 + (lane&15);
                unsigned a0,a1,a2,a3;
                ldsm4(smB + (unsigned)(P*80 + kc*32 + (lane>>4)*16), a0,a1,a2,a3);
                mma16816(acc[f][0], a0,a1,a2,a3, b0,b1);
                mma16816(acc[f][1], a0,a1,a2,a3, b2,b3);
            }
        }
    }

    int pr = lane>>2, c2 = (lane&3)*2;
    float m2a[4] = {0.f,0.f,0.f,0.f};
    #pragma unroll
    for (int f=0;f<4;f++){
        int p0 = f*16 + pr, p1 = p0 + 8;
        float w0 = 0.f, w1v = 0.f;
        #pragma unroll
        for (int jj=0;jj<2;jj++){
            int chl = wn*16 + jj*8 + c2;
            float bb0 = b3as[chl], bb1 = b3as[chl+1];
            float v0 = acc[f][jj][0]+bb0, v1 = acc[f][jj][1]+bb1;
            float v2 = acc[f][jj][2]+bb0, v3 = acc[f][jj][3]+bb1;
            if (p0 < W_){ w0  += x11s[chl]*v0 + x11s[chl+1]*v1; m2a[jj*2] += v0; m2a[jj*2+1] += v1; }
            if (p1 < W_){ w1v += x11s[chl]*v2 + x11s[chl+1]*v3; m2a[jj*2] += v2; m2a[jj*2+1] += v3; }
        }
        w0  += __shfl_xor_sync(~0u,w0,1);  w0  += __shfl_xor_sync(~0u,w0,2);
        w1v += __shfl_xor_sync(~0u,w1v,1); w1v += __shfl_xor_sync(~0u,w1v,2);
        if ((lane&3)==0){
            if (p0 < W_) atomicAdd(&red[wm*64+p0], w0);
            if (p1 < W_) atomicAdd(&red[wm*64+p1], w1v);
        }
    }
    #pragma unroll
    for (int k=0;k<4;k++){
        m2a[k] += __shfl_xor_sync(~0u,m2a[k],4);
        m2a[k] += __shfl_xor_sync(~0u,m2a[k],8);
        m2a[k] += __shfl_xor_sync(~0u,m2a[k],16);
    }
    if (pr==0 && (lane>>3)==0){
        #pragma unroll
        for (int k=0;k<4;k++){
            int chl = wn*16 + (k>>1)*8 + c2 + (k&1);
            atomicAdd(&d_m2[bg*CG_ + chl], m2a[k]);
        }
    }
    __syncthreads();
    {
        int yr = y0 + (t>>6), col = t&63;
        if (col < W_) d_w1[(size_t)bg*HW_ + yr*W_ + col] = red[t];
    }
}

__global__ void k_x21(const float* __restrict__ gnw, const float* __restrict__ gnb){
    int bg = blockIdx.x, t = threadIdx.x;
    float v = d_m2[bg*CG_+t]*(1.0f/HW_);
    float m = v;
    #pragma unroll
    for (int s=16;s;s>>=1) m = fmaxf(m, __shfl_xor_sync(~0u,m,s));
    float e = expf(v-m), sum = e;
    #pragma unroll
    for (int s=16;s;s>>=1) sum += __shfl_xor_sync(~0u,sum,s);
    float x21 = e/sum;
    float rs = d_rstd[bg*CG_+t], mu = d_mu[bg*CG_+t];
    d_A1[bg*CG_+t] = x21*gnw[t]*rs;
    float cc = x21*(gnb[t] - gnw[t]*rs*mu);
    #pragma unroll
    for (int s=16;s;s>>=1) cc += __shfl_xor_sync(~0u,cc,s);
    if (t==0) d_C1[bg] = cc;
}

// ---------------- conv4 v7: NHWC implicit GEMM, M=256 px, N=64, 3-stage cp.async, 2 CTAs/SM ----------------
#define A_BUF 12672
#define W_BUF 18432
#define S_BUF 31104
__global__ void __launch_bounds__(256,2) k_conv4(const float* __restrict__ b3b){
    extern __shared__ __align__(16) char dsm[];
    __shared__ float b3bs[64];
    __shared__ float colred[256];
    int y0 = blockIdx.x*4, b = blockIdx.y, mbase = blockIdx.z*64;
    int t = threadIdx.x, lane = t&31, w = t>>5;
    int wm = w&3, wn = w>>2;
    unsigned smB = smem_u32(dsm);
    if (t<64) b3bs[t] = b3b[mbase+t];
    colred[t] = 0.f;
    float acc[4][4][4];
    #pragma unroll
    for (int f=0;f<4;f++)
        #pragma unroll
        for (int j=0;j<4;j++){ acc[f][j][0]=0.f; acc[f][j][1]=0.f; acc[f][j][2]=0.f; acc[f][j][3]=0.f; }

    int o_l = wn*32 + (lane&7) + ((lane>>4)<<3);
    unsigned bo = (unsigned)(o_l*32 + ((((lane>>3)&1) ^ ((o_l>>2)&1))<<4));
    const __half* xTb = d_xT + (size_t)b*HW_*256;

    auto issue = [&](int kc, int pb){
        unsigned Ab = smB + (unsigned)(pb*S_BUF);
        for (int ga = t; ga < 792; ga += 256){
            int p = ga>>1, h = ga&1;
            int arow = p/66, acol = p - arow*66;
            int yy = y0 - 1 + arow, cx = acol - 1;
            bool v = (yy>=0 && yy<H_ && cx>=0 && cx<W_);
            const __half* src = xTb + ((size_t)((v?yy:0)*W_ + (v?cx:0)))*256 + kc*16 + h*8;
            unsigned dst = Ab + (unsigned)(p*32 + ((h ^ ((p>>2)&1))<<4));
            int ss = v?16:0;
            asm volatile("cp.async.cg.shared.global [%0], [%1], 16, %2;\n"
                         :: "r"(dst), "l"(src), "r"(ss) : "memory");
        }
        unsigned Wb = smB + (unsigned)(pb*S_BUF + A_BUF);
        for (int ga = t; ga < 1152; ga += 256){
            int r = ga>>7, rem = ga&127, o = rem>>1, h = rem&1;
            const __half* src = d_w4t + ((size_t)(kc*9+r)*256 + mbase + o)*16 + h*8;
            unsigned dst = Wb + (unsigned)(r*2048 + o*32 + ((h ^ ((o>>2)&1))<<4));
            asm volatile("cp.async.cg.shared.global [%0], [%1], 16;\n"
                         :: "r"(dst), "l"(src) : "memory");
        }
        asm volatile("cp.async.commit_group;\n" ::: "memory");
    };

    issue(0, 0);
    issue(1, 1);
    #pragma unroll 1
    for (int kc=0; kc<16; kc++){
        int pb = kc - (kc/3)*3;
        if (kc<15){ asm volatile("cp.async.wait_group 1;\n" ::: "memory"); }
        else      { asm volatile("cp.async.wait_group 0;\n" ::: "memory"); }
        __syncthreads();
        unsigned Ab = smB + (unsigned)(pb*S_BUF);
        unsigned Wb = smB + (unsigned)(pb*S_BUF + A_BUF);
        #pragma unroll
        for (int r=0;r<9;r++){
            int dy = r/3 - 1, dx = r - (r/3)*3 - 1;
            unsigned wr = Wb + (unsigned)(r*2048) + bo;
            unsigned Wf[2][4];
            #pragma unroll
            for (int j=0;j<2;j++)
                ldsm4(wr + (unsigned)(j*512), Wf[j][0],Wf[j][1],Wf[j][2],Wf[j][3]);
            int rowbase = (wm+1+dy)*66 + 1 + dx;
            #pragma unroll
            for (int f=0;f<4;f++){
                unsigned P = (unsigned)(rowbase + f*16 + (lane&15));
                unsigned a_addr = Ab + P*32 + ((((unsigned)(lane>>4)) ^ ((P>>2)&1))<<4);
                unsigned a0,a1,a2,a3; ldsm4(a_addr, a0,a1,a2,a3);
                #pragma unroll
                for (int j=0;j<2;j++){
                    mma16816(acc[f][2*j],   a0,a1,a2,a3, Wf[j][0],Wf[j][1]);
                    mma16816(acc[f][2*j+1], a0,a1,a2,a3, Wf[j][2],Wf[j][3]);
                }
            }
        }
        if (kc < 14){
            int nb = kc+2;
            issue(nb, nb - (nb/3)*3);
        }
    }

    int pr = lane>>2, c2 = (lane&3)*2;
    size_t ybase = (size_t)b*HW_ + (size_t)(y0+wm)*W_;
    #pragma unroll
    for (int f=0;f<4;f++){
        int p0 = f*16 + pr, p1 = p0 + 8;
        float ps0 = 0.f, ps1 = 0.f;
        #pragma unroll
        for (int jj=0;jj<4;jj++){
            int chl = wn*32 + (jj>>1)*16 + (jj&1)*8 + c2;
            float v0 = acc[f][jj][0]+b3bs[chl], v1 = acc[f][jj][1]+b3bs[chl+1];
            float v2 = acc[f][jj][2]+b3bs[chl], v3 = acc[f][jj][3]+b3bs[chl+1];
            ps0 += v0+v1; ps1 += v2+v3;
            if (p0 < W_) *(__half2*)&d_x4T[(ybase+p0)*256 + mbase + chl] = __floats2half2_rn(v0,v1);
            if (p1 < W_) *(__half2*)&d_x4T[(ybase+p1)*256 + mbase + chl] = __floats2half2_rn(v2,v3);
        }
        ps0 += __shfl_xor_sync(~0u,ps0,1); ps0 += __shfl_xor_sync(~0u,ps0,2);
        ps1 += __shfl_xor_sync(~0u,ps1,1); ps1 += __shfl_xor_sync(~0u,ps1,2);
        if ((lane&3)==0){
            if (p0 < W_) atomicAdd(&colred[wm*64+p0], ps0);
            if (p1 < W_) atomicAdd(&colred[wm*64+p1], ps1);
        }
    }
    __syncthreads();
    {
        int yy = t>>6, cc = t&63;
        if (cc < W_) atomicAdd(&d_s4[(size_t)b*HW_ + (y0+yy)*W_ + cc], colred[t]);
    }
}

__global__ void __launch_bounds__(224) k_pass3(){
    __shared__ float s3red[4][56];
    int y = blockIdx.x, b = blockIdx.y;
    int t = threadIdx.x, cl = t/56, j = t%56;
    float s3acc = 0.f;
    for (int gi=0;gi<2;gi++){
        int g = cl*2+gi, bg = b*G_+g;
        float t2 = 0.f;
        #pragma unroll 4
        for (int ci=0;ci<CG_;ci++){
            int ch = b*C_ + g*CG_ + ci;
            float xv = __half2float(d_x16[(size_t)ch*HW_ + y*W_ + j]);
            float x0 = xv * d_sh[ch*H_+y] * d_sw[ch*W_+j];
            s3acc += x0 * d_rbstd[g*CG_+ci];
            t2 += d_A1[ch]*x0;
        }
        d_w1[(size_t)bg*HW_ + y*W_ + j] += t2 + d_C1[bg];
    }
    s3red[cl][j] = s3acc;
    __syncthreads();
    if (cl==0)
        d_s3[(size_t)b*HW_ + y*W_ + j] =
            (s3red[0][j]+s3red[1][j]+s3red[2][j]+s3red[3][j])*(1.0f/C_);
}

__global__ void __launch_bounds__(256) k_softmax(int which){
    int row = blockIdx.x;
    float scale = which ? (1.0f/C_) : 1.0f;
    float* p = (which ? d_s4 : d_s3) + (size_t)row*HW_;
    __shared__ float red[8];
    int t = threadIdx.x, lane = t&31, wid = t>>5;
    float mx = -1e30f;
    for (int i=t;i<HW_;i+=256) mx = fmaxf(mx, p[i]*scale);
    #pragma unroll
    for (int s=16;s;s>>=1) mx = fmaxf(mx, __shfl_xor_sync(~0u,mx,s));
    if (lane==0) red[wid]=mx;
    __syncthreads();
    mx = red[0];
    #pragma unroll
    for (int i=1;i<8;i++) mx = fmaxf(mx, red[i]);
    __syncthreads();
    float sum = 0.f;
    for (int i=t;i<HW_;i+=256){ float e = expf(p[i]*scale-mx); p[i]=e; sum += e; }
    #pragma unroll
    for (int s=16;s;s>>=1) sum += __shfl_xor_sync(~0u,sum,s);
    if (lane==0) red[wid]=sum;
    __syncthreads();
    sum = 0.f;
    #pragma unroll
    for (int i=0;i<8;i++) sum += red[i];
    float inv = 1.0f/sum;
    for (int i=t;i<HW_;i+=256) p[i] *= inv;
}

__global__ void __launch_bounds__(256) k_t4(){
    int b = blockIdx.y, i0 = blockIdx.x*224;
    int t = threadIdx.x;
    const float* s3p = d_s3 + (size_t)b*HW_ + i0;
    const __half* xp = d_x4T + ((size_t)b*HW_ + i0)*256 + t;
    float acc = 0.f;
    for (int i=0;i<224;i++)
        acc += s3p[i]*__half2float(xp[(size_t)i*256]);
    atomicAdd(&d_t4[b*C_ + t], acc);
}

__global__ void __launch_bounds__(128) k_wfin(){
    __shared__ float r1s[4];
    int c = blockIdx.x, b = blockIdx.y, ch = b*C_+c;
    int t = threadIdx.x;
    const __half* xp  = d_x16 + (size_t)ch*HW_;
    const float* s4p = d_s4 + (size_t)b*HW_;
    const float* shp = d_sh + ch*H_;
    const float* swp = d_sw + ch*W_;
    float u = 0.f;
    for (int i=t;i<HW_;i+=128){
        float x0 = __half2float(xp[i])*shp[i/W_]*swp[i%W_];
        u += s4p[i]*x0;
    }
    int lane = t&31, wid = t>>5;
    #pragma unroll
    for (int s=16;s;s>>=1) u += __shfl_xor_sync(~0u,u,s);
    if (lane==0) r1s[wid]=u;
    __syncthreads();
    if (t==0){
        u = r1s[0]+r1s[1]+r1s[2]+r1s[3];
        float w2 = d_t4[ch] + d_rbstd[c]*(u - d_bm[c]);
        d_sw2[ch] = sigf(w2);
    }
}

__global__ void __launch_bounds__(256) k_out(const float* __restrict__ x, float* __restrict__ out){
    size_t i = ((size_t)blockIdx.x*256 + threadIdx.x)*4;
    int p = (int)(i % HW_);
    int ch = (int)(i / HW_);
    int b = ch >> 8, c = ch & 255;
    int bg = b*G_ + (c>>5);
    float4 xv = *(const float4*)(x+i);
    const float* w1p = d_w1 + (size_t)bg*HW_ + p;
    float s2 = d_sw2[ch];
    float4 o;
    o.x = xv.x*(sigf(w1p[0]) + s2);
    o.y = xv.y*(sigf(w1p[1]) + s2);
    o.z = xv.z*(sigf(w1p[2]) + s2);
    o.w = xv.w*(sigf(w1p[3]) + s2);
    *(float4*)(out+i) = o;
}

// ---------------- launch: 3-stream fork/join DAG (nothing on default between fork and join) ----------------
extern "C" void kernel_launch(void* const* d_in, const int* in_sizes, int n_in,
                              void* d_out, int out_size){
    const float* x   = (const float*)d_in[0];
    const float* w1  = (const float*)d_in[1];
    const float* b1  = (const float*)d_in[2];
    const float* w3a = (const float*)d_in[3];
    const float* b3a = (const float*)d_in[4];
    const float* w3b = (const float*)d_in[5];
    const float* b3b = (const float*)d_in[6];
    const float* gnw = (const float*)d_in[7];
    const float* gnb = (const float*)d_in[8];
    float* out = (float*)d_out;

    static cudaStream_t sA = nullptr, sB = nullptr, sC = nullptr;
    static cudaEvent_t evF=nullptr, evX=nullptr, evC=nullptr, evA=nullptr, evB=nullptr;
    if (!sA){
        cudaStreamCreateWithFlags(&sA, cudaStreamNonBlocking);
        cudaStreamCreateWithFlags(&sB, cudaStreamNonBlocking);
        cudaStreamCreateWithFlags(&sC, cudaStreamNonBlocking);
        cudaEventCreateWithFlags(&evF, cudaEventDisableTiming);
        cudaEventCreateWithFlags(&evX, cudaEventDisableTiming);
        cudaEventCreateWithFlags(&evC, cudaEventDisableTiming);
        cudaEventCreateWithFlags(&evA, cudaEventDisableTiming);
        cudaEventCreateWithFlags(&evB, cudaEventDisableTiming);
        cudaFuncSetAttribute(k_conv4, cudaFuncAttributeMaxDynamicSharedMemorySize, 3*S_BUF);
        cudaFuncSetAttribute(k_conv2, cudaFuncAttributeMaxDynamicSharedMemorySize, C2_DYN);
    }

    // prologue on default stream
    k_zero  <<<392, 256>>>();
    k_wprep <<<2304, 256>>>(w3b, w3a);
    k_tr    <<<dim3(196, B_), 256>>>(x);
    cudaEventRecord(evF, 0);

    // sA: conv4 (launch #4 overall -> ncu-profiled slot)
    cudaStreamWaitEvent(sA, evF, 0);
    k_conv4 <<<dim3(H_/4, B_, 4), 256, 3*S_BUF, sA>>>(b3b);
    cudaEventRecord(evA, sA);

    // sB: gating/GN chain
    cudaStreamWaitEvent(sB, evF, 0);
    k_x11   <<<1, 32, 0, sB>>>(gnb);
    cudaEventRecord(evX, sB);
    k_rowcol<<<B_*C_, 256, 0, sB>>>(x);
    k_hw    <<<BG_, 128, 0, sB>>>(w1, b1);
    k_stats <<<B_*C_, 128, 0, sB>>>();
    k_fin   <<<32, 256, 0, sB>>>();

    // sC: conv2 (needs only x11 + xT + w2t) — parallel with stats/fin
    cudaStreamWaitEvent(sC, evF, 0);
    cudaStreamWaitEvent(sC, evX, 0);
    k_conv2 <<<dim3(H_/4, BG_), 256, C2_DYN, sC>>>(b3a);
    cudaEventRecord(evC, sC);

    // sB continues after conv2 result
    cudaStreamWaitEvent(sB, evC, 0);
    k_x21   <<<BG_, 32, 0, sB>>>(gnw, gnb);
    k_pass3 <<<dim3(H_, B_), 224, 0, sB>>>();
    k_softmax<<<B_, 256, 0, sB>>>(0);     // s3 softmax — overlaps conv4
    cudaEventRecord(evB, sB);

    // join on default + epilogue
    cudaStreamWaitEvent(0, evA, 0);
    cudaStreamWaitEvent(0, evB, 0);
    k_softmax<<<B_, 256>>>(1);            // s4 softmax (needs conv4)
    k_t4    <<<dim3(14, B_), 256>>>();
    k_wfin  <<<dim3(C_, B_), 128>>>();
    k_out   <<<25088, 256>>>(x, out);
}

// round 11
// speedup vs baseline: 3.0467x; 1.1729x over previous
#include <cuda_runtime.h>
#include <cuda_fp16.h>
#include <math.h>

#define B_ 32
#define C_ 256
#define H_ 56
#define W_ 56
#define HW_ 3136
#define G_ 8
#define CG_ 32
#define BG_ 256
#define EPSV 1e-5f

// ---------------- static device scratch ----------------
__device__ __half d_x16[(size_t)B_*C_*HW_];   // fp16 x, NCHW
__device__ __half d_xT [(size_t)B_*HW_*C_];   // fp16 x, NHWC
__device__ __half d_w4c[(size_t)2304*256];    // w3b -> [ic*9+r][o]
__device__ __half d_wr [9*256];               // wr[r][ic] = sum_o w3b[o][ic][r]
__device__ __half d_w2t[9*32*32];             // w3a -> [r][o][i]
__device__ float d_xhm[BG_*CG_*H_], d_xwm[BG_*CG_*W_];
__device__ float d_sh [BG_*CG_*H_], d_sw [BG_*CG_*W_];
__device__ float d_chsum[BG_*CG_], d_chsq[BG_*CG_];
__device__ float d_mu[BG_*CG_], d_rstd[BG_*CG_];
__device__ float d_bm[C_], d_rbstd[C_];
__device__ float d_x11[CG_];
__device__ float d_m2[BG_*CG_];
__device__ float d_A1[BG_*CG_], d_C1[BG_];
__device__ float d_w1[(size_t)BG_*HW_];
__device__ float d_s3[(size_t)B_*HW_], d_s4[(size_t)B_*HW_];
__device__ float d_y[(size_t)B_*C_*9];
__device__ float d_t4[B_*C_];
__device__ float d_sw2[B_*C_];

// ---------------- helpers ----------------
__device__ __forceinline__ unsigned smem_u32(const void* p){
    return (unsigned)__cvta_generic_to_shared(p);
}
__device__ __forceinline__ void ldsm4(unsigned a, unsigned &r0, unsigned &r1, unsigned &r2, unsigned &r3){
    asm volatile("ldmatrix.sync.aligned.m8n8.x4.shared.b16 {%0,%1,%2,%3},[%4];\n"
        : "=r"(r0),"=r"(r1),"=r"(r2),"=r"(r3) : "r"(a));
}
__device__ __forceinline__ void mma16816(float* c, unsigned a0, unsigned a1, unsigned a2, unsigned a3,
                                         unsigned b0, unsigned b1){
    asm volatile("mma.sync.aligned.m16n8k16.row.col.f32.f16.f16.f32 "
        "{%0,%1,%2,%3}, {%4,%5,%6,%7}, {%8,%9}, {%0,%1,%2,%3};\n"
        : "+f"(c[0]),"+f"(c[1]),"+f"(c[2]),"+f"(c[3])
        : "r"(a0),"r"(a1),"r"(a2),"r"(a3),"r"(b0),"r"(b1));
}
__device__ __forceinline__ float sigf(float v){ return 1.f/(1.f+expf(-v)); }

// ---------------- small kernels ----------------
__global__ void k_zero(){
    int i = blockIdx.x*blockDim.x + threadIdx.x;
    if (i < BG_*CG_) d_m2[i] = 0.f;
}

__global__ void k_wprep(const float* __restrict__ w3b, const float* __restrict__ w3a){
    int j = blockIdx.x*blockDim.x + threadIdx.x;
    if (j < 256*2304){
        int o = j/2304, k = j - o*2304;
        d_w4c[(size_t)k*256 + o] = __float2half(w3b[j]);
    }
    if (j < 32*32*9){
        int o = j/288, ic = (j/9)%32, r = j%9;
        d_w2t[(r*32+o)*32+ic] = __float2half(w3a[j]);
    }
    if (j < 2304){
        float s = 0.f;
        for (int o=0;o<256;o++) s += w3b[o*2304 + j];
        int ic = j/9, r = j - ic*9;
        d_wr[r*256 + ic] = __float2half(s);
    }
}

__global__ void k_x11(const float* __restrict__ gnb){
    int t = threadIdx.x;
    float v = gnb[t], m = v;
    #pragma unroll
    for (int s=16;s;s>>=1) m = fmaxf(m, __shfl_xor_sync(~0u, m, s));
    float e = expf(v-m), sum = e;
    #pragma unroll
    for (int s=16;s;s>>=1) sum += __shfl_xor_sync(~0u, sum, s);
    d_x11[t] = e/sum;
}

__global__ void __launch_bounds__(256) k_rowcol(const float* __restrict__ x){
    __shared__ float tile[HW_];
    int ch = blockIdx.x;
    const float* src = x + (size_t)ch*HW_;
    __half2* dst = (__half2*)(d_x16 + (size_t)ch*HW_);
    for (int i = threadIdx.x*4; i < HW_; i += 1024){
        float4 v = *(const float4*)(src+i);
        tile[i]=v.x; tile[i+1]=v.y; tile[i+2]=v.z; tile[i+3]=v.w;
        dst[i>>1]     = __floats2half2_rn(v.x, v.y);
        dst[(i>>1)+1] = __floats2half2_rn(v.z, v.w);
    }
    __syncthreads();
    int t = threadIdx.x;
    if (t < H_){
        float rs = 0.f, cs = 0.f;
        #pragma unroll 8
        for (int w = 0; w < W_; w++) rs += tile[t*W_ + w];
        #pragma unroll 8
        for (int h = 0; h < H_; h++) cs += tile[h*W_ + t];
        d_xhm[ch*H_ + t] = rs * (1.0f/W_);
        d_xwm[ch*W_ + t] = cs * (1.0f/H_);
    }
}

// NCHW fp32 -> NHWC fp16 transpose
__global__ void __launch_bounds__(256) k_tr(const float* __restrict__ x){
    __shared__ __half sm[16*256];
    int b = blockIdx.y, p0 = blockIdx.x*16;
    int t = threadIdx.x;
    const float* src = x + (size_t)(b*C_ + t)*HW_ + p0;
    #pragma unroll
    for (int i=0;i<16;i+=4){
        float4 v = *(const float4*)(src+i);
        sm[(i+0)*256 + t] = __float2half(v.x);
        sm[(i+1)*256 + t] = __float2half(v.y);
        sm[(i+2)*256 + t] = __float2half(v.z);
        sm[(i+3)*256 + t] = __float2half(v.w);
    }
    __syncthreads();
    __half* dst = d_xT + ((size_t)b*HW_ + p0)*256;
    #pragma unroll
    for (int k=0;k<2;k++){
        int idx = t + k*256;
        int px = idx>>5, cc = (idx&31)*8;
        *(uint4*)&dst[(size_t)px*256 + cc] = *(uint4*)&sm[px*256+cc];
    }
}

__global__ void __launch_bounds__(128) k_hw(const float* __restrict__ w1, const float* __restrict__ b1){
    __shared__ float ws[1024], cat[32*112], bs[32];
    int bg = blockIdx.x;
    for (int i = threadIdx.x; i < 1024; i += 128) ws[i] = w1[i];
    if (threadIdx.x < 32) bs[threadIdx.x] = b1[threadIdx.x];
    for (int i = threadIdx.x; i < 32*112; i += 128){
        int c = i/112, p = i%112;
        cat[i] = (p < H_) ? d_xhm[(bg*CG_+c)*H_+p] : d_xwm[(bg*CG_+c)*W_+(p-H_)];
    }
    __syncthreads();
    for (int i = threadIdx.x; i < 32*112; i += 128){
        int o = i/112, p = i%112;
        float acc = bs[o];
        #pragma unroll 8
        for (int c = 0; c < 32; c++) acc += ws[o*32+c]*cat[c*112+p];
        float s = sigf(acc);
        if (p < H_) d_sh[(bg*CG_+o)*H_+p] = s;
        else        d_sw[(bg*CG_+o)*W_+(p-H_)] = s;
    }
}

__global__ void __launch_bounds__(128) k_stats(){
    int ch = blockIdx.x;
    const __half* src = d_x16 + (size_t)ch*HW_;
    const float* shp = d_sh + ch*H_;
    const float* swp = d_sw + ch*W_;
    float s = 0.f, q = 0.f;
    for (int i = threadIdx.x; i < HW_; i += 128){
        float v = __half2float(src[i])*shp[i/W_]*swp[i%W_];
        s += v; q += v*v;
    }
    __shared__ float ss[4], qq[4];
    int lane = threadIdx.x & 31, w = threadIdx.x >> 5;
    #pragma unroll
    for (int o=16;o;o>>=1){ s += __shfl_xor_sync(~0u,s,o); q += __shfl_xor_sync(~0u,q,o); }
    if (lane==0){ ss[w]=s; qq[w]=q; }
    __syncthreads();
    if (threadIdx.x==0){
        d_chsum[ch] = ss[0]+ss[1]+ss[2]+ss[3];
        d_chsq [ch] = qq[0]+qq[1]+qq[2]+qq[3];
    }
}

__global__ void k_fin(){
    int i = blockIdx.x*blockDim.x + threadIdx.x;
    if (i < BG_*CG_){
        float mu = d_chsum[i]*(1.0f/HW_);
        float var = d_chsq[i]*(1.0f/HW_) - mu*mu;
        d_mu[i] = mu;
        d_rstd[i] = rsqrtf(var + EPSV);
    }
    if (i < C_){
        float s = 0.f, q = 0.f;
        for (int b = 0; b < B_; b++){ s += d_chsum[b*C_+i]; q += d_chsq[b*C_+i]; }
        const float n = (float)B_*(float)HW_;
        float bm = s/n, bv = q/n - bm*bm;
        d_bm[i] = bm;
        d_rbstd[i] = rsqrtf(bv + EPSV);
    }
}

// ---------------- conv2: NHWC grouped 3x3, whole-tap smem staging, 1 sync ----------------
#define W2_OFF 31680
#define C2_DYN (31680+23040)
__global__ void __launch_bounds__(256) k_conv2(const float* __restrict__ b3a){
    extern __shared__ __align__(16) char dsm2[];
    __shared__ float red[256], x11s[32], b3as[32];
    int y0 = blockIdx.x*4, bg = blockIdx.y;
    int b = bg>>3, g = bg&7;
    int t = threadIdx.x, lane = t&31, w = t>>5;
    int wm = w&3, wn = w>>2;
    unsigned smB = smem_u32(dsm2);
    if (t<32){ x11s[t]=d_x11[t]; b3as[t]=b3a[t]; }
    red[t] = 0.f;

    const __half* xTb = d_xT + (size_t)b*HW_*256 + g*32;
    for (int ga = t; ga < 1584; ga += 256){
        int p = ga>>2, h = ga&3;
        int arow = p/66, acol = p - arow*66;
        int yy = y0 - 1 + arow, cx = acol - 1;
        bool v = (yy>=0 && yy<H_ && cx>=0 && cx<W_);
        const __half* src = xTb + ((size_t)((v?yy:0)*W_ + (v?cx:0)))*256 + h*8;
        unsigned dst = smB + (unsigned)(p*80 + h*16);
        int ss = v?16:0;
        asm volatile("cp.async.cg.shared.global [%0], [%1], 16, %2;\n"
                     :: "r"(dst), "l"(src), "r"(ss) : "memory");
    }
    for (int ga = t; ga < 1152; ga += 256){
        int r = ga>>7, rem = ga&127, o = rem>>2, h = rem&3;
        const __half* src = d_w2t + (r*32+o)*32 + h*8;
        unsigned dst = smB + (unsigned)(W2_OFF + r*2560 + o*80 + h*16);
        asm volatile("cp.async.cg.shared.global [%0], [%1], 16;\n"
                     :: "r"(dst), "l"(src) : "memory");
    }
    asm volatile("cp.async.commit_group;\ncp.async.wait_group 0;\n" ::: "memory");
    __syncthreads();

    float acc[4][2][4];
    #pragma unroll
    for (int f=0;f<4;f++)
        #pragma unroll
        for (int j=0;j<2;j++){ acc[f][j][0]=0.f; acc[f][j][1]=0.f; acc[f][j][2]=0.f; acc[f][j][3]=0.f; }

    int o_l = wn*16 + (lane&7) + ((lane>>4)<<3);
    unsigned wofs = (unsigned)(W2_OFF + o_l*80 + ((lane>>3)&1)*16);
    #pragma unroll
    for (int r=0;r<9;r++){
        int dy = r/3 - 1, dx = r - (r/3)*3 - 1;
        int rowbase = (wm+1+dy)*66 + 1 + dx;
        #pragma unroll
        for (int kc=0;kc<2;kc++){
            unsigned b0,b1,b2,b3;
            ldsm4(smB + wofs + (unsigned)(r*2560 + kc*32), b0,b1,b2,b3);
            #pragma unroll
            for (int f=0;f<4;f++){
                int P = rowbase + f*16 + (lane&15);
                unsigned a0,a1,a2,a3;
                ldsm4(smB + (unsigned)(P*80 + kc*32 + (lane>>4)*16), a0,a1,a2,a3);
                mma16816(acc[f][0], a0,a1,a2,a3, b0,b1);
                mma16816(acc[f][1], a0,a1,a2,a3, b2,b3);
            }
        }
    }

    int pr = lane>>2, c2 = (lane&3)*2;
    float m2a[4] = {0.f,0.f,0.f,0.f};
    #pragma unroll
    for (int f=0;f<4;f++){
        int p0 = f*16 + pr, p1 = p0 + 8;
        float w0 = 0.f, w1v = 0.f;
        #pragma unroll
        for (int jj=0;jj<2;jj++){
            int chl = wn*16 + jj*8 + c2;
            float bb0 = b3as[chl], bb1 = b3as[chl+1];
            float v0 = acc[f][jj][0]+bb0, v1 = acc[f][jj][1]+bb1;
            float v2 = acc[f][jj][2]+bb0, v3 = acc[f][jj][3]+bb1;
            if (p0 < W_){ w0  += x11s[chl]*v0 + x11s[chl+1]*v1; m2a[jj*2] += v0; m2a[jj*2+1] += v1; }
            if (p1 < W_){ w1v += x11s[chl]*v2 + x11s[chl+1]*v3; m2a[jj*2] += v2; m2a[jj*2+1] += v3; }
        }
        w0  += __shfl_xor_sync(~0u,w0,1);  w0  += __shfl_xor_sync(~0u,w0,2);
        w1v += __shfl_xor_sync(~0u,w1v,1); w1v += __shfl_xor_sync(~0u,w1v,2);
        if ((lane&3)==0){
            if (p0 < W_) atomicAdd(&red[wm*64+p0], w0);
            if (p1 < W_) atomicAdd(&red[wm*64+p1], w1v);
        }
    }
    #pragma unroll
    for (int k=0;k<4;k++){
        m2a[k] += __shfl_xor_sync(~0u,m2a[k],4);
        m2a[k] += __shfl_xor_sync(~0u,m2a[k],8);
        m2a[k] += __shfl_xor_sync(~0u,m2a[k],16);
    }
    if (pr==0 && (lane>>3)==0){
        #pragma unroll
        for (int k=0;k<4;k++){
            int chl = wn*16 + (k>>1)*8 + c2 + (k&1);
            atomicAdd(&d_m2[bg*CG_ + chl], m2a[k]);
        }
    }
    __syncthreads();
    {
        int yr = y0 + (t>>6), col = t&63;
        if (col < W_) d_w1[(size_t)bg*HW_ + yr*W_ + col] = red[t];
    }
}

__global__ void k_x21(const float* __restrict__ gnw, const float* __restrict__ gnb){
    int bg = blockIdx.x, t = threadIdx.x;
    float v = d_m2[bg*CG_+t]*(1.0f/HW_);
    float m = v;
    #pragma unroll
    for (int s=16;s;s>>=1) m = fmaxf(m, __shfl_xor_sync(~0u,m,s));
    float e = expf(v-m), sum = e;
    #pragma unroll
    for (int s=16;s;s>>=1) sum += __shfl_xor_sync(~0u,sum,s);
    float x21 = e/sum;
    float rs = d_rstd[bg*CG_+t], mu = d_mu[bg*CG_+t];
    d_A1[bg*CG_+t] = x21*gnw[t]*rs;
    float cc = x21*(gnb[t] - gnw[t]*rs*mu);
    #pragma unroll
    for (int s=16;s;s>>=1) cc += __shfl_xor_sync(~0u,cc,s);
    if (t==0) d_C1[bg] = cc;
}

// ---------------- s4 logits: z[p] = sum_{ic,r} wr[r][ic] * xT[p+delta_r][ic] ----------------
__global__ void __launch_bounds__(256) k_s4logit(){
    __shared__ __half wrs[9*256];
    int y = blockIdx.x, b = blockIdx.y;
    int t = threadIdx.x, lane = t&31, w = t>>5;
    for (int i = t; i < 288; i += 256)      // FIX: full 288-uint4 staging (was if(t<288) with 256 threads)
        ((uint4*)wrs)[i] = ((const uint4*)d_wr)[i];
    __syncthreads();
    const __half* xTb = d_xT + (size_t)b*HW_*256;
    #pragma unroll
    for (int px=0; px<7; px++){
        int j = w*7 + px;
        float acc = 0.f;
        #pragma unroll
        for (int r=0;r<9;r++){
            int yy = y + r/3 - 1, xx = j + r%3 - 1;
            if (yy>=0 && yy<H_ && xx>=0 && xx<W_){
                uint4 xv = *(const uint4*)(xTb + ((size_t)(yy*W_+xx))*256 + lane*8);
                uint4 wv = *(const uint4*)(wrs + r*256 + lane*8);
                __half2* xh = (__half2*)&xv;
                __half2* wh = (__half2*)&wv;
                __half2 p = __hmul2(xh[0], wh[0]);
                p = __hfma2(xh[1], wh[1], p);
                p = __hfma2(xh[2], wh[2], p);
                p = __hfma2(xh[3], wh[3], p);
                float2 f = __half22float2(p);
                acc += f.x + f.y;
            }
        }
        #pragma unroll
        for (int s=16;s;s>>=1) acc += __shfl_xor_sync(~0u,acc,s);
        if (lane==0) d_s4[(size_t)b*HW_ + y*W_ + j] = acc;
    }
}

// ---------------- y correlation: y[b,ic,r] = sum_p s3[b,p] * xpad[b,ic,p+delta_r] ----------------
__global__ void __launch_bounds__(128) k_ycorr(){
    __shared__ __half xs[58*58];
    __shared__ float s3s[HW_];
    __shared__ float racc[9][4];
    int ic = blockIdx.x, b = blockIdx.y;
    int ch = b*C_ + ic;
    int t = threadIdx.x;
    for (int i=t;i<58*58;i+=128) xs[i] = __float2half(0.f);
    __syncthreads();
    const __half* src = d_x16 + (size_t)ch*HW_;
    const float* s3g = d_s3 + (size_t)b*HW_;
    for (int i=t;i<HW_;i+=128){
        int y = i/W_, x = i - y*W_;
        xs[(y+1)*58 + x+1] = src[i];
        s3s[i] = s3g[i];
    }
    __syncthreads();
    float a[9] = {0,0,0,0,0,0,0,0,0};
    for (int i=t;i<HW_;i+=128){
        int y = i/W_, x = i - y*W_;
        float s = s3s[i];
        int base = y*58 + x;
        #pragma unroll
        for (int r=0;r<9;r++)
            a[r] += s * __half2float(xs[base + (r/3)*58 + (r%3)]);
    }
    int lane = t&31, w = t>>5;
    #pragma unroll
    for (int r=0;r<9;r++){
        float v = a[r];
        #pragma unroll
        for (int s=16;s;s>>=1) v += __shfl_xor_sync(~0u,v,s);
        if (lane==0) racc[r][w] = v;
    }
    __syncthreads();
    if (t < 9)
        d_y[(size_t)(b*C_+ic)*9 + t] = racc[t][0]+racc[t][1]+racc[t][2]+racc[t][3];
}

// ---------------- t4[b,c] = b3b[c] + sum_k w4c[k][c] * y[b][k] ----------------
__global__ void __launch_bounds__(256) k_t4mat(const float* __restrict__ b3b){
    __shared__ float ys[2304];
    int b = blockIdx.x, t = threadIdx.x;
    for (int i=t;i<2304;i+=256) ys[i] = d_y[(size_t)b*2304 + i];
    __syncthreads();
    float acc = b3b[t];
    #pragma unroll 8
    for (int k=0;k<2304;k++)
        acc += __half2float(d_w4c[(size_t)k*256 + t]) * ys[k];
    d_t4[b*C_ + t] = acc;
}

__global__ void __launch_bounds__(224) k_pass3(){
    __shared__ float s3red[4][56];
    int y = blockIdx.x, b = blockIdx.y;
    int t = threadIdx.x, cl = t/56, j = t%56;
    float s3acc = 0.f;
    for (int gi=0;gi<2;gi++){
        int g = cl*2+gi, bg = b*G_+g;
        float t2 = 0.f;
        #pragma unroll 4
        for (int ci=0;ci<CG_;ci++){
            int ch = b*C_ + g*CG_ + ci;
            float xv = __half2float(d_x16[(size_t)ch*HW_ + y*W_ + j]);
            float x0 = xv * d_sh[ch*H_+y] * d_sw[ch*W_+j];
            s3acc += x0 * d_rbstd[g*CG_+ci];
            t2 += d_A1[ch]*x0;
        }
        d_w1[(size_t)bg*HW_ + y*W_ + j] += t2 + d_C1[bg];
    }
    s3red[cl][j] = s3acc;
    __syncthreads();
    if (cl==0)
        d_s3[(size_t)b*HW_ + y*W_ + j] =
            (s3red[0][j]+s3red[1][j]+s3red[2][j]+s3red[3][j])*(1.0f/C_);
}

__global__ void __launch_bounds__(256) k_softmax(int which){
    int row = blockIdx.x;
    float scale = which ? (1.0f/C_) : 1.0f;
    float* p = (which ? d_s4 : d_s3) + (size_t)row*HW_;
    __shared__ float red[8];
    int t = threadIdx.x, lane = t&31, wid = t>>5;
    float mx = -1e30f;
    for (int i=t;i<HW_;i+=256) mx = fmaxf(mx, p[i]*scale);
    #pragma unroll
    for (int s=16;s;s>>=1) mx = fmaxf(mx, __shfl_xor_sync(~0u,mx,s));
    if (lane==0) red[wid]=mx;
    __syncthreads();
    mx = red[0];
    #pragma unroll
    for (int i=1;i<8;i++) mx = fmaxf(mx, red[i]);
    __syncthreads();
    float sum = 0.f;
    for (int i=t;i<HW_;i+=256){ float e = expf(p[i]*scale-mx); p[i]=e; sum += e; }
    #pragma unroll
    for (int s=16;s;s>>=1) sum += __shfl_xor_sync(~0u,sum,s);
    if (lane==0) red[wid]=sum;
    __syncthreads();
    sum = 0.f;
    #pragma unroll
    for (int i=0;i<8;i++) sum += red[i];
    float inv = 1.0f/sum;
    for (int i=t;i<HW_;i+=256) p[i] *= inv;
}

__global__ void __launch_bounds__(128) k_wfin(){
    __shared__ float r1s[4];
    int c = blockIdx.x, b = blockIdx.y, ch = b*C_+c;
    int t = threadIdx.x;
    const __half* xp  = d_x16 + (size_t)ch*HW_;
    const float* s4p = d_s4 + (size_t)b*HW_;
    const float* shp = d_sh + ch*H_;
    const float* swp = d_sw + ch*W_;
    float u = 0.f;
    for (int i=t;i<HW_;i+=128){
        float x0 = __half2float(xp[i])*shp[i/W_]*swp[i%W_];
        u += s4p[i]*x0;
    }
    int lane = t&31, wid = t>>5;
    #pragma unroll
    for (int s=16;s;s>>=1) u += __shfl_xor_sync(~0u,u,s);
    if (lane==0) r1s[wid]=u;
    __syncthreads();
    if (t==0){
        u = r1s[0]+r1s[1]+r1s[2]+r1s[3];
        float w2 = d_t4[ch] + d_rbstd[c]*(u - d_bm[c]);
        d_sw2[ch] = sigf(w2);
    }
}

__global__ void __launch_bounds__(256) k_out(const float* __restrict__ x, float* __restrict__ out){
    size_t i = ((size_t)blockIdx.x*256 + threadIdx.x)*4;
    int p = (int)(i % HW_);
    int ch = (int)(i / HW_);
    int b = ch >> 8, c = ch & 255;
    int bg = b*G_ + (c>>5);
    float4 xv = *(const float4*)(x+i);
    const float* w1p = d_w1 + (size_t)bg*HW_ + p;
    float s2 = d_sw2[ch];
    float4 o;
    o.x = xv.x*(sigf(w1p[0]) + s2);
    o.y = xv.y*(sigf(w1p[1]) + s2);
    o.z = xv.z*(sigf(w1p[2]) + s2);
    o.w = xv.w*(sigf(w1p[3]) + s2);
    *(float4*)(out+i) = o;
}

// ---------------- launch ----------------
extern "C" void kernel_launch(void* const* d_in, const int* in_sizes, int n_in,
                              void* d_out, int out_size){
    const float* x   = (const float*)d_in[0];
    const float* w1  = (const float*)d_in[1];
    const float* b1  = (const float*)d_in[2];
    const float* w3a = (const float*)d_in[3];
    const float* b3a = (const float*)d_in[4];
    const float* w3b = (const float*)d_in[5];
    const float* b3b = (const float*)d_in[6];
    const float* gnw = (const float*)d_in[7];
    const float* gnb = (const float*)d_in[8];
    float* out = (float*)d_out;

    static cudaStream_t sB = nullptr;
    static cudaEvent_t evF=nullptr, evW=nullptr, evT=nullptr, evB=nullptr;
    if (!sB){
        cudaStreamCreateWithFlags(&sB, cudaStreamNonBlocking);
        cudaEventCreateWithFlags(&evF, cudaEventDisableTiming);
        cudaEventCreateWithFlags(&evW, cudaEventDisableTiming);
        cudaEventCreateWithFlags(&evT, cudaEventDisableTiming);
        cudaEventCreateWithFlags(&evB, cudaEventDisableTiming);
        cudaFuncSetAttribute(k_conv2, cudaFuncAttributeMaxDynamicSharedMemorySize, C2_DYN);
    }

    // default: prologue
    k_zero  <<<32, 256>>>();
    cudaEventRecord(evF, 0);
    k_wprep <<<2304, 256>>>(w3b, w3a);
    cudaEventRecord(evW, 0);

    // sB: xT transpose -> s4 logits -> s4 softmax (overlaps the GN chain)
    cudaStreamWaitEvent(sB, evF, 0);
    k_tr    <<<dim3(196, B_), 256, 0, sB>>>(x);
    cudaEventRecord(evT, sB);
    cudaStreamWaitEvent(sB, evW, 0);
    k_s4logit<<<dim3(H_, B_), 256, 0, sB>>>();
    k_softmax<<<B_, 256, 0, sB>>>(1);
    cudaEventRecord(evB, sB);

    // default: gating / GN chain
    k_x11   <<<1, 32>>>(gnb);
    k_rowcol<<<B_*C_, 256>>>(x);
    k_hw    <<<BG_, 128>>>(w1, b1);
    k_stats <<<B_*C_, 128>>>();
    k_fin   <<<32, 256>>>();
    cudaStreamWaitEvent(0, evT, 0);
    k_conv2 <<<dim3(H_/4, BG_), 256, C2_DYN>>>(b3a);
    k_x21   <<<BG_, 32>>>(gnw, gnb);
    k_pass3 <<<dim3(H_, B_), 224>>>();
    k_softmax<<<B_, 256>>>(0);
    k_ycorr <<<dim3(C_, B_), 128>>>();
    k_t4mat <<<B_, 256>>>(b3b);
    cudaStreamWaitEvent(0, evB, 0);
    k_wfin  <<<dim3(C_, B_), 128>>>();
    k_out   <<<25088, 256>>>(x, out);
}

// round 12
// speedup vs baseline: 3.1616x; 1.0377x over previous
#include <cuda_runtime.h>
#include <cuda_fp16.h>
#include <math.h>

#define B_ 32
#define C_ 256
#define H_ 56
#define W_ 56
#define HW_ 3136
#define G_ 8
#define CG_ 32
#define BG_ 256
#define EPSV 1e-5f

// ---------------- static device scratch ----------------
__device__ __half d_xT [(size_t)B_*HW_*C_];   // fp16 x, NHWC
__device__ __half d_w4c[(size_t)2304*256];    // w3b -> [ic*9+r][o]
__device__ __half d_wr [9*256];               // wr[r][ic] = sum_o w3b[o][ic][r]
__device__ __half d_w2t[9*32*32];             // w3a -> [r][o][i]
__device__ float d_xhm[BG_*CG_*H_], d_xwm[BG_*CG_*W_];
__device__ float d_shT[(size_t)B_*H_*C_];     // gate sigmoid(xh), [b][y][c]
__device__ float d_swT[(size_t)B_*W_*C_];     // gate sigmoid(xw), [b][j][c]
__device__ float d_chsum[BG_*CG_], d_chsq[BG_*CG_];
__device__ float d_mu[BG_*CG_], d_rstd[BG_*CG_];
__device__ float d_bm[C_], d_rbstd[C_];
__device__ float d_x11[CG_];
__device__ float d_m2[BG_*CG_];
__device__ float d_A1[BG_*CG_], d_C1[BG_];
__device__ float d_w1[(size_t)BG_*HW_];
__device__ float d_s3[(size_t)B_*HW_], d_s4[(size_t)B_*HW_];
__device__ float d_y[(size_t)B_*C_*9];
__device__ float d_t4[B_*C_];
__device__ float d_u[B_*C_];
__device__ float d_sw2[B_*C_];

// ---------------- helpers ----------------
__device__ __forceinline__ unsigned smem_u32(const void* p){
    return (unsigned)__cvta_generic_to_shared(p);
}
__device__ __forceinline__ void ldsm4(unsigned a, unsigned &r0, unsigned &r1, unsigned &r2, unsigned &r3){
    asm volatile("ldmatrix.sync.aligned.m8n8.x4.shared.b16 {%0,%1,%2,%3},[%4];\n"
        : "=r"(r0),"=r"(r1),"=r"(r2),"=r"(r3) : "r"(a));
}
__device__ __forceinline__ void mma16816(float* c, unsigned a0, unsigned a1, unsigned a2, unsigned a3,
                                         unsigned b0, unsigned b1){
    asm volatile("mma.sync.aligned.m16n8k16.row.col.f32.f16.f16.f32 "
        "{%0,%1,%2,%3}, {%4,%5,%6,%7}, {%8,%9}, {%0,%1,%2,%3};\n"
        : "+f"(c[0]),"+f"(c[1]),"+f"(c[2]),"+f"(c[3])
        : "r"(a0),"r"(a1),"r"(a2),"r"(a3),"r"(b0),"r"(b1));
}
__device__ __forceinline__ float sigf(float v){ return 1.f/(1.f+expf(-v)); }

// ---------------- small kernels ----------------
__global__ void k_zero(){
    int i = blockIdx.x*blockDim.x + threadIdx.x;
    if (i < BG_*CG_){ d_m2[i] = 0.f; d_chsum[i] = 0.f; d_chsq[i] = 0.f; d_u[i] = 0.f; }
    if (i < B_*C_*9) d_y[i] = 0.f;
}

__global__ void k_wprep(const float* __restrict__ w3b, const float* __restrict__ w3a){
    int j = blockIdx.x*blockDim.x + threadIdx.x;
    if (j < 256*2304){
        int o = j/2304, k = j - o*2304;
        d_w4c[(size_t)k*256 + o] = __float2half(w3b[j]);
    }
    if (j < 32*32*9){
        int o = j/288, ic = (j/9)%32, r = j%9;
        d_w2t[(r*32+o)*32+ic] = __float2half(w3a[j]);
    }
    if (j < 2304){
        float s = 0.f;
        for (int o=0;o<256;o++) s += w3b[o*2304 + j];
        int ic = j/9, r = j - ic*9;
        d_wr[r*256 + ic] = __float2half(s);
    }
}

__global__ void k_x11(const float* __restrict__ gnb){
    int t = threadIdx.x;
    float v = gnb[t], m = v;
    #pragma unroll
    for (int s=16;s;s>>=1) m = fmaxf(m, __shfl_xor_sync(~0u, m, s));
    float e = expf(v-m), sum = e;
    #pragma unroll
    for (int s=16;s;s>>=1) sum += __shfl_xor_sync(~0u, sum, s);
    d_x11[t] = e/sum;
}

// row/col means per channel (reads fp32 x once; no fp16 mirror anymore)
__global__ void __launch_bounds__(256) k_rowcol(const float* __restrict__ x){
    __shared__ float tile[HW_];
    int ch = blockIdx.x;
    const float* src = x + (size_t)ch*HW_;
    for (int i = threadIdx.x*4; i < HW_; i += 1024){
        float4 v = *(const float4*)(src+i);
        tile[i]=v.x; tile[i+1]=v.y; tile[i+2]=v.z; tile[i+3]=v.w;
    }
    __syncthreads();
    int t = threadIdx.x;
    if (t < H_){
        float rs = 0.f, cs = 0.f;
        #pragma unroll 8
        for (int w = 0; w < W_; w++) rs += tile[t*W_ + w];
        #pragma unroll 8
        for (int h = 0; h < H_; h++) cs += tile[h*W_ + t];
        d_xhm[ch*H_ + t] = rs * (1.0f/W_);
        d_xwm[ch*W_ + t] = cs * (1.0f/H_);
    }
}

// NCHW fp32 -> NHWC fp16 transpose
__global__ void __launch_bounds__(256) k_tr(const float* __restrict__ x){
    __shared__ __half sm[16*256];
    int b = blockIdx.y, p0 = blockIdx.x*16;
    int t = threadIdx.x;
    const float* src = x + (size_t)(b*C_ + t)*HW_ + p0;
    #pragma unroll
    for (int i=0;i<16;i+=4){
        float4 v = *(const float4*)(src+i);
        sm[(i+0)*256 + t] = __float2half(v.x);
        sm[(i+1)*256 + t] = __float2half(v.y);
        sm[(i+2)*256 + t] = __float2half(v.z);
        sm[(i+3)*256 + t] = __float2half(v.w);
    }
    __syncthreads();
    __half* dst = d_xT + ((size_t)b*HW_ + p0)*256;
    #pragma unroll
    for (int k=0;k<2;k++){
        int idx = t + k*256;
        int px = idx>>5, cc = (idx&31)*8;
        *(uint4*)&dst[(size_t)px*256 + cc] = *(uint4*)&sm[px*256+cc];
    }
}

// 1x1 conv on [xh;xw] + sigmoid; writes TRANSPOSED gate layouts
__global__ void __launch_bounds__(128) k_hw(const float* __restrict__ w1, const float* __restrict__ b1){
    __shared__ float ws[1024], cat[32*112], bs[32];
    int bg = blockIdx.x;
    int b = bg>>3, g = bg&7;
    for (int i = threadIdx.x; i < 1024; i += 128) ws[i] = w1[i];
    if (threadIdx.x < 32) bs[threadIdx.x] = b1[threadIdx.x];
    for (int i = threadIdx.x; i < 32*112; i += 128){
        int c = i/112, p = i%112;
        cat[i] = (p < H_) ? d_xhm[(bg*CG_+c)*H_+p] : d_xwm[(bg*CG_+c)*W_+(p-H_)];
    }
    __syncthreads();
    for (int i = threadIdx.x; i < 32*112; i += 128){
        int o = i/112, p = i%112;
        float acc = bs[o];
        #pragma unroll 8
        for (int c = 0; c < 32; c++) acc += ws[o*32+c]*cat[c*112+p];
        float s = sigf(acc);
        if (p < H_) d_shT[((size_t)b*H_ + p)*C_ + g*CG_ + o] = s;
        else        d_swT[((size_t)b*W_ + (p-H_))*C_ + g*CG_ + o] = s;
    }
}

// per-channel sum/sumsq of x0, NHWC coalesced; block=(y,b), thread=channel
__global__ void __launch_bounds__(256) k_stats(){
    int y = blockIdx.x, b = blockIdx.y;
    int c = threadIdx.x;
    float shv = d_shT[((size_t)b*H_ + y)*C_ + c];
    const __half* xp = d_xT + ((size_t)(b*HW_ + y*W_))*C_ + c;
    const float* swp = d_swT + (size_t)b*W_*C_ + c;
    float s = 0.f, q = 0.f;
    #pragma unroll 4
    for (int j=0;j<W_;j++){
        float v = __half2float(xp[(size_t)j*C_]) * shv * swp[(size_t)j*C_];
        s += v; q += v*v;
    }
    atomicAdd(&d_chsum[b*C_ + c], s);
    atomicAdd(&d_chsq [b*C_ + c], q);
}

__global__ void k_fin(){
    int i = blockIdx.x*blockDim.x + threadIdx.x;
    if (i < BG_*CG_){
        float mu = d_chsum[i]*(1.0f/HW_);
        float var = d_chsq[i]*(1.0f/HW_) - mu*mu;
        d_mu[i] = mu;
        d_rstd[i] = rsqrtf(var + EPSV);
    }
    if (i < C_){
        float s = 0.f, q = 0.f;
        for (int b = 0; b < B_; b++){ s += d_chsum[b*C_+i]; q += d_chsq[b*C_+i]; }
        const float n = (float)B_*(float)HW_;
        float bm = s/n, bv = q/n - bm*bm;
        d_bm[i] = bm;
        d_rbstd[i] = rsqrtf(bv + EPSV);
    }
}

// ---------------- conv2: NHWC grouped 3x3, whole-tap smem staging, 1 sync ----------------
#define W2_OFF 31680
#define C2_DYN (31680+23040)
__global__ void __launch_bounds__(256) k_conv2(const float* __restrict__ b3a){
    extern __shared__ __align__(16) char dsm2[];
    __shared__ float red[256], x11s[32], b3as[32];
    int y0 = blockIdx.x*4, bg = blockIdx.y;
    int b = bg>>3, g = bg&7;
    int t = threadIdx.x, lane = t&31, w = t>>5;
    int wm = w&3, wn = w>>2;
    unsigned smB = smem_u32(dsm2);
    if (t<32){ x11s[t]=d_x11[t]; b3as[t]=b3a[t]; }
    red[t] = 0.f;

    const __half* xTb = d_xT + (size_t)b*HW_*256 + g*32;
    for (int ga = t; ga < 1584; ga += 256){
        int p = ga>>2, h = ga&3;
        int arow = p/66, acol = p - arow*66;
        int yy = y0 - 1 + arow, cx = acol - 1;
        bool v = (yy>=0 && yy<H_ && cx>=0 && cx<W_);
        const __half* src = xTb + ((size_t)((v?yy:0)*W_ + (v?cx:0)))*256 + h*8;
        unsigned dst = smB + (unsigned)(p*80 + h*16);
        int ss = v?16:0;
        asm volatile("cp.async.cg.shared.global [%0], [%1], 16, %2;\n"
                     :: "r"(dst), "l"(src), "r"(ss) : "memory");
    }
    for (int ga = t; ga < 1152; ga += 256){
        int r = ga>>7, rem = ga&127, o = rem>>2, h = rem&3;
        const __half* src = d_w2t + (r*32+o)*32 + h*8;
        unsigned dst = smB + (unsigned)(W2_OFF + r*2560 + o*80 + h*16);
        asm volatile("cp.async.cg.shared.global [%0], [%1], 16;\n"
                     :: "r"(dst), "l"(src) : "memory");
    }
    asm volatile("cp.async.commit_group;\ncp.async.wait_group 0;\n" ::: "memory");
    __syncthreads();

    float acc[4][2][4];
    #pragma unroll
    for (int f=0;f<4;f++)
        #pragma unroll
        for (int j=0;j<2;j++){ acc[f][j][0]=0.f; acc[f][j][1]=0.f; acc[f][j][2]=0.f; acc[f][j][3]=0.f; }

    int o_l = wn*16 + (lane&7) + ((lane>>4)<<3);
    unsigned wofs = (unsigned)(W2_OFF + o_l*80 + ((lane>>3)&1)*16);
    #pragma unroll
    for (int r=0;r<9;r++){
        int dy = r/3 - 1, dx = r - (r/3)*3 - 1;
        int rowbase = (wm+1+dy)*66 + 1 + dx;
        #pragma unroll
        for (int kc=0;kc<2;kc++){
            unsigned b0,b1,b2,b3;
            ldsm4(smB + wofs + (unsigned)(r*2560 + kc*32), b0,b1,b2,b3);
            #pragma unroll
            for (int f=0;f<4;f++){
                int P = rowbase + f*16 + (lane&15);
                unsigned a0,a1,a2,a3;
                ldsm4(smB + (unsigned)(P*80 + kc*32 + (lane>>4)*16), a0,a1,a2,a3);
                mma16816(acc[f][0], a0,a1,a2,a3, b0,b1);
                mma16816(acc[f][1], a0,a1,a2,a3, b2,b3);
            }
        }
    }

    int pr = lane>>2, c2 = (lane&3)*2;
    float m2a[4] = {0.f,0.f,0.f,0.f};
    #pragma unroll
    for (int f=0;f<4;f++){
        int p0 = f*16 + pr, p1 = p0 + 8;
        float w0 = 0.f, w1v = 0.f;
        #pragma unroll
        for (int jj=0;jj<2;jj++){
            int chl = wn*16 + jj*8 + c2;
            float bb0 = b3as[chl], bb1 = b3as[chl+1];
            float v0 = acc[f][jj][0]+bb0, v1 = acc[f][jj][1]+bb1;
            float v2 = acc[f][jj][2]+bb0, v3 = acc[f][jj][3]+bb1;
            if (p0 < W_){ w0  += x11s[chl]*v0 + x11s[chl+1]*v1; m2a[jj*2] += v0; m2a[jj*2+1] += v1; }
            if (p1 < W_){ w1v += x11s[chl]*v2 + x11s[chl+1]*v3; m2a[jj*2] += v2; m2a[jj*2+1] += v3; }
        }
        w0  += __shfl_xor_sync(~0u,w0,1);  w0  += __shfl_xor_sync(~0u,w0,2);
        w1v += __shfl_xor_sync(~0u,w1v,1); w1v += __shfl_xor_sync(~0u,w1v,2);
        if ((lane&3)==0){
            if (p0 < W_) atomicAdd(&red[wm*64+p0], w0);
            if (p1 < W_) atomicAdd(&red[wm*64+p1], w1v);
        }
    }
    #pragma unroll
    for (int k=0;k<4;k++){
        m2a[k] += __shfl_xor_sync(~0u,m2a[k],4);
        m2a[k] += __shfl_xor_sync(~0u,m2a[k],8);
        m2a[k] += __shfl_xor_sync(~0u,m2a[k],16);
    }
    if (pr==0 && (lane>>3)==0){
        #pragma unroll
        for (int k=0;k<4;k++){
            int chl = wn*16 + (k>>1)*8 + c2 + (k&1);
            atomicAdd(&d_m2[bg*CG_ + chl], m2a[k]);
        }
    }
    __syncthreads();
    {
        int yr = y0 + (t>>6), col = t&63;
        if (col < W_) d_w1[(size_t)bg*HW_ + yr*W_ + col] = red[t];
    }
}

__global__ void k_x21(const float* __restrict__ gnw, const float* __restrict__ gnb){
    int bg = blockIdx.x, t = threadIdx.x;
    float v = d_m2[bg*CG_+t]*(1.0f/HW_);
    float m = v;
    #pragma unroll
    for (int s=16;s;s>>=1) m = fmaxf(m, __shfl_xor_sync(~0u,m,s));
    float e = expf(v-m), sum = e;
    #pragma unroll
    for (int s=16;s;s>>=1) sum += __shfl_xor_sync(~0u,sum,s);
    float x21 = e/sum;
    float rs = d_rstd[bg*CG_+t], mu = d_mu[bg*CG_+t];
    d_A1[bg*CG_+t] = x21*gnw[t]*rs;
    float cc = x21*(gnb[t] - gnw[t]*rs*mu);
    #pragma unroll
    for (int s=16;s;s>>=1) cc += __shfl_xor_sync(~0u,cc,s);
    if (t==0) d_C1[bg] = cc;
}

// ---------------- s4 logits: z[p] = sum_{ic,r} wr[r][ic] * xT[p+delta_r][ic] ----------------
__global__ void __launch_bounds__(256) k_s4logit(){
    __shared__ __half wrs[9*256];
    int y = blockIdx.x, b = blockIdx.y;
    int t = threadIdx.x, lane = t&31, w = t>>5;
    for (int i = t; i < 288; i += 256)
        ((uint4*)wrs)[i] = ((const uint4*)d_wr)[i];
    __syncthreads();
    const __half* xTb = d_xT + (size_t)b*HW_*256;
    #pragma unroll
    for (int px=0; px<7; px++){
        int j = w*7 + px;
        float acc = 0.f;
        #pragma unroll
        for (int r=0;r<9;r++){
            int yy = y + r/3 - 1, xx = j + r%3 - 1;
            if (yy>=0 && yy<H_ && xx>=0 && xx<W_){
                uint4 xv = *(const uint4*)(xTb + ((size_t)(yy*W_+xx))*256 + lane*8);
                uint4 wv = *(const uint4*)(wrs + r*256 + lane*8);
                __half2* xh = (__half2*)&xv;
                __half2* wh = (__half2*)&wv;
                __half2 p = __hmul2(xh[0], wh[0]);
                p = __hfma2(xh[1], wh[1], p);
                p = __hfma2(xh[2], wh[2], p);
                p = __hfma2(xh[3], wh[3], p);
                float2 f = __half22float2(p);
                acc += f.x + f.y;
            }
        }
        #pragma unroll
        for (int s=16;s;s>>=1) acc += __shfl_xor_sync(~0u,acc,s);
        if (lane==0) d_s4[(size_t)b*HW_ + y*W_ + j] = acc;
    }
}

// ---------------- pass3 NHWC: w1 term2, s3 logits, u = sum s4*x0 — one xT read ----------------
__global__ void __launch_bounds__(256) k_pass3(){
    __shared__ float wacc[8][56];
    int y = blockIdx.x, b = blockIdx.y;
    int c = threadIdx.x, lane = c&31, w = c>>5;
    int bg = b*G_ + w;                       // group == warp (32 channels)
    float shv = d_shT[((size_t)b*H_ + y)*C_ + c];
    float A1v = d_A1[bg*CG_ + lane];
    float rbv = d_rbstd[c];
    float C1v = d_C1[bg];
    const __half* xp = d_xT + ((size_t)(b*HW_ + y*W_))*C_ + c;
    const float* swp = d_swT + (size_t)b*W_*C_ + c;
    const float* s4p = d_s4 + (size_t)b*HW_ + y*W_;
    float* w1p = d_w1 + (size_t)bg*HW_ + y*W_;
    float uacc = 0.f;
    for (int j=0;j<W_;j++){
        float x0 = __half2float(xp[(size_t)j*C_]) * shv * swp[(size_t)j*C_];
        uacc += s4p[j]*x0;
        float t2 = A1v*x0, sl = rbv*x0;
        #pragma unroll
        for (int s=16;s;s>>=1){
            t2 += __shfl_xor_sync(~0u,t2,s);
            sl += __shfl_xor_sync(~0u,sl,s);
        }
        if (lane==0){
            w1p[j] += t2 + C1v;
            wacc[w][j] = sl;
        }
    }
    atomicAdd(&d_u[b*C_ + c], uacc);
    __syncthreads();
    if (c < W_){
        float s = 0.f;
        #pragma unroll
        for (int g=0;g<8;g++) s += wacc[g][c];
        d_s3[(size_t)b*HW_ + y*W_ + c] = s*(1.0f/C_);
    }
}

__global__ void __launch_bounds__(256) k_softmax(int which){
    int row = blockIdx.x;
    float scale = which ? (1.0f/C_) : 1.0f;
    float* p = (which ? d_s4 : d_s3) + (size_t)row*HW_;
    __shared__ float red[8];
    int t = threadIdx.x, lane = t&31, wid = t>>5;
    float mx = -1e30f;
    for (int i=t;i<HW_;i+=256) mx = fmaxf(mx, p[i]*scale);
    #pragma unroll
    for (int s=16;s;s>>=1) mx = fmaxf(mx, __shfl_xor_sync(~0u,mx,s));
    if (lane==0) red[wid]=mx;
    __syncthreads();
    mx = red[0];
    #pragma unroll
    for (int i=1;i<8;i++) mx = fmaxf(mx, red[i]);
    __syncthreads();
    float sum = 0.f;
    for (int i=t;i<HW_;i+=256){ float e = expf(p[i]*scale-mx); p[i]=e; sum += e; }
    #pragma unroll
    for (int s=16;s;s>>=1) sum += __shfl_xor_sync(~0u,sum,s);
    if (lane==0) red[wid]=sum;
    __syncthreads();
    sum = 0.f;
    #pragma unroll
    for (int i=0;i<8;i++) sum += red[i];
    float inv = 1.0f/sum;
    for (int i=t;i<HW_;i+=256) p[i] *= inv;
}

// ---------------- ycorr NHWC: y[b,c,r] += xT[q][c] * s3[q - delta_r] ----------------
__global__ void __launch_bounds__(256) k_ycorr(){
    __shared__ float s3r[3][58];
    int y = blockIdx.x, b = blockIdx.y;
    int c = threadIdx.x;
    if (c < 174){
        int rr = c/58, jj = c%58;
        int yy = y - 1 + rr, xx = jj - 1;
        s3r[rr][jj] = (yy>=0 && yy<H_ && xx>=0 && xx<W_) ? d_s3[(size_t)b*HW_ + yy*W_ + xx] : 0.f;
    }
    __syncthreads();
    const __half* xp = d_xT + ((size_t)(b*HW_ + y*W_))*C_ + c;
    float a[9] = {0,0,0,0,0,0,0,0,0};
    for (int j=0;j<W_;j++){
        float v = __half2float(xp[(size_t)j*C_]);
        #pragma unroll
        for (int r=0;r<9;r++){
            int dy = r/3 - 1, dx = r - (r/3)*3 - 1;
            a[r] += v * s3r[1-dy][j - dx + 1];
        }
    }
    float* yp = d_y + (size_t)b*2304 + c*9;
    #pragma unroll
    for (int r=0;r<9;r++) atomicAdd(&yp[r], a[r]);
}

// ---------------- t4[b,c] = b3b[c] + sum_k w4c[k][c] * y[b][k] ----------------
__global__ void __launch_bounds__(256) k_t4mat(const float* __restrict__ b3b){
    __shared__ float ys[2304];
    int b = blockIdx.x, t = threadIdx.x;
    for (int i=t;i<2304;i+=256) ys[i] = d_y[(size_t)b*2304 + i];
    __syncthreads();
    float acc = b3b[t];
    #pragma unroll 8
    for (int k=0;k<2304;k++)
        acc += __half2float(d_w4c[(size_t)k*256 + t]) * ys[k];
    d_t4[b*C_ + t] = acc;
}

__global__ void k_wfin2(){
    int i = blockIdx.x*blockDim.x + threadIdx.x;
    if (i < B_*C_){
        int c = i & 255;
        float w2 = d_t4[i] + d_rbstd[c]*(d_u[i] - d_bm[c]);
        d_sw2[i] = sigf(w2);
    }
}

__global__ void __launch_bounds__(256) k_out(const float* __restrict__ x, float* __restrict__ out){
    size_t i = ((size_t)blockIdx.x*256 + threadIdx.x)*4;
    int p = (int)(i % HW_);
    int ch = (int)(i / HW_);
    int b = ch >> 8, c = ch & 255;
    int bg = b*G_ + (c>>5);
    float4 xv = *(const float4*)(x+i);
    const float* w1p = d_w1 + (size_t)bg*HW_ + p;
    float s2 = d_sw2[ch];
    float4 o;
    o.x = xv.x*(sigf(w1p[0]) + s2);
    o.y = xv.y*(sigf(w1p[1]) + s2);
    o.z = xv.z*(sigf(w1p[2]) + s2);
    o.w = xv.w*(sigf(w1p[3]) + s2);
    *(float4*)(out+i) = o;
}

// ---------------- launch ----------------
extern "C" void kernel_launch(void* const* d_in, const int* in_sizes, int n_in,
                              void* d_out, int out_size){
    const float* x   = (const float*)d_in[0];
    const float* w1  = (const float*)d_in[1];
    const float* b1  = (const float*)d_in[2];
    const float* w3a = (const float*)d_in[3];
    const float* b3a = (const float*)d_in[4];
    const float* w3b = (const float*)d_in[5];
    const float* b3b = (const float*)d_in[6];
    const float* gnw = (const float*)d_in[7];
    const float* gnb = (const float*)d_in[8];
    float* out = (float*)d_out;

    static cudaStream_t sB = nullptr;
    static cudaEvent_t evF=nullptr, evW=nullptr, evT=nullptr, evB=nullptr;
    if (!sB){
        cudaStreamCreateWithFlags(&sB, cudaStreamNonBlocking);
        cudaEventCreateWithFlags(&evF, cudaEventDisableTiming);
        cudaEventCreateWithFlags(&evW, cudaEventDisableTiming);
        cudaEventCreateWithFlags(&evT, cudaEventDisableTiming);
        cudaEventCreateWithFlags(&evB, cudaEventDisableTiming);
        cudaFuncSetAttribute(k_conv2, cudaFuncAttributeMaxDynamicSharedMemorySize, C2_DYN);
    }

    // default: prologue
    k_zero  <<<288, 256>>>();
    cudaEventRecord(evF, 0);
    k_wprep <<<2304, 256>>>(w3b, w3a);
    cudaEventRecord(evW, 0);

    // sB: xT transpose -> s4 logits -> s4 softmax
    cudaStreamWaitEvent(sB, evF, 0);
    k_tr    <<<dim3(196, B_), 256, 0, sB>>>(x);
    cudaEventRecord(evT, sB);
    cudaStreamWaitEvent(sB, evW, 0);
    k_s4logit<<<dim3(H_, B_), 256, 0, sB>>>();
    k_softmax<<<B_, 256, 0, sB>>>(1);
    cudaEventRecord(evB, sB);

    // default: gating / GN chain (NHWC consumers)
    k_x11   <<<1, 32>>>(gnb);
    k_rowcol<<<B_*C_, 256>>>(x);
    k_hw    <<<BG_, 128>>>(w1, b1);
    cudaStreamWaitEvent(0, evT, 0);
    k_stats <<<dim3(H_, B_), 256>>>();
    k_fin   <<<32, 256>>>();
    k_conv2 <<<dim3(H_/4, BG_), 256, C2_DYN>>>(b3a);
    k_x21   <<<BG_, 32>>>(gnw, gnb);
    cudaStreamWaitEvent(0, evB, 0);
    k_pass3 <<<dim3(H_, B_), 256>>>();
    k_softmax<<<B_, 256>>>(0);
    k_ycorr <<<dim3(H_, B_), 256>>>();
    k_t4mat <<<B_, 256>>>(b3b);
    k_wfin2 <<<32, 256>>>();
    k_out   <<<25088, 256>>>(x, out);
}

// round 14
// speedup vs baseline: 3.6885x; 1.1667x over previous
#include <cuda_runtime.h>
#include <cuda_fp16.h>
#include <math.h>

#define B_ 32
#define C_ 256
#define H_ 56
#define W_ 56
#define HW_ 3136
#define G_ 8
#define CG_ 32
#define BG_ 256
#define EPSV 1e-5f

// ---------------- static device scratch ----------------
__device__ __half d_xT [(size_t)B_*HW_*C_];   // fp16 x, NHWC
__device__ __half d_w4c[(size_t)2304*256];    // w3b -> [ic*9+r][o]
__device__ __half d_wr [9*256];               // wr[r][c] = sum_o w3b[o][c][r]
__device__ __half d_wa9[9*256];               // wa9[r][c] = sum_o x11[o]*w3a[o][c&31][r]
__device__ float d_cb;                        // sum_o x11[o]*b3a[o]
__device__ float d_xhm[BG_*CG_*H_], d_xwm[BG_*CG_*W_];
__device__ float d_shT[(size_t)B_*H_*C_];     // sigmoid(xh), [b][y][c]
__device__ float d_swT[(size_t)B_*W_*C_];     // sigmoid(xw), [b][j][c]
__device__ float d_chsum[BG_*CG_], d_chsq[BG_*CG_];
__device__ float d_mu[BG_*CG_], d_rstd[BG_*CG_];
__device__ float d_bm[C_], d_rbstd[C_];
__device__ float d_x11[CG_];
__device__ float d_T[(size_t)B_*C_*9];
__device__ float d_m2[BG_*CG_];
__device__ float d_A1[BG_*CG_], d_C1[BG_];
__device__ float d_w1[(size_t)BG_*HW_];
__device__ float d_s3[(size_t)B_*HW_], d_s4[(size_t)B_*HW_];
__device__ float d_y[(size_t)B_*C_*9];
__device__ float d_u[B_*C_];
__device__ float d_sw2[B_*C_];

__device__ __forceinline__ float sigf(float v){ return 1.f/(1.f+expf(-v)); }

// ---------------- small kernels ----------------
__global__ void k_zero(){
    int i = blockIdx.x*blockDim.x + threadIdx.x;
    if (i < BG_*CG_){ d_chsum[i] = 0.f; d_chsq[i] = 0.f; d_u[i] = 0.f; }
    if (i < B_*C_*9) d_y[i] = 0.f;
}

__global__ void k_wprep(const float* __restrict__ w3b){
    int j = blockIdx.x*blockDim.x + threadIdx.x;
    if (j < 256*2304){
        int o = j/2304, k = j - o*2304;
        d_w4c[(size_t)k*256 + o] = __float2half(w3b[j]);
    }
    if (j < 2304){
        float s = 0.f;
        for (int o=0;o<256;o++) s += w3b[o*2304 + j];
        int ic = j/9, r = j - ic*9;
        d_wr[r*256 + ic] = __float2half(s);
    }
}

__global__ void k_x11(const float* __restrict__ gnb){
    int t = threadIdx.x;
    float v = gnb[t], m = v;
    #pragma unroll
    for (int s=16;s;s>>=1) m = fmaxf(m, __shfl_xor_sync(~0u, m, s));
    float e = expf(v-m), sum = e;
    #pragma unroll
    for (int s=16;s;s>>=1) sum += __shfl_xor_sync(~0u, sum, s);
    d_x11[t] = e/sum;
}

// wa9[r][c] = sum_o x11[o]*w3a[o][c&31][r], replicated across 8 groups; cb scalar
__global__ void k_wa(const float* __restrict__ w3a, const float* __restrict__ b3a){
    int t = threadIdx.x;                // 288 threads
    int ic = t/9, r = t - ic*9;
    float s = 0.f;
    for (int o=0;o<32;o++) s += d_x11[o]*w3a[o*288 + ic*9 + r];
    __half h = __float2half(s);
    #pragma unroll
    for (int g=0;g<8;g++) d_wa9[r*256 + g*32 + ic] = h;
    if (t==0){
        float c = 0.f;
        for (int o=0;o<32;o++) c += d_x11[o]*b3a[o];
        d_cb = c;
    }
}

// row/col means per channel (fp32 x)
__global__ void __launch_bounds__(256) k_rowcol(const float* __restrict__ x){
    __shared__ float tile[HW_];
    int ch = blockIdx.x;
    const float* src = x + (size_t)ch*HW_;
    for (int i = threadIdx.x*4; i < HW_; i += 1024){
        float4 v = *(const float4*)(src+i);
        tile[i]=v.x; tile[i+1]=v.y; tile[i+2]=v.z; tile[i+3]=v.w;
    }
    __syncthreads();
    int t = threadIdx.x;
    if (t < H_){
        float rs = 0.f, cs = 0.f;
        #pragma unroll 8
        for (int w = 0; w < W_; w++) rs += tile[t*W_ + w];
        #pragma unroll 8
        for (int h = 0; h < H_; h++) cs += tile[h*W_ + t];
        d_xhm[ch*H_ + t] = rs * (1.0f/W_);
        d_xwm[ch*W_ + t] = cs * (1.0f/H_);
    }
}

// NCHW fp32 -> NHWC fp16 transpose
__global__ void __launch_bounds__(256) k_tr(const float* __restrict__ x){
    __shared__ __half sm[16*256];
    int b = blockIdx.y, p0 = blockIdx.x*16;
    int t = threadIdx.x;
    const float* src = x + (size_t)(b*C_ + t)*HW_ + p0;
    #pragma unroll
    for (int i=0;i<16;i+=4){
        float4 v = *(const float4*)(src+i);
        sm[(i+0)*256 + t] = __float2half(v.x);
        sm[(i+1)*256 + t] = __float2half(v.y);
        sm[(i+2)*256 + t] = __float2half(v.z);
        sm[(i+3)*256 + t] = __float2half(v.w);
    }
    __syncthreads();
    __half* dst = d_xT + ((size_t)b*HW_ + p0)*256;
    #pragma unroll
    for (int k=0;k<2;k++){
        int idx = t + k*256;
        int px = idx>>5, cc = (idx&31)*8;
        *(uint4*)&dst[(size_t)px*256 + cc] = *(uint4*)&sm[px*256+cc];
    }
}

// 1x1 conv on [xh;xw] + sigmoid; transposed gate layouts
__global__ void __launch_bounds__(128) k_hw(const float* __restrict__ w1, const float* __restrict__ b1){
    __shared__ float ws[1024], cat[32*112], bs[32];
    int bg = blockIdx.x;
    int b = bg>>3, g = bg&7;
    for (int i = threadIdx.x; i < 1024; i += 128) ws[i] = w1[i];
    if (threadIdx.x < 32) bs[threadIdx.x] = b1[threadIdx.x];
    for (int i = threadIdx.x; i < 32*112; i += 128){
        int c = i/112, p = i%112;
        cat[i] = (p < H_) ? d_xhm[(bg*CG_+c)*H_+p] : d_xwm[(bg*CG_+c)*W_+(p-H_)];
    }
    __syncthreads();
    for (int i = threadIdx.x; i < 32*112; i += 128){
        int o = i/112, p = i%112;
        float acc = bs[o];
        #pragma unroll 8
        for (int c = 0; c < 32; c++) acc += ws[o*32+c]*cat[c*112+p];
        float s = sigf(acc);
        if (p < H_) d_shT[((size_t)b*H_ + p)*C_ + g*CG_ + o] = s;
        else        d_swT[((size_t)b*W_ + (p-H_))*C_ + g*CG_ + o] = s;
    }
}

// per-channel sum/sumsq of x0, NHWC
__global__ void __launch_bounds__(256) k_stats(){
    int y = blockIdx.x, b = blockIdx.y;
    int c = threadIdx.x;
    float shv = d_shT[((size_t)b*H_ + y)*C_ + c];
    const __half* xp = d_xT + ((size_t)(b*HW_ + y*W_))*C_ + c;
    const float* swp = d_swT + (size_t)b*W_*C_ + c;
    float s = 0.f, q = 0.f;
    #pragma unroll 4
    for (int j=0;j<W_;j++){
        float v = __half2float(xp[(size_t)j*C_]) * shv * swp[(size_t)j*C_];
        s += v; q += v*v;
    }
    atomicAdd(&d_chsum[b*C_ + c], s);
    atomicAdd(&d_chsq [b*C_ + c], q);
}

__global__ void k_fin(){
    int i = blockIdx.x*blockDim.x + threadIdx.x;
    if (i < BG_*CG_){
        float mu = d_chsum[i]*(1.0f/HW_);
        float var = d_chsq[i]*(1.0f/HW_) - mu*mu;
        d_mu[i] = mu;
        d_rstd[i] = rsqrtf(var + EPSV);
    }
    if (i < C_){
        float s = 0.f, q = 0.f;
        for (int b = 0; b < B_; b++){ s += d_chsum[b*C_+i]; q += d_chsq[b*C_+i]; }
        const float n = (float)B_*(float)HW_;
        float bm = s/n, bv = q/n - bm*bm;
        d_bm[i] = bm;
        d_rbstd[i] = rsqrtf(bv + EPSV);
    }
}

// T[ch][r] = sum_p xpad[ch, p+delta_r]  (exact, from row/col means + corners)
__global__ void __launch_bounds__(256) k_T(const float* __restrict__ x){
    int b = blockIdx.x, c = threadIdx.x;
    int ch = b*C_ + c;
    float S = 0.f;
    for (int yy=0; yy<H_; yy++) S += d_xhm[ch*H_+yy];
    S *= W_;
    float r0  = d_xhm[ch*H_+0]*W_,     r55 = d_xhm[ch*H_+H_-1]*W_;
    float c0  = d_xwm[ch*W_+0]*H_,     c55 = d_xwm[ch*W_+W_-1]*H_;
    const float* xp = x + (size_t)ch*HW_;
    float x00 = xp[0], x0e = xp[W_-1], xe0 = xp[(H_-1)*W_], xee = xp[HW_-1];
    #pragma unroll
    for (int r=0;r<9;r++){
        int dy = r/3 - 1, dx = r - (r/3)*3 - 1;
        float T = S;
        if (dy==1)  T -= r0;
        if (dy==-1) T -= r55;
        if (dx==1)  T -= c0;
        if (dx==-1) T -= c55;
        if (dy==1 && dx==1)   T += x00;
        if (dy==1 && dx==-1)  T += x0e;
        if (dy==-1 && dx==1)  T += xe0;
        if (dy==-1 && dx==-1) T += xee;
        d_T[(size_t)ch*9 + r] = T;
    }
}

// m2[bg][o] = sum_{ic,r} w3a[o][ic][r]*T[bg,ic,r] + HW*b3a[o]
__global__ void __launch_bounds__(256) k_m2(const float* __restrict__ w3a, const float* __restrict__ b3a){
    __shared__ float Ts[288];
    int bg = blockIdx.x, b = bg>>3, g = bg&7;
    int t = threadIdx.x, lane = t&31, w = t>>5;
    for (int i=t;i<288;i+=256) Ts[i] = d_T[((size_t)(b*C_ + g*32))*9 + i];
    __syncthreads();
    for (int o=w;o<32;o+=8){
        float s = 0.f;
        for (int i=lane;i<288;i+=32) s += w3a[o*288 + i]*Ts[i];
        #pragma unroll
        for (int sh=16;sh;sh>>=1) s += __shfl_xor_sync(~0u,s,sh);
        if (lane==0) d_m2[bg*32 + o] = s + (float)HW_*b3a[o];
    }
}

__global__ void k_x21(const float* __restrict__ gnw, const float* __restrict__ gnb){
    int bg = blockIdx.x, t = threadIdx.x;
    float v = d_m2[bg*CG_+t]*(1.0f/HW_);
    float m = v;
    #pragma unroll
    for (int s=16;s;s>>=1) m = fmaxf(m, __shfl_xor_sync(~0u,m,s));
    float e = expf(v-m), sum = e;
    #pragma unroll
    for (int s=16;s;s>>=1) sum += __shfl_xor_sync(~0u,sum,s);
    float x21 = e/sum;
    float rs = d_rstd[bg*CG_+t], mu = d_mu[bg*CG_+t];
    d_A1[bg*CG_+t] = x21*gnw[t]*rs;
    float cc = x21*(gnb[t] - gnw[t]*rs*mu);
    #pragma unroll
    for (int s=16;s;s>>=1) cc += __shfl_xor_sync(~0u,cc,s);
    if (t==0) d_C1[bg] = cc;
}

// combined 9-tap correlations: s4 logits (wr) AND w1 term1 (wa9, per group) in one xT pass
__global__ void __launch_bounds__(256) k_corr(){
    __shared__ __half wrs[9*256], was[9*256];
    int y = blockIdx.x, b = blockIdx.y;
    int t = threadIdx.x, lane = t&31, w = t>>5;
    for (int i=t;i<288;i+=256){
        ((uint4*)wrs)[i] = ((const uint4*)d_wr)[i];
        ((uint4*)was)[i] = ((const uint4*)d_wa9)[i];
    }
    __syncthreads();
    float cb = d_cb;
    const __half* xTb = d_xT + (size_t)b*HW_*256;
    #pragma unroll
    for (int px=0; px<7; px++){
        int j = w*7 + px;
        float az = 0.f, aa = 0.f;
        #pragma unroll
        for (int r=0;r<9;r++){
            int yy = y + r/3 - 1, xx = j + r%3 - 1;
            if (yy>=0 && yy<H_ && xx>=0 && xx<W_){
                uint4 xv = *(const uint4*)(xTb + ((size_t)(yy*W_+xx))*256 + lane*8);
                uint4 wz = *(const uint4*)(wrs + r*256 + lane*8);
                uint4 wg = *(const uint4*)(was + r*256 + lane*8);
                __half2* xh = (__half2*)&xv;
                __half2* zh = (__half2*)&wz;
                __half2* gh = (__half2*)&wg;
                __half2 pz = __hmul2(xh[0], zh[0]);
                pz = __hfma2(xh[1], zh[1], pz);
                pz = __hfma2(xh[2], zh[2], pz);
                pz = __hfma2(xh[3], zh[3], pz);
                __half2 pg = __hmul2(xh[0], gh[0]);
                pg = __hfma2(xh[1], gh[1], pg);
                pg = __hfma2(xh[2], gh[2], pg);
                pg = __hfma2(xh[3], gh[3], pg);
                float2 fz = __half22float2(pz);
                float2 fg = __half22float2(pg);
                az += fz.x + fz.y;
                aa += fg.x + fg.y;
            }
        }
        // per-group sums: lane covers channels lane*8..lane*8+7 (group = lane>>2)
        aa += __shfl_xor_sync(~0u,aa,1);
        aa += __shfl_xor_sync(~0u,aa,2);
        #pragma unroll
        for (int s=16;s;s>>=1) az += __shfl_xor_sync(~0u,az,s);
        if ((lane&3)==0){
            int g = lane>>2;
            d_w1[((size_t)(b*G_+g))*HW_ + y*W_ + j] = aa + cb;
        }
        if (lane==0) d_s4[(size_t)b*HW_ + y*W_ + j] = az;
    }
}

// pass3 NHWC: w1 += term2, s3 logits, u = sum s4*x0
__global__ void __launch_bounds__(256) k_pass3(){
    __shared__ float wacc[8][56];
    int y = blockIdx.x, b = blockIdx.y;
    int c = threadIdx.x, lane = c&31, w = c>>5;
    int bg = b*G_ + w;
    float shv = d_shT[((size_t)b*H_ + y)*C_ + c];
    float A1v = d_A1[bg*CG_ + lane];
    float rbv = d_rbstd[c];
    float C1v = d_C1[bg];
    const __half* xp = d_xT + ((size_t)(b*HW_ + y*W_))*C_ + c;
    const float* swp = d_swT + (size_t)b*W_*C_ + c;
    const float* s4p = d_s4 + (size_t)b*HW_ + y*W_;
    float* w1p = d_w1 + (size_t)bg*HW_ + y*W_;
    float uacc = 0.f;
    for (int j=0;j<W_;j++){
        float x0 = __half2float(xp[(size_t)j*C_]) * shv * swp[(size_t)j*C_];
        uacc += s4p[j]*x0;
        float t2 = A1v*x0, sl = rbv*x0;
        #pragma unroll
        for (int s=16;s;s>>=1){
            t2 += __shfl_xor_sync(~0u,t2,s);
            sl += __shfl_xor_sync(~0u,sl,s);
        }
        if (lane==0){
            w1p[j] += t2 + C1v;
            wacc[w][j] = sl;
        }
    }
    atomicAdd(&d_u[b*C_ + c], uacc);
    __syncthreads();
    if (c < W_){
        float s = 0.f;
        #pragma unroll
        for (int g=0;g<8;g++) s += wacc[g][c];
        d_s3[(size_t)b*HW_ + y*W_ + c] = s*(1.0f/C_);
    }
}

__global__ void __launch_bounds__(256) k_softmax(int which){
    int row = blockIdx.x;
    float scale = which ? (1.0f/C_) : 1.0f;
    float* p = (which ? d_s4 : d_s3) + (size_t)row*HW_;
    __shared__ float red[8];
    int t = threadIdx.x, lane = t&31, wid = t>>5;
    float mx = -1e30f;
    for (int i=t;i<HW_;i+=256) mx = fmaxf(mx, p[i]*scale);
    #pragma unroll
    for (int s=16;s;s>>=1) mx = fmaxf(mx, __shfl_xor_sync(~0u,mx,s));
    if (lane==0) red[wid]=mx;
    __syncthreads();
    mx = red[0];
    #pragma unroll
    for (int i=1;i<8;i++) mx = fmaxf(mx, red[i]);
    __syncthreads();
    float sum = 0.f;
    for (int i=t;i<HW_;i+=256){ float e = expf(p[i]*scale-mx); p[i]=e; sum += e; }
    #pragma unroll
    for (int s=16;s;s>>=1) sum += __shfl_xor_sync(~0u,sum,s);
    if (lane==0) red[wid]=sum;
    __syncthreads();
    sum = 0.f;
    #pragma unroll
    for (int i=0;i<8;i++) sum += red[i];
    float inv = 1.0f/sum;
    for (int i=t;i<HW_;i+=256) p[i] *= inv;
}

// ycorr NHWC: y[b,c,r] += xT[q][c] * s3[q - delta_r]
__global__ void __launch_bounds__(256) k_ycorr(){
    __shared__ float s3r[3][58];
    int y = blockIdx.x, b = blockIdx.y;
    int c = threadIdx.x;
    if (c < 174){
        int rr = c/58, jj = c%58;
        int yy = y - 1 + rr, xx = jj - 1;
        s3r[rr][jj] = (yy>=0 && yy<H_ && xx>=0 && xx<W_) ? d_s3[(size_t)b*HW_ + yy*W_ + xx] : 0.f;
    }
    __syncthreads();
    const __half* xp = d_xT + ((size_t)(b*HW_ + y*W_))*C_ + c;
    float a[9] = {0,0,0,0,0,0,0,0,0};
    for (int j=0;j<W_;j++){
        float v = __half2float(xp[(size_t)j*C_]);
        #pragma unroll
        for (int r=0;r<9;r++){
            int dy = r/3 - 1, dx = r - (r/3)*3 - 1;
            a[r] += v * s3r[1-dy][j - dx + 1];
        }
    }
    float* yp = d_y + (size_t)b*2304 + c*9;
    #pragma unroll
    for (int r=0;r<9;r++) atomicAdd(&yp[r], a[r]);
}

// t4 + wfin fused: sw2 = sigmoid(t4 + rbstd*(u - bm))
__global__ void __launch_bounds__(256) k_t4fin(const float* __restrict__ b3b){
    __shared__ float ys[2304];
    int b = blockIdx.x, t = threadIdx.x;
    for (int i=t;i<2304;i+=256) ys[i] = d_y[(size_t)b*2304 + i];
    __syncthreads();
    float acc = b3b[t];
    #pragma unroll 8
    for (int k=0;k<2304;k++)
        acc += __half2float(d_w4c[(size_t)k*256 + t]) * ys[k];
    d_sw2[b*C_ + t] = sigf(acc + d_rbstd[t]*(d_u[b*C_ + t] - d_bm[t]));
}

__global__ void __launch_bounds__(256) k_out(const float* __restrict__ x, float* __restrict__ out){
    size_t i = ((size_t)blockIdx.x*256 + threadIdx.x)*4;
    int p = (int)(i % HW_);
    int ch = (int)(i / HW_);
    int b = ch >> 8, c = ch & 255;
    int bg = b*G_ + (c>>5);
    float4 xv = *(const float4*)(x+i);
    float4 wv = *(const float4*)(d_w1 + (size_t)bg*HW_ + p);
    float s2 = d_sw2[ch];
    float4 o;
    o.x = xv.x*(sigf(wv.x) + s2);
    o.y = xv.y*(sigf(wv.y) + s2);
    o.z = xv.z*(sigf(wv.z) + s2);
    o.w = xv.w*(sigf(wv.w) + s2);
    *(float4*)(out+i) = o;
}

// ---------------- launch ----------------
extern "C" void kernel_launch(void* const* d_in, const int* in_sizes, int n_in,
                              void* d_out, int out_size){
    const float* x   = (const float*)d_in[0];
    const float* w1  = (const float*)d_in[1];
    const float* b1  = (const float*)d_in[2];
    const float* w3a = (const float*)d_in[3];
    const float* b3a = (const float*)d_in[4];
    const float* w3b = (const float*)d_in[5];
    const float* b3b = (const float*)d_in[6];
    const float* gnw = (const float*)d_in[7];
    const float* gnb = (const float*)d_in[8];
    float* out = (float*)d_out;

    static cudaStream_t sB = nullptr;
    static cudaEvent_t evR=nullptr, evW=nullptr, evT=nullptr, evB=nullptr;
    if (!sB){
        cudaStreamCreateWithFlags(&sB, cudaStreamNonBlocking);
        cudaEventCreateWithFlags(&evR, cudaEventDisableTiming);
        cudaEventCreateWithFlags(&evW, cudaEventDisableTiming);
        cudaEventCreateWithFlags(&evT, cudaEventDisableTiming);
        cudaEventCreateWithFlags(&evB, cudaEventDisableTiming);
    }

    // default: root the capture, then prologue (weight prep)
    k_zero  <<<288, 256>>>();
    cudaEventRecord(evR, 0);               // root event for sB fork

    // sB: xT transpose (waits on root — required for valid stream capture)
    cudaStreamWaitEvent(sB, evR, 0);
    k_tr    <<<dim3(196, B_), 256, 0, sB>>>(x);
    cudaEventRecord(evT, sB);

    // default: weight prep
    k_x11   <<<1, 32>>>(gnb);
    k_wa    <<<1, 288>>>(w3a, b3a);
    k_wprep <<<2304, 256>>>(w3b);
    cudaEventRecord(evW, 0);

    // sB: combined correlations (s4 logits + w1 term1) -> s4 softmax
    cudaStreamWaitEvent(sB, evW, 0);
    k_corr  <<<dim3(H_, B_), 256, 0, sB>>>();
    k_softmax<<<B_, 256, 0, sB>>>(1);
    cudaEventRecord(evB, sB);

    // default: gating / GN chain
    k_rowcol<<<B_*C_, 256>>>(x);
    k_hw    <<<BG_, 128>>>(w1, b1);
    cudaStreamWaitEvent(0, evT, 0);
    k_stats <<<dim3(H_, B_), 256>>>();
    k_fin   <<<32, 256>>>();
    k_T     <<<B_, 256>>>(x);
    k_m2    <<<BG_, 256>>>(w3a, b3a);
    k_x21   <<<BG_, 32>>>(gnw, gnb);
    cudaStreamWaitEvent(0, evB, 0);
    k_pass3 <<<dim3(H_, B_), 256>>>();
    k_softmax<<<B_, 256>>>(0);
    k_ycorr <<<dim3(H_, B_), 256>>>();
    k_t4fin <<<B_, 256>>>(b3b);
    k_out   <<<25088, 256>>>(x, out);
}

// round 15
// speedup vs baseline: 3.7607x; 1.0196x over previous
#include <cuda_runtime.h>
#include <cuda_fp16.h>
#include <math.h>

#define B_ 32
#define C_ 256
#define H_ 56
#define W_ 56
#define HW_ 3136
#define G_ 8
#define CG_ 32
#define BG_ 256
#define EPSV 1e-5f

// ---------------- static device scratch ----------------
__device__ __half d_xT [(size_t)B_*HW_*C_];   // fp16 x, NHWC
__device__ __half d_w4c[(size_t)2304*256];    // w3b -> [ic*9+r][o]
__device__ __half d_wr [9*256];               // wr[r][c] = sum_o w3b[o][c][r]
__device__ __half d_wa9[9*256];               // wa9[r][c] = sum_o x11[o]*w3a[o][c&31][r]
__device__ float d_cb;
__device__ float d_xhm[BG_*CG_*H_], d_xwm[BG_*CG_*W_];
__device__ float d_shT[(size_t)B_*H_*C_];     // sigmoid(xh), [b][y][c]
__device__ float d_swT[(size_t)B_*W_*C_];     // sigmoid(xw), [b][j][c]
__device__ float d_chsum[BG_*CG_], d_chsq[BG_*CG_];
__device__ float d_mu[BG_*CG_], d_rstd[BG_*CG_];
__device__ float d_bm[C_], d_rbstd[C_];
__device__ float d_x11[CG_];
__device__ float d_A1[BG_*CG_], d_C1[BG_];
__device__ float d_w1[(size_t)BG_*HW_];
__device__ float d_s3[(size_t)B_*HW_], d_s4[(size_t)B_*HW_];
__device__ float d_y[(size_t)B_*C_*9];
__device__ float d_u[B_*C_];
__device__ float d_sw2[B_*C_];

__device__ __forceinline__ float sigf(float v){ return 1.f/(1.f+expf(-v)); }

// ---------------- small kernels ----------------
__global__ void k_zero(){
    int i = blockIdx.x*blockDim.x + threadIdx.x;
    if (i < BG_*CG_){ d_chsum[i] = 0.f; d_chsq[i] = 0.f; d_u[i] = 0.f; }
    if (i < B_*C_*9) d_y[i] = 0.f;
}

// w3b -> w4c [k][o] fp16 (coalesced writes along o after the o-major read)
__global__ void k_wprep(const float* __restrict__ w3b){
    int j = blockIdx.x*blockDim.x + threadIdx.x;
    if (j < 256*2304){
        int o = j/2304, k = j - o*2304;
        d_w4c[(size_t)k*256 + o] = __float2half(w3b[j]);
    }
}

// wr[r][ic] = sum_o w4c[ic*9+r][o]  (coalesced row-sum, warp per row)
__global__ void __launch_bounds__(256) k_wr(){
    int k = blockIdx.x*8 + (threadIdx.x>>5);      // 288 blocks x 8 warps = 2304 rows
    int lane = threadIdx.x&31;
    uint4 v = *(const uint4*)(d_w4c + (size_t)k*256 + lane*8);
    __half2* h = (__half2*)&v;
    float s = 0.f;
    #pragma unroll
    for (int i=0;i<4;i++){ float2 f = __half22float2(h[i]); s += f.x + f.y; }
    #pragma unroll
    for (int sh=16;sh;sh>>=1) s += __shfl_xor_sync(~0u,s,sh);
    if (lane==0){
        int ic = k/9, r = k - ic*9;
        d_wr[r*256 + ic] = __float2half(s);
    }
}

__global__ void k_x11(const float* __restrict__ gnb){
    int t = threadIdx.x;
    float v = gnb[t], m = v;
    #pragma unroll
    for (int s=16;s;s>>=1) m = fmaxf(m, __shfl_xor_sync(~0u, m, s));
    float e = expf(v-m), sum = e;
    #pragma unroll
    for (int s=16;s;s>>=1) sum += __shfl_xor_sync(~0u, sum, s);
    d_x11[t] = e/sum;
}

// wa9[r][c] = sum_o x11[o]*w3a[o][c&31][r]; cb scalar
__global__ void k_wa(const float* __restrict__ w3a, const float* __restrict__ b3a){
    int t = threadIdx.x;                // 288 threads
    int ic = t/9, r = t - ic*9;
    float s = 0.f;
    for (int o=0;o<32;o++) s += d_x11[o]*w3a[o*288 + ic*9 + r];
    __half h = __float2half(s);
    #pragma unroll
    for (int g=0;g<8;g++) d_wa9[r*256 + g*32 + ic] = h;
    if (t==0){
        float c = 0.f;
        for (int o=0;o<32;o++) c += d_x11[o]*b3a[o];
        d_cb = c;
    }
}

// row/col means per channel (fp32 x)
__global__ void __launch_bounds__(256) k_rowcol(const float* __restrict__ x){
    __shared__ float tile[HW_];
    int ch = blockIdx.x;
    const float* src = x + (size_t)ch*HW_;
    for (int i = threadIdx.x*4; i < HW_; i += 1024){
        float4 v = *(const float4*)(src+i);
        tile[i]=v.x; tile[i+1]=v.y; tile[i+2]=v.z; tile[i+3]=v.w;
    }
    __syncthreads();
    int t = threadIdx.x;
    if (t < H_){
        float rs = 0.f, cs = 0.f;
        #pragma unroll 8
        for (int w = 0; w < W_; w++) rs += tile[t*W_ + w];
        #pragma unroll 8
        for (int h = 0; h < H_; h++) cs += tile[h*W_ + t];
        d_xhm[ch*H_ + t] = rs * (1.0f/W_);
        d_xwm[ch*W_ + t] = cs * (1.0f/H_);
    }
}

// NCHW fp32 -> NHWC fp16 transpose, coalesced both sides (64px x 256ch tiles)
__global__ void __launch_bounds__(256) k_tr(const float* __restrict__ x){
    __shared__ __half sm[256][66];
    int b = blockIdx.y, p0 = blockIdx.x*64;
    int t = threadIdx.x, lane = t&31, w = t>>5;
    #pragma unroll 4
    for (int it=0; it<32; it++){
        int c = it*8 + w;
        float2 v = *(const float2*)(x + (size_t)(b*C_+c)*HW_ + p0 + lane*2);
        sm[c][lane*2]   = __float2half(v.x);
        sm[c][lane*2+1] = __float2half(v.y);
    }
    __syncthreads();
    __half* dst = d_xT + ((size_t)(b*HW_ + p0))*C_;
    #pragma unroll 4
    for (int i=t; i<8192; i+=256){
        int px = i>>7, c2 = (i&127)*2;
        *(__half2*)(dst + (size_t)px*C_ + c2) = __halves2half2(sm[c2][px], sm[c2+1][px]);
    }
}

// 1x1 conv on [xh;xw] + sigmoid; transposed gate layouts
__global__ void __launch_bounds__(128) k_hw(const float* __restrict__ w1, const float* __restrict__ b1){
    __shared__ float ws[1024], cat[32*112], bs[32];
    int bg = blockIdx.x;
    int b = bg>>3, g = bg&7;
    for (int i = threadIdx.x; i < 1024; i += 128) ws[i] = w1[i];
    if (threadIdx.x < 32) bs[threadIdx.x] = b1[threadIdx.x];
    for (int i = threadIdx.x; i < 32*112; i += 128){
        int c = i/112, p = i%112;
        cat[i] = (p < H_) ? d_xhm[(bg*CG_+c)*H_+p] : d_xwm[(bg*CG_+c)*W_+(p-H_)];
    }
    __syncthreads();
    for (int i = threadIdx.x; i < 32*112; i += 128){
        int o = i/112, p = i%112;
        float acc = bs[o];
        #pragma unroll 8
        for (int c = 0; c < 32; c++) acc += ws[o*32+c]*cat[c*112+p];
        float s = sigf(acc);
        if (p < H_) d_shT[((size_t)b*H_ + p)*C_ + g*CG_ + o] = s;
        else        d_swT[((size_t)b*W_ + (p-H_))*C_ + g*CG_ + o] = s;
    }
}

// per-channel sum/sumsq of x0, NHWC
__global__ void __launch_bounds__(256) k_stats(){
    int y = blockIdx.x, b = blockIdx.y;
    int c = threadIdx.x;
    float shv = d_shT[((size_t)b*H_ + y)*C_ + c];
    const __half* xp = d_xT + ((size_t)(b*HW_ + y*W_))*C_ + c;
    const float* swp = d_swT + (size_t)b*W_*C_ + c;
    float s = 0.f, q = 0.f;
    #pragma unroll 4
    for (int j=0;j<W_;j++){
        float v = __half2float(xp[(size_t)j*C_]) * shv * swp[(size_t)j*C_];
        s += v; q += v*v;
    }
    atomicAdd(&d_chsum[b*C_ + c], s);
    atomicAdd(&d_chsq [b*C_ + c], q);
}

__global__ void k_fin(){
    int i = blockIdx.x*blockDim.x + threadIdx.x;
    if (i < BG_*CG_){
        float mu = d_chsum[i]*(1.0f/HW_);
        float var = d_chsq[i]*(1.0f/HW_) - mu*mu;
        d_mu[i] = mu;
        d_rstd[i] = rsqrtf(var + EPSV);
    }
    if (i < C_){
        float s = 0.f, q = 0.f;
        for (int b = 0; b < B_; b++){ s += d_chsum[b*C_+i]; q += d_chsq[b*C_+i]; }
        const float n = (float)B_*(float)HW_;
        float bm = s/n, bv = q/n - bm*bm;
        d_bm[i] = bm;
        d_rbstd[i] = rsqrtf(bv + EPSV);
    }
}

// merged: T (window sums) -> m2 -> x21 softmax -> A1/C1, one block per bg
__global__ void __launch_bounds__(256) k_gn2(const float* __restrict__ w3a, const float* __restrict__ b3a,
                                            const float* __restrict__ gnw, const float* __restrict__ gnb,
                                            const float* __restrict__ x){
    __shared__ float Ts[288], m2s[32];
    int bg = blockIdx.x, b = bg>>3, g = bg&7;
    int t = threadIdx.x, lane = t&31, w = t>>5;
    for (int i=t;i<288;i+=256){
        int ic = i/9, r = i - ic*9;
        int ch = b*C_ + g*32 + ic;
        float S = 0.f;
        for (int yy=0; yy<H_; yy++) S += d_xhm[ch*H_+yy];
        S *= W_;
        int dy = r/3 - 1, dx = r - (r/3)*3 - 1;
        float T = S;
        if (dy==1)  T -= d_xhm[ch*H_+0]*W_;
        if (dy==-1) T -= d_xhm[ch*H_+H_-1]*W_;
        if (dx==1)  T -= d_xwm[ch*W_+0]*H_;
        if (dx==-1) T -= d_xwm[ch*W_+W_-1]*H_;
        const float* xp = x + (size_t)ch*HW_;
        if (dy==1 && dx==1)   T += xp[0];
        if (dy==1 && dx==-1)  T += xp[W_-1];
        if (dy==-1 && dx==1)  T += xp[(H_-1)*W_];
        if (dy==-1 && dx==-1) T += xp[HW_-1];
        Ts[i] = T;
    }
    __syncthreads();
    for (int o=w;o<32;o+=8){
        float s = 0.f;
        for (int i=lane;i<288;i+=32) s += w3a[o*288 + i]*Ts[i];
        #pragma unroll
        for (int sh=16;sh;sh>>=1) s += __shfl_xor_sync(~0u,s,sh);
        if (lane==0) m2s[o] = s + (float)HW_*b3a[o];
    }
    __syncthreads();
    if (w==0){
        float v = m2s[lane]*(1.0f/HW_);
        float m = v;
        #pragma unroll
        for (int s=16;s;s>>=1) m = fmaxf(m, __shfl_xor_sync(~0u,m,s));
        float e = expf(v-m), sum = e;
        #pragma unroll
        for (int s=16;s;s>>=1) sum += __shfl_xor_sync(~0u,sum,s);
        float x21 = e/sum;
        float rs = d_rstd[bg*CG_+lane], mu = d_mu[bg*CG_+lane];
        d_A1[bg*CG_+lane] = x21*gnw[lane]*rs;
        float cc = x21*(gnb[lane] - gnw[lane]*rs*mu);
        #pragma unroll
        for (int s=16;s;s>>=1) cc += __shfl_xor_sync(~0u,cc,s);
        if (lane==0) d_C1[bg] = cc;
    }
}

// combined 9-tap correlations: s4 logits (wr) AND w1 term1 (wa9) in one xT pass
__global__ void __launch_bounds__(256) k_corr(){
    __shared__ __half wrs[9*256], was[9*256];
    int y = blockIdx.x, b = blockIdx.y;
    int t = threadIdx.x, lane = t&31, w = t>>5;
    for (int i=t;i<288;i+=256){
        ((uint4*)wrs)[i] = ((const uint4*)d_wr)[i];
        ((uint4*)was)[i] = ((const uint4*)d_wa9)[i];
    }
    __syncthreads();
    float cb = d_cb;
    const __half* xTb = d_xT + (size_t)b*HW_*256;
    #pragma unroll
    for (int px=0; px<7; px++){
        int j = w*7 + px;
        float az = 0.f, aa = 0.f;
        #pragma unroll
        for (int r=0;r<9;r++){
            int yy = y + r/3 - 1, xx = j + r%3 - 1;
            if (yy>=0 && yy<H_ && xx>=0 && xx<W_){
                uint4 xv = *(const uint4*)(xTb + ((size_t)(yy*W_+xx))*256 + lane*8);
                uint4 wz = *(const uint4*)(wrs + r*256 + lane*8);
                uint4 wg = *(const uint4*)(was + r*256 + lane*8);
                __half2* xh = (__half2*)&xv;
                __half2* zh = (__half2*)&wz;
                __half2* gh = (__half2*)&wg;
                __half2 pz = __hmul2(xh[0], zh[0]);
                pz = __hfma2(xh[1], zh[1], pz);
                pz = __hfma2(xh[2], zh[2], pz);
                pz = __hfma2(xh[3], zh[3], pz);
                __half2 pg = __hmul2(xh[0], gh[0]);
                pg = __hfma2(xh[1], gh[1], pg);
                pg = __hfma2(xh[2], gh[2], pg);
                pg = __hfma2(xh[3], gh[3], pg);
                float2 fz = __half22float2(pz);
                float2 fg = __half22float2(pg);
                az += fz.x + fz.y;
                aa += fg.x + fg.y;
            }
        }
        aa += __shfl_xor_sync(~0u,aa,1);
        aa += __shfl_xor_sync(~0u,aa,2);
        #pragma unroll
        for (int s=16;s;s>>=1) az += __shfl_xor_sync(~0u,az,s);
        if ((lane&3)==0){
            int g = lane>>2;
            d_w1[((size_t)(b*G_+g))*HW_ + y*W_ + j] = aa + cb;
        }
        if (lane==0) d_s4[(size_t)b*HW_ + y*W_ + j] = az;
    }
}

// pass3 NHWC: w1 += term2, s3 logits, u = sum s4*x0
__global__ void __launch_bounds__(256) k_pass3(){
    __shared__ float wacc[8][56];
    int y = blockIdx.x, b = blockIdx.y;
    int c = threadIdx.x, lane = c&31, w = c>>5;
    int bg = b*G_ + w;
    float shv = d_shT[((size_t)b*H_ + y)*C_ + c];
    float A1v = d_A1[bg*CG_ + lane];
    float rbv = d_rbstd[c];
    float C1v = d_C1[bg];
    const __half* xp = d_xT + ((size_t)(b*HW_ + y*W_))*C_ + c;
    const float* swp = d_swT + (size_t)b*W_*C_ + c;
    const float* s4p = d_s4 + (size_t)b*HW_ + y*W_;
    float* w1p = d_w1 + (size_t)bg*HW_ + y*W_;
    float uacc = 0.f;
    for (int j=0;j<W_;j++){
        float x0 = __half2float(xp[(size_t)j*C_]) * shv * swp[(size_t)j*C_];
        uacc += s4p[j]*x0;
        float t2 = A1v*x0, sl = rbv*x0;
        #pragma unroll
        for (int s=16;s;s>>=1){
            t2 += __shfl_xor_sync(~0u,t2,s);
            sl += __shfl_xor_sync(~0u,sl,s);
        }
        if (lane==0){
            w1p[j] += t2 + C1v;
            wacc[w][j] = sl;
        }
    }
    atomicAdd(&d_u[b*C_ + c], uacc);
    __syncthreads();
    if (c < W_){
        float s = 0.f;
        #pragma unroll
        for (int g=0;g<8;g++) s += wacc[g][c];
        d_s3[(size_t)b*HW_ + y*W_ + c] = s*(1.0f/C_);
    }
}

__global__ void __launch_bounds__(256) k_softmax(int which){
    int row = blockIdx.x;
    float scale = which ? (1.0f/C_) : 1.0f;
    float* p = (which ? d_s4 : d_s3) + (size_t)row*HW_;
    __shared__ float red[8];
    int t = threadIdx.x, lane = t&31, wid = t>>5;
    float mx = -1e30f;
    for (int i=t;i<HW_;i+=256) mx = fmaxf(mx, p[i]*scale);
    #pragma unroll
    for (int s=16;s;s>>=1) mx = fmaxf(mx, __shfl_xor_sync(~0u,mx,s));
    if (lane==0) red[wid]=mx;
    __syncthreads();
    mx = red[0];
    #pragma unroll
    for (int i=1;i<8;i++) mx = fmaxf(mx, red[i]);
    __syncthreads();
    float sum = 0.f;
    for (int i=t;i<HW_;i+=256){ float e = expf(p[i]*scale-mx); p[i]=e; sum += e; }
    #pragma unroll
    for (int s=16;s;s>>=1) sum += __shfl_xor_sync(~0u,sum,s);
    if (lane==0) red[wid]=sum;
    __syncthreads();
    sum = 0.f;
    #pragma unroll
    for (int i=0;i<8;i++) sum += red[i];
    float inv = 1.0f/sum;
    for (int i=t;i<HW_;i+=256) p[i] *= inv;
}

// ycorr NHWC: y[b,c,r] += xT[q][c] * s3[q - delta_r]
__global__ void __launch_bounds__(256) k_ycorr(){
    __shared__ float s3r[3][58];
    int y = blockIdx.x, b = blockIdx.y;
    int c = threadIdx.x;
    if (c < 174){
        int rr = c/58, jj = c%58;
        int yy = y - 1 + rr, xx = jj - 1;
        s3r[rr][jj] = (yy>=0 && yy<H_ && xx>=0 && xx<W_) ? d_s3[(size_t)b*HW_ + yy*W_ + xx] : 0.f;
    }
    __syncthreads();
    const __half* xp = d_xT + ((size_t)(b*HW_ + y*W_))*C_ + c;
    float a[9] = {0,0,0,0,0,0,0,0,0};
    for (int j=0;j<W_;j++){
        float v = __half2float(xp[(size_t)j*C_]);
        #pragma unroll
        for (int r=0;r<9;r++){
            int dy = r/3 - 1, dx = r - (r/3)*3 - 1;
            a[r] += v * s3r[1-dy][j - dx + 1];
        }
    }
    float* yp = d_y + (size_t)b*2304 + c*9;
    #pragma unroll
    for (int r=0;r<9;r++) atomicAdd(&yp[r], a[r]);
}

// t4 + wfin fused
__global__ void __launch_bounds__(256) k_t4fin(const float* __restrict__ b3b){
    __shared__ float ys[2304];
    int b = blockIdx.x, t = threadIdx.x;
    for (int i=t;i<2304;i+=256) ys[i] = d_y[(size_t)b*2304 + i];
    __syncthreads();
    float acc = b3b[t];
    #pragma unroll 8
    for (int k=0;k<2304;k++)
        acc += __half2float(d_w4c[(size_t)k*256 + t]) * ys[k];
    d_sw2[b*C_ + t] = sigf(acc + d_rbstd[t]*(d_u[b*C_ + t] - d_bm[t]));
}

__global__ void __launch_bounds__(256) k_out(const float* __restrict__ x, float* __restrict__ out){
    size_t i = ((size_t)blockIdx.x*256 + threadIdx.x)*4;
    int p = (int)(i % HW_);
    int ch = (int)(i / HW_);
    int b = ch >> 8, c = ch & 255;
    int bg = b*G_ + (c>>5);
    float4 xv = *(const float4*)(x+i);
    float4 wv = *(const float4*)(d_w1 + (size_t)bg*HW_ + p);
    float s2 = d_sw2[ch];
    float4 o;
    o.x = xv.x*(sigf(wv.x) + s2);
    o.y = xv.y*(sigf(wv.y) + s2);
    o.z = xv.z*(sigf(wv.z) + s2);
    o.w = xv.w*(sigf(wv.w) + s2);
    *(float4*)(out+i) = o;
}

// ---------------- launch ----------------
extern "C" void kernel_launch(void* const* d_in, const int* in_sizes, int n_in,
                              void* d_out, int out_size){
    const float* x   = (const float*)d_in[0];
    const float* w1  = (const float*)d_in[1];
    const float* b1  = (const float*)d_in[2];
    const float* w3a = (const float*)d_in[3];
    const float* b3a = (const float*)d_in[4];
    const float* w3b = (const float*)d_in[5];
    const float* b3b = (const float*)d_in[6];
    const float* gnw = (const float*)d_in[7];
    const float* gnb = (const float*)d_in[8];
    float* out = (float*)d_out;

    static cudaStream_t sB = nullptr;
    static cudaEvent_t evR=nullptr, evW=nullptr, evT=nullptr, evB=nullptr;
    if (!sB){
        cudaStreamCreateWithFlags(&sB, cudaStreamNonBlocking);
        cudaEventCreateWithFlags(&evR, cudaEventDisableTiming);
        cudaEventCreateWithFlags(&evW, cudaEventDisableTiming);
        cudaEventCreateWithFlags(&evT, cudaEventDisableTiming);
        cudaEventCreateWithFlags(&evB, cudaEventDisableTiming);
    }

    // default: root the capture
    k_zero  <<<288, 256>>>();
    cudaEventRecord(evR, 0);

    // sB: xT transpose (rooted fork)
    cudaStreamWaitEvent(sB, evR, 0);
    k_tr    <<<dim3(49, B_), 256, 0, sB>>>(x);
    cudaEventRecord(evT, sB);

    // default: weight prep
    k_x11   <<<1, 32>>>(gnb);
    k_wa    <<<1, 288>>>(w3a, b3a);
    k_wprep <<<2304, 256>>>(w3b);
    k_wr    <<<288, 256>>>();
    cudaEventRecord(evW, 0);

    // sB: combined correlations -> s4 softmax
    cudaStreamWaitEvent(sB, evW, 0);
    k_corr  <<<dim3(H_, B_), 256, 0, sB>>>();
    k_softmax<<<B_, 256, 0, sB>>>(1);
    cudaEventRecord(evB, sB);

    // default: gating / GN chain
    k_rowcol<<<B_*C_, 256>>>(x);
    k_hw    <<<BG_, 128>>>(w1, b1);
    cudaStreamWaitEvent(0, evT, 0);
    k_stats <<<dim3(H_, B_), 256>>>();
    k_fin   <<<32, 256>>>();
    k_gn2   <<<BG_, 256>>>(w3a, b3a, gnw, gnb, x);
    cudaStreamWaitEvent(0, evB, 0);
    k_pass3 <<<dim3(H_, B_), 256>>>();
    k_softmax<<<B_, 256>>>(0);
    k_ycorr <<<dim3(H_, B_), 256>>>();
    k_t4fin <<<B_, 256>>>(b3b);
    k_out   <<<25088, 256>>>(x, out);
}

// round 16
// speedup vs baseline: 4.0821x; 1.0855x over previous
#include <cuda_runtime.h>
#include <cuda_fp16.h>
#include <math.h>

#define B_ 32
#define C_ 256
#define H_ 56
#define W_ 56
#define HW_ 3136
#define G_ 8
#define CG_ 32
#define BG_ 256
#define EPSV 1e-5f

// ---------------- static device scratch ----------------
__device__ __half d_xT [(size_t)B_*HW_*C_];   // fp16 x, NHWC
__device__ __half d_w4c[(size_t)2304*256];    // w3b -> [ic*9+r][o]
__device__ __half d_wr [9*256];               // wr[r][c] = sum_o w3b[o][c][r]
__device__ __half d_wa9[9*256];               // wa9[r][c] = sum_o x11[o]*w3a[o][c&31][r]
__device__ float d_cb;
__device__ float d_xhm[BG_*CG_*H_], d_xwm[BG_*CG_*W_];
__device__ float d_shT[(size_t)B_*H_*C_];     // sigmoid(xh), [b][y][c]
__device__ float d_swT[(size_t)B_*W_*C_];     // sigmoid(xw), [b][j][c]
__device__ float d_chsum[BG_*CG_], d_chsq[BG_*CG_];
__device__ float d_mu[BG_*CG_], d_rstd[BG_*CG_];
__device__ float d_bm[C_], d_rbstd[C_];
__device__ float d_A1[BG_*CG_], d_C1[BG_];
__device__ float d_w1[(size_t)BG_*HW_];
__device__ float d_s3[(size_t)B_*HW_], d_s4[(size_t)B_*HW_];
__device__ float d_y[(size_t)B_*C_*9];
__device__ float d_u[B_*C_];
__device__ float d_sw2[B_*C_];

__device__ __forceinline__ float sigf(float v){ return 1.f/(1.f+expf(-v)); }

// ---------------- small kernels ----------------
__global__ void k_zero(){
    int i = blockIdx.x*blockDim.x + threadIdx.x;
    if (i < BG_*CG_){ d_chsum[i] = 0.f; d_chsq[i] = 0.f; d_u[i] = 0.f; }
    if (i < B_*C_*9) d_y[i] = 0.f;
}

// w3b -> w4c [k][o] fp16
__global__ void k_wprep(const float* __restrict__ w3b){
    int j = blockIdx.x*blockDim.x + threadIdx.x;
    if (j < 256*2304){
        int o = j/2304, k = j - o*2304;
        d_w4c[(size_t)k*256 + o] = __float2half(w3b[j]);
    }
}

// wr[r][ic] = sum_o w4c[ic*9+r][o]  (coalesced row-sum, warp per row)
__global__ void __launch_bounds__(256) k_wr(){
    int k = blockIdx.x*8 + (threadIdx.x>>5);
    int lane = threadIdx.x&31;
    uint4 v = *(const uint4*)(d_w4c + (size_t)k*256 + lane*8);
    __half2* h = (__half2*)&v;
    float s = 0.f;
    #pragma unroll
    for (int i=0;i<4;i++){ float2 f = __half22float2(h[i]); s += f.x + f.y; }
    #pragma unroll
    for (int sh=16;sh;sh>>=1) s += __shfl_xor_sync(~0u,s,sh);
    if (lane==0){
        int ic = k/9, r = k - ic*9;
        d_wr[r*256 + ic] = __float2half(s);
    }
}

// merged: x11 = softmax(gnb) (smem) -> wa9[r][c], cb
__global__ void __launch_bounds__(288) k_wa(const float* __restrict__ w3a, const float* __restrict__ b3a,
                                            const float* __restrict__ gnb){
    __shared__ float x11s[32];
    int t = threadIdx.x;
    if (t < 32){
        float v = gnb[t], m = v;
        #pragma unroll
        for (int s=16;s;s>>=1) m = fmaxf(m, __shfl_xor_sync(~0u, m, s));
        float e = expf(v-m), sum = e;
        #pragma unroll
        for (int s=16;s;s>>=1) sum += __shfl_xor_sync(~0u, sum, s);
        x11s[t] = e/sum;
    }
    __syncthreads();
    int ic = t/9, r = t - ic*9;
    float s = 0.f;
    for (int o=0;o<32;o++) s += x11s[o]*w3a[o*288 + ic*9 + r];
    __half h = __float2half(s);
    #pragma unroll
    for (int g=0;g<8;g++) d_wa9[r*256 + g*32 + ic] = h;
    if (t==0){
        float c = 0.f;
        for (int o=0;o<32;o++) c += x11s[o]*b3a[o];
        d_cb = c;
    }
}

// row/col means per channel (fp32 x)
__global__ void __launch_bounds__(256) k_rowcol(const float* __restrict__ x){
    __shared__ float tile[HW_];
    int ch = blockIdx.x;
    const float* src = x + (size_t)ch*HW_;
    for (int i = threadIdx.x*4; i < HW_; i += 1024){
        float4 v = *(const float4*)(src+i);
        tile[i]=v.x; tile[i+1]=v.y; tile[i+2]=v.z; tile[i+3]=v.w;
    }
    __syncthreads();
    int t = threadIdx.x;
    if (t < H_){
        float rs = 0.f, cs = 0.f;
        #pragma unroll 8
        for (int w = 0; w < W_; w++) rs += tile[t*W_ + w];
        #pragma unroll 8
        for (int h = 0; h < H_; h++) cs += tile[h*W_ + t];
        d_xhm[ch*H_ + t] = rs * (1.0f/W_);
        d_xwm[ch*W_ + t] = cs * (1.0f/H_);
    }
}

// NCHW fp32 -> NHWC fp16 transpose (64px x 256ch tiles)
__global__ void __launch_bounds__(256) k_tr(const float* __restrict__ x){
    __shared__ __half sm[256][66];
    int b = blockIdx.y, p0 = blockIdx.x*64;
    int t = threadIdx.x, lane = t&31, w = t>>5;
    #pragma unroll 4
    for (int it=0; it<32; it++){
        int c = it*8 + w;
        float2 v = *(const float2*)(x + (size_t)(b*C_+c)*HW_ + p0 + lane*2);
        sm[c][lane*2]   = __float2half(v.x);
        sm[c][lane*2+1] = __float2half(v.y);
    }
    __syncthreads();
    __half* dst = d_xT + ((size_t)(b*HW_ + p0))*C_;
    #pragma unroll 4
    for (int i=t; i<8192; i+=256){
        int px = i>>7, c2 = (i&127)*2;
        *(__half2*)(dst + (size_t)px*C_ + c2) = __halves2half2(sm[c2][px], sm[c2+1][px]);
    }
}

// 1x1 conv on [xh;xw] + sigmoid; transposed gate layouts
__global__ void __launch_bounds__(128) k_hw(const float* __restrict__ w1, const float* __restrict__ b1){
    __shared__ float ws[1024], cat[32*112], bs[32];
    int bg = blockIdx.x;
    int b = bg>>3, g = bg&7;
    for (int i = threadIdx.x; i < 1024; i += 128) ws[i] = w1[i];
    if (threadIdx.x < 32) bs[threadIdx.x] = b1[threadIdx.x];
    for (int i = threadIdx.x; i < 32*112; i += 128){
        int c = i/112, p = i%112;
        cat[i] = (p < H_) ? d_xhm[(bg*CG_+c)*H_+p] : d_xwm[(bg*CG_+c)*W_+(p-H_)];
    }
    __syncthreads();
    for (int i = threadIdx.x; i < 32*112; i += 128){
        int o = i/112, p = i%112;
        float acc = bs[o];
        #pragma unroll 8
        for (int c = 0; c < 32; c++) acc += ws[o*32+c]*cat[c*112+p];
        float s = sigf(acc);
        if (p < H_) d_shT[((size_t)b*H_ + p)*C_ + g*CG_ + o] = s;
        else        d_swT[((size_t)b*W_ + (p-H_))*C_ + g*CG_ + o] = s;
    }
}

// per-channel sum/sumsq of x0, NHWC
__global__ void __launch_bounds__(256) k_stats(){
    int y = blockIdx.x, b = blockIdx.y;
    int c = threadIdx.x;
    float shv = d_shT[((size_t)b*H_ + y)*C_ + c];
    const __half* xp = d_xT + ((size_t)(b*HW_ + y*W_))*C_ + c;
    const float* swp = d_swT + (size_t)b*W_*C_ + c;
    float s = 0.f, q = 0.f;
    #pragma unroll 4
    for (int j=0;j<W_;j++){
        float v = __half2float(xp[(size_t)j*C_]) * shv * swp[(size_t)j*C_];
        s += v; q += v*v;
    }
    atomicAdd(&d_chsum[b*C_ + c], s);
    atomicAdd(&d_chsq [b*C_ + c], q);
}

__global__ void k_fin(){
    int i = blockIdx.x*blockDim.x + threadIdx.x;
    if (i < BG_*CG_){
        float mu = d_chsum[i]*(1.0f/HW_);
        float var = d_chsq[i]*(1.0f/HW_) - mu*mu;
        d_mu[i] = mu;
        d_rstd[i] = rsqrtf(var + EPSV);
    }
    if (i < C_){
        float s = 0.f, q = 0.f;
        for (int b = 0; b < B_; b++){ s += d_chsum[b*C_+i]; q += d_chsq[b*C_+i]; }
        const float n = (float)B_*(float)HW_;
        float bm = s/n, bv = q/n - bm*bm;
        d_bm[i] = bm;
        d_rbstd[i] = rsqrtf(bv + EPSV);
    }
}

// merged: T (window sums) -> m2 -> x21 softmax -> A1/C1, one block per bg
__global__ void __launch_bounds__(256) k_gn2(const float* __restrict__ w3a, const float* __restrict__ b3a,
                                            const float* __restrict__ gnw, const float* __restrict__ gnb,
                                            const float* __restrict__ x){
    __shared__ float Ts[288], m2s[32];
    int bg = blockIdx.x, b = bg>>3, g = bg&7;
    int t = threadIdx.x, lane = t&31, w = t>>5;
    for (int i=t;i<288;i+=256){
        int ic = i/9, r = i - ic*9;
        int ch = b*C_ + g*32 + ic;
        float S = 0.f;
        for (int yy=0; yy<H_; yy++) S += d_xhm[ch*H_+yy];
        S *= W_;
        int dy = r/3 - 1, dx = r - (r/3)*3 - 1;
        float T = S;
        if (dy==1)  T -= d_xhm[ch*H_+0]*W_;
        if (dy==-1) T -= d_xhm[ch*H_+H_-1]*W_;
        if (dx==1)  T -= d_xwm[ch*W_+0]*H_;
        if (dx==-1) T -= d_xwm[ch*W_+W_-1]*H_;
        const float* xp = x + (size_t)ch*HW_;
        if (dy==1 && dx==1)   T += xp[0];
        if (dy==1 && dx==-1)  T += xp[W_-1];
        if (dy==-1 && dx==1)  T += xp[(H_-1)*W_];
        if (dy==-1 && dx==-1) T += xp[HW_-1];
        Ts[i] = T;
    }
    __syncthreads();
    for (int o=w;o<32;o+=8){
        float s = 0.f;
        for (int i=lane;i<288;i+=32) s += w3a[o*288 + i]*Ts[i];
        #pragma unroll
        for (int sh=16;sh;sh>>=1) s += __shfl_xor_sync(~0u,s,sh);
        if (lane==0) m2s[o] = s + (float)HW_*b3a[o];
    }
    __syncthreads();
    if (w==0){
        float v = m2s[lane]*(1.0f/HW_);
        float m = v;
        #pragma unroll
        for (int s=16;s;s>>=1) m = fmaxf(m, __shfl_xor_sync(~0u,m,s));
        float e = expf(v-m), sum = e;
        #pragma unroll
        for (int s=16;s;s>>=1) sum += __shfl_xor_sync(~0u,sum,s);
        float x21 = e/sum;
        float rs = d_rstd[bg*CG_+lane], mu = d_mu[bg*CG_+lane];
        d_A1[bg*CG_+lane] = x21*gnw[lane]*rs;
        float cc = x21*(gnb[lane] - gnw[lane]*rs*mu);
        #pragma unroll
        for (int s=16;s;s>>=1) cc += __shfl_xor_sync(~0u,cc,s);
        if (lane==0) d_C1[bg] = cc;
    }
}

// combined 9-tap correlations: s4 logits (wr) AND w1 term1 (wa9) in one xT pass
__global__ void __launch_bounds__(256) k_corr(){
    __shared__ __half wrs[9*256], was[9*256];
    int y = blockIdx.x, b = blockIdx.y;
    int t = threadIdx.x, lane = t&31, w = t>>5;
    for (int i=t;i<288;i+=256){
        ((uint4*)wrs)[i] = ((const uint4*)d_wr)[i];
        ((uint4*)was)[i] = ((const uint4*)d_wa9)[i];
    }
    __syncthreads();
    float cb = d_cb;
    const __half* xTb = d_xT + (size_t)b*HW_*256;
    #pragma unroll
    for (int px=0; px<7; px++){
        int j = w*7 + px;
        float az = 0.f, aa = 0.f;
        #pragma unroll
        for (int r=0;r<9;r++){
            int yy = y + r/3 - 1, xx = j + r%3 - 1;
            if (yy>=0 && yy<H_ && xx>=0 && xx<W_){
                uint4 xv = *(const uint4*)(xTb + ((size_t)(yy*W_+xx))*256 + lane*8);
                uint4 wz = *(const uint4*)(wrs + r*256 + lane*8);
                uint4 wg = *(const uint4*)(was + r*256 + lane*8);
                __half2* xh = (__half2*)&xv;
                __half2* zh = (__half2*)&wz;
                __half2* gh = (__half2*)&wg;
                __half2 pz = __hmul2(xh[0], zh[0]);
                pz = __hfma2(xh[1], zh[1], pz);
                pz = __hfma2(xh[2], zh[2], pz);
                pz = __hfma2(xh[3], zh[3], pz);
                __half2 pg = __hmul2(xh[0], gh[0]);
                pg = __hfma2(xh[1], gh[1], pg);
                pg = __hfma2(xh[2], gh[2], pg);
                pg = __hfma2(xh[3], gh[3], pg);
                float2 fz = __half22float2(pz);
                float2 fg = __half22float2(pg);
                az += fz.x + fz.y;
                aa += fg.x + fg.y;
            }
        }
        aa += __shfl_xor_sync(~0u,aa,1);
        aa += __shfl_xor_sync(~0u,aa,2);
        #pragma unroll
        for (int s=16;s;s>>=1) az += __shfl_xor_sync(~0u,az,s);
        if ((lane&3)==0){
            int g = lane>>2;
            d_w1[((size_t)(b*G_+g))*HW_ + y*W_ + j] = aa + cb;
        }
        if (lane==0) d_s4[(size_t)b*HW_ + y*W_ + j] = az;
    }
}

// pass3 v2: smem x0 staging; phase2 per-(g,j) sums (no per-pixel shuffles)
__global__ void __launch_bounds__(256) k_pass3(){
    extern __shared__ float sx0[];           // [256][57]
    __shared__ float red[8][56];
    __shared__ float A1s[256], C1s[8];
    int y = blockIdx.x, b = blockIdx.y;
    int c = threadIdx.x;
    A1s[c] = d_A1[(b*G_ + (c>>5))*CG_ + (c&31)];
    if (c < 8) C1s[c] = d_C1[b*G_ + c];
    float shv = d_shT[((size_t)b*H_ + y)*C_ + c];
    const __half* xp = d_xT + ((size_t)(b*HW_ + y*W_))*C_ + c;
    const float* swp = d_swT + (size_t)b*W_*C_ + c;
    const float* s4p = d_s4 + (size_t)b*HW_ + y*W_;
    float uacc = 0.f;
    float* row = sx0 + c*57;
    for (int j=0;j<W_;j++){
        float x0 = __half2float(xp[(size_t)j*C_]) * shv * swp[(size_t)j*C_];
        uacc += s4p[j]*x0;
        row[j] = x0;
    }
    atomicAdd(&d_u[b*C_ + c], uacc);
    __syncthreads();
    float* w1b = d_w1 + (size_t)(b*G_)*HW_ + y*W_;
    for (int it=c; it<448; it+=256){
        int g = it/56, j = it - g*56;
        float t2 = 0.f, sl = 0.f;
        const float* base = sx0 + (g*32)*57 + j;
        #pragma unroll 8
        for (int ci=0; ci<32; ci++){
            float v = base[ci*57];
            t2 += A1s[g*32+ci]*v;
            sl += d_rbstd[g*32+ci]*v;
        }
        w1b[(size_t)g*HW_ + j] += t2 + C1s[g];
        red[g][j] = sl;
    }
    __syncthreads();
    if (c < W_){
        float s = 0.f;
        #pragma unroll
        for (int g=0;g<8;g++) s += red[g][c];
        d_s3[(size_t)b*HW_ + y*W_ + c] = s*(1.0f/C_);
    }
}

__global__ void __launch_bounds__(256) k_softmax(int which){
    int row = blockIdx.x;
    float scale = which ? (1.0f/C_) : 1.0f;
    float* p = (which ? d_s4 : d_s3) + (size_t)row*HW_;
    __shared__ float red[8];
    int t = threadIdx.x, lane = t&31, wid = t>>5;
    float mx = -1e30f;
    for (int i=t;i<HW_;i+=256) mx = fmaxf(mx, p[i]*scale);
    #pragma unroll
    for (int s=16;s;s>>=1) mx = fmaxf(mx, __shfl_xor_sync(~0u,mx,s));
    if (lane==0) red[wid]=mx;
    __syncthreads();
    mx = red[0];
    #pragma unroll
    for (int i=1;i<8;i++) mx = fmaxf(mx, red[i]);
    __syncthreads();
    float sum = 0.f;
    for (int i=t;i<HW_;i+=256){ float e = expf(p[i]*scale-mx); p[i]=e; sum += e; }
    #pragma unroll
    for (int s=16;s;s>>=1) sum += __shfl_xor_sync(~0u,sum,s);
    if (lane==0) red[wid]=sum;
    __syncthreads();
    sum = 0.f;
    #pragma unroll
    for (int i=0;i<8;i++) sum += red[i];
    float inv = 1.0f/sum;
    for (int i=t;i<HW_;i+=256) p[i] *= inv;
}

// ycorr v2: 7 rows per block, s3 halo staged once, 9 atomics per thread
__global__ void __launch_bounds__(256) k_ycorr(){
    __shared__ float s3r[9][58];
    int y0 = blockIdx.x*7, b = blockIdx.y;
    int c = threadIdx.x;
    for (int i=c;i<9*58;i+=256){
        int rr = i/58, jj = i - rr*58;
        int yy = y0 - 1 + rr, xx = jj - 1;
        s3r[rr][jj] = (yy>=0 && yy<H_ && xx>=0 && xx<W_) ? d_s3[(size_t)b*HW_ + yy*W_ + xx] : 0.f;
    }
    __syncthreads();
    float a[9] = {0,0,0,0,0,0,0,0,0};
    for (int k=0;k<7;k++){
        const __half* xp = d_xT + ((size_t)(b*HW_ + (y0+k)*W_))*C_ + c;
        for (int j=0;j<W_;j++){
            float v = __half2float(xp[(size_t)j*C_]);
            #pragma unroll
            for (int r=0;r<9;r++){
                int dy = r/3 - 1, dx = r - (r/3)*3 - 1;
                a[r] += v * s3r[k+1-dy][j - dx + 1];
            }
        }
    }
    float* yp = d_y + (size_t)b*2304 + c*9;
    #pragma unroll
    for (int r=0;r<9;r++) atomicAdd(&yp[r], a[r]);
}

// t4 + wfin fused
__global__ void __launch_bounds__(256) k_t4fin(const float* __restrict__ b3b){
    __shared__ float ys[2304];
    int b = blockIdx.x, t = threadIdx.x;
    for (int i=t;i<2304;i+=256) ys[i] = d_y[(size_t)b*2304 + i];
    __syncthreads();
    float acc = b3b[t];
    #pragma unroll 8
    for (int k=0;k<2304;k++)
        acc += __half2float(d_w4c[(size_t)k*256 + t]) * ys[k];
    d_sw2[b*C_ + t] = sigf(acc + d_rbstd[t]*(d_u[b*C_ + t] - d_bm[t]));
}

__global__ void __launch_bounds__(256) k_out(const float* __restrict__ x, float* __restrict__ out){
    size_t i = ((size_t)blockIdx.x*256 + threadIdx.x)*4;
    int p = (int)(i % HW_);
    int ch = (int)(i / HW_);
    int b = ch >> 8, c = ch & 255;
    int bg = b*G_ + (c>>5);
    float4 xv = *(const float4*)(x+i);
    float4 wv = *(const float4*)(d_w1 + (size_t)bg*HW_ + p);
    float s2 = d_sw2[ch];
    float4 o;
    o.x = xv.x*(sigf(wv.x) + s2);
    o.y = xv.y*(sigf(wv.y) + s2);
    o.z = xv.z*(sigf(wv.z) + s2);
    o.w = xv.w*(sigf(wv.w) + s2);
    *(float4*)(out+i) = o;
}

// ---------------- launch ----------------
extern "C" void kernel_launch(void* const* d_in, const int* in_sizes, int n_in,
                              void* d_out, int out_size){
    const float* x   = (const float*)d_in[0];
    const float* w1  = (const float*)d_in[1];
    const float* b1  = (const float*)d_in[2];
    const float* w3a = (const float*)d_in[3];
    const float* b3a = (const float*)d_in[4];
    const float* w3b = (const float*)d_in[5];
    const float* b3b = (const float*)d_in[6];
    const float* gnw = (const float*)d_in[7];
    const float* gnb = (const float*)d_in[8];
    float* out = (float*)d_out;

    static cudaStream_t sB = nullptr;
    static cudaEvent_t evR=nullptr, evW=nullptr, evT=nullptr, evB=nullptr;
    if (!sB){
        cudaStreamCreateWithFlags(&sB, cudaStreamNonBlocking);
        cudaEventCreateWithFlags(&evR, cudaEventDisableTiming);
        cudaEventCreateWithFlags(&evW, cudaEventDisableTiming);
        cudaEventCreateWithFlags(&evT, cudaEventDisableTiming);
        cudaEventCreateWithFlags(&evB, cudaEventDisableTiming);
        cudaFuncSetAttribute(k_pass3, cudaFuncAttributeMaxDynamicSharedMemorySize, 256*57*4);
    }

    // default: root the capture
    k_zero  <<<288, 256>>>();
    cudaEventRecord(evR, 0);

    // sB: xT transpose (rooted fork)
    cudaStreamWaitEvent(sB, evR, 0);
    k_tr    <<<dim3(49, B_), 256, 0, sB>>>(x);
    cudaEventRecord(evT, sB);

    // default: weight prep
    k_wa    <<<1, 288>>>(w3a, b3a, gnb);
    k_wprep <<<2304, 256>>>(w3b);
    k_wr    <<<288, 256>>>();
    cudaEventRecord(evW, 0);

    // sB: combined correlations -> s4 softmax
    cudaStreamWaitEvent(sB, evW, 0);
    k_corr  <<<dim3(H_, B_), 256, 0, sB>>>();
    k_softmax<<<B_, 256, 0, sB>>>(1);
    cudaEventRecord(evB, sB);

    // default: gating / GN chain
    k_rowcol<<<B_*C_, 256>>>(x);
    k_hw    <<<BG_, 128>>>(w1, b1);
    cudaStreamWaitEvent(0, evT, 0);
    k_stats <<<dim3(H_, B_), 256>>>();
    k_fin   <<<32, 256>>>();
    k_gn2   <<<BG_, 256>>>(w3a, b3a, gnw, gnb, x);
    cudaStreamWaitEvent(0, evB, 0);
    k_pass3 <<<dim3(H_, B_), 256, 256*57*4>>>();
    k_softmax<<<B_, 256>>>(0);
    k_ycorr <<<dim3(8, B_), 256>>>();
    k_t4fin <<<B_, 256>>>(b3b);
    k_out   <<<25088, 256>>>(x, out);
}

// round 17
// speedup vs baseline: 4.5682x; 1.1191x over previous
#include <cuda_runtime.h>
#include <cuda_fp16.h>
#include <math.h>

#define B_ 32
#define C_ 256
#define H_ 56
#define W_ 56
#define HW_ 3136
#define G_ 8
#define CG_ 32
#define BG_ 256
#define EPSV 1e-5f

// ---------------- static device scratch ----------------
__device__ __half d_xT [(size_t)B_*HW_*C_];   // fp16 x, NHWC
__device__ __half d_w4c[(size_t)2304*256];    // w3b -> [ic*9+r][o]
__device__ __half d_wr [9*256];               // wr[r][c] = sum_o w3b[o][c][r]
__device__ __half d_wa9[9*256];               // wa9[r][c] = sum_o x11[o]*w3a[o][c&31][r]
__device__ float d_cb;
__device__ float d_xhm[BG_*CG_*H_], d_xwm[BG_*CG_*W_];
__device__ float d_shT[(size_t)B_*H_*C_];     // sigmoid(xh), [b][y][c]
__device__ float d_swT[(size_t)B_*W_*C_];     // sigmoid(xw), [b][j][c]
__device__ float d_chsum[BG_*CG_], d_chsq[BG_*CG_];
__device__ float d_bm[C_], d_rbstd[C_];
__device__ float d_A1[BG_*CG_], d_C1[BG_];
__device__ __half d_w1[(size_t)BG_*HW_];      // fp16 w1 logits
__device__ float d_s3[(size_t)B_*HW_], d_s4[(size_t)B_*HW_];
__device__ float d_y[(size_t)B_*C_*9];
__device__ float d_u[B_*C_];
__device__ float d_sw2[B_*C_];

__device__ __forceinline__ float sigf(float v){ return 1.f/(1.f+expf(-v)); }

// ---------------- small kernels ----------------
__global__ void k_zero(){
    int i = blockIdx.x*blockDim.x + threadIdx.x;
    if (i < BG_*CG_){ d_chsum[i] = 0.f; d_chsq[i] = 0.f; d_u[i] = 0.f; }
    if (i < B_*C_*9) d_y[i] = 0.f;
}

// w3b -> w4c [k][o] fp16
__global__ void k_wprep(const float* __restrict__ w3b){
    int j = blockIdx.x*blockDim.x + threadIdx.x;
    if (j < 256*2304){
        int o = j/2304, k = j - o*2304;
        d_w4c[(size_t)k*256 + o] = __float2half(w3b[j]);
    }
}

// wr[r][ic] = sum_o w4c[ic*9+r][o]
__global__ void __launch_bounds__(256) k_wr(){
    int k = blockIdx.x*8 + (threadIdx.x>>5);
    int lane = threadIdx.x&31;
    uint4 v = *(const uint4*)(d_w4c + (size_t)k*256 + lane*8);
    __half2* h = (__half2*)&v;
    float s = 0.f;
    #pragma unroll
    for (int i=0;i<4;i++){ float2 f = __half22float2(h[i]); s += f.x + f.y; }
    #pragma unroll
    for (int sh=16;sh;sh>>=1) s += __shfl_xor_sync(~0u,s,sh);
    if (lane==0){
        int ic = k/9, r = k - ic*9;
        d_wr[r*256 + ic] = __float2half(s);
    }
}

// x11 = softmax(gnb) -> wa9[r][c], cb
__global__ void __launch_bounds__(288) k_wa(const float* __restrict__ w3a, const float* __restrict__ b3a,
                                            const float* __restrict__ gnb){
    __shared__ float x11s[32];
    int t = threadIdx.x;
    if (t < 32){
        float v = gnb[t], m = v;
        #pragma unroll
        for (int s=16;s;s>>=1) m = fmaxf(m, __shfl_xor_sync(~0u, m, s));
        float e = expf(v-m), sum = e;
        #pragma unroll
        for (int s=16;s;s>>=1) sum += __shfl_xor_sync(~0u, sum, s);
        x11s[t] = e/sum;
    }
    __syncthreads();
    int ic = t/9, r = t - ic*9;
    float s = 0.f;
    for (int o=0;o<32;o++) s += x11s[o]*w3a[o*288 + ic*9 + r];
    __half h = __float2half(s);
    #pragma unroll
    for (int g=0;g<8;g++) d_wa9[r*256 + g*32 + ic] = h;
    if (t==0){
        float c = 0.f;
        for (int o=0;o<32;o++) c += x11s[o]*b3a[o];
        d_cb = c;
    }
}

// row/col means per channel (fp32 x)
__global__ void __launch_bounds__(256) k_rowcol(const float* __restrict__ x){
    __shared__ float tile[HW_];
    int ch = blockIdx.x;
    const float* src = x + (size_t)ch*HW_;
    for (int i = threadIdx.x*4; i < HW_; i += 1024){
        float4 v = *(const float4*)(src+i);
        tile[i]=v.x; tile[i+1]=v.y; tile[i+2]=v.z; tile[i+3]=v.w;
    }
    __syncthreads();
    int t = threadIdx.x;
    if (t < H_){
        float rs = 0.f, cs = 0.f;
        #pragma unroll 8
        for (int w = 0; w < W_; w++) rs += tile[t*W_ + w];
        #pragma unroll 8
        for (int h = 0; h < H_; h++) cs += tile[h*W_ + t];
        d_xhm[ch*H_ + t] = rs * (1.0f/W_);
        d_xwm[ch*W_ + t] = cs * (1.0f/H_);
    }
}

// NCHW fp32 -> NHWC fp16 transpose
__global__ void __launch_bounds__(256) k_tr(const float* __restrict__ x){
    __shared__ __half sm[256][66];
    int b = blockIdx.y, p0 = blockIdx.x*64;
    int t = threadIdx.x, lane = t&31, w = t>>5;
    #pragma unroll 4
    for (int it=0; it<32; it++){
        int c = it*8 + w;
        float2 v = *(const float2*)(x + (size_t)(b*C_+c)*HW_ + p0 + lane*2);
        sm[c][lane*2]   = __float2half(v.x);
        sm[c][lane*2+1] = __float2half(v.y);
    }
    __syncthreads();
    __half* dst = d_xT + ((size_t)(b*HW_ + p0))*C_;
    #pragma unroll 4
    for (int i=t; i<8192; i+=256){
        int px = i>>7, c2 = (i&127)*2;
        *(__half2*)(dst + (size_t)px*C_ + c2) = __halves2half2(sm[c2][px], sm[c2+1][px]);
    }
}

// 1x1 conv on [xh;xw] + sigmoid
__global__ void __launch_bounds__(128) k_hw(const float* __restrict__ w1, const float* __restrict__ b1){
    __shared__ float ws[1024], cat[32*112], bs[32];
    int bg = blockIdx.x;
    int b = bg>>3, g = bg&7;
    for (int i = threadIdx.x; i < 1024; i += 128) ws[i] = w1[i];
    if (threadIdx.x < 32) bs[threadIdx.x] = b1[threadIdx.x];
    for (int i = threadIdx.x; i < 32*112; i += 128){
        int c = i/112, p = i%112;
        cat[i] = (p < H_) ? d_xhm[(bg*CG_+c)*H_+p] : d_xwm[(bg*CG_+c)*W_+(p-H_)];
    }
    __syncthreads();
    for (int i = threadIdx.x; i < 32*112; i += 128){
        int o = i/112, p = i%112;
        float acc = bs[o];
        #pragma unroll 8
        for (int c = 0; c < 32; c++) acc += ws[o*32+c]*cat[c*112+p];
        float s = sigf(acc);
        if (p < H_) d_shT[((size_t)b*H_ + p)*C_ + g*CG_ + o] = s;
        else        d_swT[((size_t)b*W_ + (p-H_))*C_ + g*CG_ + o] = s;
    }
}

// per-channel sum/sumsq of x0
__global__ void __launch_bounds__(256) k_stats(){
    int y = blockIdx.x, b = blockIdx.y;
    int c = threadIdx.x;
    float shv = d_shT[((size_t)b*H_ + y)*C_ + c];
    const __half* xp = d_xT + ((size_t)(b*HW_ + y*W_))*C_ + c;
    const float* swp = d_swT + (size_t)b*W_*C_ + c;
    float s = 0.f, q = 0.f;
    #pragma unroll 4
    for (int j=0;j<W_;j++){
        float v = __half2float(xp[(size_t)j*C_]) * shv * swp[(size_t)j*C_];
        s += v; q += v*v;
    }
    atomicAdd(&d_chsum[b*C_ + c], s);
    atomicAdd(&d_chsq [b*C_ + c], q);
}

// merged: fin (local mu/rstd, global bm/rbstd) + T window sums + m2 + x21 softmax + A1/C1
__global__ void __launch_bounds__(256) k_gn2(const float* __restrict__ w3a, const float* __restrict__ b3a,
                                            const float* __restrict__ gnw, const float* __restrict__ gnb,
                                            const float* __restrict__ x){
    __shared__ float Ts[288], m2s[32], mus[32], rss[32];
    int bg = blockIdx.x, b = bg>>3, g = bg&7;
    int t = threadIdx.x, lane = t&31, w = t>>5;
    if (t < 32){
        int ch = bg*CG_ + t;
        float mu = d_chsum[ch]*(1.0f/HW_);
        float var = d_chsq[ch]*(1.0f/HW_) - mu*mu;
        mus[t] = mu;
        rss[t] = rsqrtf(var + EPSV);
    }
    // bm/rbstd written by the 8 b==0 blocks (each covers channels g*32..g*32+31)
    if (b==0 && t < 32){
        int c = g*32 + t;
        float s = 0.f, q = 0.f;
        for (int bb=0; bb<B_; bb++){ s += d_chsum[bb*C_+c]; q += d_chsq[bb*C_+c]; }
        const float n = (float)B_*(float)HW_;
        float bm = s/n, bv = q/n - bm*bm;
        d_bm[c] = bm;
        d_rbstd[c] = rsqrtf(bv + EPSV);
    }
    for (int i=t;i<288;i+=256){
        int ic = i/9, r = i - ic*9;
        int ch = b*C_ + g*32 + ic;
        float S = 0.f;
        for (int yy=0; yy<H_; yy++) S += d_xhm[ch*H_+yy];
        S *= W_;
        int dy = r/3 - 1, dx = r - (r/3)*3 - 1;
        float T = S;
        if (dy==1)  T -= d_xhm[ch*H_+0]*W_;
        if (dy==-1) T -= d_xhm[ch*H_+H_-1]*W_;
        if (dx==1)  T -= d_xwm[ch*W_+0]*H_;
        if (dx==-1) T -= d_xwm[ch*W_+W_-1]*H_;
        const float* xp = x + (size_t)ch*HW_;
        if (dy==1 && dx==1)   T += xp[0];
        if (dy==1 && dx==-1)  T += xp[W_-1];
        if (dy==-1 && dx==1)  T += xp[(H_-1)*W_];
        if (dy==-1 && dx==-1) T += xp[HW_-1];
        Ts[i] = T;
    }
    __syncthreads();
    for (int o=w;o<32;o+=8){
        float s = 0.f;
        for (int i=lane;i<288;i+=32) s += w3a[o*288 + i]*Ts[i];
        #pragma unroll
        for (int sh=16;sh;sh>>=1) s += __shfl_xor_sync(~0u,s,sh);
        if (lane==0) m2s[o] = s + (float)HW_*b3a[o];
    }
    __syncthreads();
    if (w==0){
        float v = m2s[lane]*(1.0f/HW_);
        float m = v;
        #pragma unroll
        for (int s=16;s;s>>=1) m = fmaxf(m, __shfl_xor_sync(~0u,m,s));
        float e = expf(v-m), sum = e;
        #pragma unroll
        for (int s=16;s;s>>=1) sum += __shfl_xor_sync(~0u,sum,s);
        float x21 = e/sum;
        float rs = rss[lane], mu = mus[lane];
        d_A1[bg*CG_+lane] = x21*gnw[lane]*rs;
        float cc = x21*(gnb[lane] - gnw[lane]*rs*mu);
        #pragma unroll
        for (int s=16;s;s>>=1) cc += __shfl_xor_sync(~0u,cc,s);
        if (lane==0) d_C1[bg] = cc;
    }
}

// combined 9-tap correlations: s4 logits + w1 term1 (fp16 w1)
__global__ void __launch_bounds__(256) k_corr(){
    __shared__ __half wrs[9*256], was[9*256];
    int y = blockIdx.x, b = blockIdx.y;
    int t = threadIdx.x, lane = t&31, w = t>>5;
    for (int i=t;i<288;i+=256){
        ((uint4*)wrs)[i] = ((const uint4*)d_wr)[i];
        ((uint4*)was)[i] = ((const uint4*)d_wa9)[i];
    }
    __syncthreads();
    float cb = d_cb;
    const __half* xTb = d_xT + (size_t)b*HW_*256;
    #pragma unroll
    for (int px=0; px<7; px++){
        int j = w*7 + px;
        float az = 0.f, aa = 0.f;
        #pragma unroll
        for (int r=0;r<9;r++){
            int yy = y + r/3 - 1, xx = j + r%3 - 1;
            if (yy>=0 && yy<H_ && xx>=0 && xx<W_){
                uint4 xv = *(const uint4*)(xTb + ((size_t)(yy*W_+xx))*256 + lane*8);
                uint4 wz = *(const uint4*)(wrs + r*256 + lane*8);
                uint4 wg = *(const uint4*)(was + r*256 + lane*8);
                __half2* xh = (__half2*)&xv;
                __half2* zh = (__half2*)&wz;
                __half2* gh = (__half2*)&wg;
                __half2 pz = __hmul2(xh[0], zh[0]);
                pz = __hfma2(xh[1], zh[1], pz);
                pz = __hfma2(xh[2], zh[2], pz);
                pz = __hfma2(xh[3], zh[3], pz);
                __half2 pg = __hmul2(xh[0], gh[0]);
                pg = __hfma2(xh[1], gh[1], pg);
                pg = __hfma2(xh[2], gh[2], pg);
                pg = __hfma2(xh[3], gh[3], pg);
                float2 fz = __half22float2(pz);
                float2 fg = __half22float2(pg);
                az += fz.x + fz.y;
                aa += fg.x + fg.y;
            }
        }
        aa += __shfl_xor_sync(~0u,aa,1);
        aa += __shfl_xor_sync(~0u,aa,2);
        #pragma unroll
        for (int s=16;s;s>>=1) az += __shfl_xor_sync(~0u,az,s);
        if ((lane&3)==0){
            int g = lane>>2;
            d_w1[((size_t)(b*G_+g))*HW_ + y*W_ + j] = __float2half(aa + cb);
        }
        if (lane==0) d_s4[(size_t)b*HW_ + y*W_ + j] = az;
    }
}

// pass3: smem x0 staging; w1 += term2 (fp16), s3 logits, u
__global__ void __launch_bounds__(256) k_pass3(){
    extern __shared__ float sx0[];           // [256][57]
    __shared__ float red[8][56];
    __shared__ float A1s[256], C1s[8];
    int y = blockIdx.x, b = blockIdx.y;
    int c = threadIdx.x;
    A1s[c] = d_A1[(b*G_ + (c>>5))*CG_ + (c&31)];
    if (c < 8) C1s[c] = d_C1[b*G_ + c];
    float shv = d_shT[((size_t)b*H_ + y)*C_ + c];
    const __half* xp = d_xT + ((size_t)(b*HW_ + y*W_))*C_ + c;
    const float* swp = d_swT + (size_t)b*W_*C_ + c;
    const float* s4p = d_s4 + (size_t)b*HW_ + y*W_;
    float uacc = 0.f;
    float* row = sx0 + c*57;
    for (int j=0;j<W_;j++){
        float x0 = __half2float(xp[(size_t)j*C_]) * shv * swp[(size_t)j*C_];
        uacc += s4p[j]*x0;
        row[j] = x0;
    }
    atomicAdd(&d_u[b*C_ + c], uacc);
    __syncthreads();
    __half* w1b = d_w1 + (size_t)(b*G_)*HW_ + y*W_;
    for (int it=c; it<448; it+=256){
        int g = it/56, j = it - g*56;
        float t2 = 0.f, sl = 0.f;
        const float* base = sx0 + (g*32)*57 + j;
        #pragma unroll 8
        for (int ci=0; ci<32; ci++){
            float v = base[ci*57];
            t2 += A1s[g*32+ci]*v;
            sl += d_rbstd[g*32+ci]*v;
        }
        __half* wp = w1b + (size_t)g*HW_ + j;
        *wp = __float2half(__half2float(*wp) + t2 + C1s[g]);
        red[g][j] = sl;
    }
    __syncthreads();
    if (c < W_){
        float s = 0.f;
        #pragma unroll
        for (int g=0;g<8;g++) s += red[g][c];
        d_s3[(size_t)b*HW_ + y*W_ + c] = s*(1.0f/C_);
    }
}

__global__ void __launch_bounds__(256) k_softmax(int which){
    int row = blockIdx.x;
    float scale = which ? (1.0f/C_) : 1.0f;
    float* p = (which ? d_s4 : d_s3) + (size_t)row*HW_;
    __shared__ float red[8];
    int t = threadIdx.x, lane = t&31, wid = t>>5;
    float mx = -1e30f;
    for (int i=t;i<HW_;i+=256) mx = fmaxf(mx, p[i]*scale);
    #pragma unroll
    for (int s=16;s;s>>=1) mx = fmaxf(mx, __shfl_xor_sync(~0u,mx,s));
    if (lane==0) red[wid]=mx;
    __syncthreads();
    mx = red[0];
    #pragma unroll
    for (int i=1;i<8;i++) mx = fmaxf(mx, red[i]);
    __syncthreads();
    float sum = 0.f;
    for (int i=t;i<HW_;i+=256){ float e = expf(p[i]*scale-mx); p[i]=e; sum += e; }
    #pragma unroll
    for (int s=16;s;s>>=1) sum += __shfl_xor_sync(~0u,sum,s);
    if (lane==0) red[wid]=sum;
    __syncthreads();
    sum = 0.f;
    #pragma unroll
    for (int i=0;i<8;i++) sum += red[i];
    float inv = 1.0f/sum;
    for (int i=t;i<HW_;i+=256) p[i] *= inv;
}

// ycorr: 7 rows per block
__global__ void __launch_bounds__(256) k_ycorr(){
    __shared__ float s3r[9][58];
    int y0 = blockIdx.x*7, b = blockIdx.y;
    int c = threadIdx.x;
    for (int i=c;i<9*58;i+=256){
        int rr = i/58, jj = i - rr*58;
        int yy = y0 - 1 + rr, xx = jj - 1;
        s3r[rr][jj] = (yy>=0 && yy<H_ && xx>=0 && xx<W_) ? d_s3[(size_t)b*HW_ + yy*W_ + xx] : 0.f;
    }
    __syncthreads();
    float a[9] = {0,0,0,0,0,0,0,0,0};
    for (int k=0;k<7;k++){
        const __half* xp = d_xT + ((size_t)(b*HW_ + (y0+k)*W_))*C_ + c;
        for (int j=0;j<W_;j++){
            float v = __half2float(xp[(size_t)j*C_]);
            #pragma unroll
            for (int r=0;r<9;r++){
                int dy = r/3 - 1, dx = r - (r/3)*3 - 1;
                a[r] += v * s3r[k+1-dy][j - dx + 1];
            }
        }
    }
    float* yp = d_y + (size_t)b*2304 + c*9;
    #pragma unroll
    for (int r=0;r<9;r++) atomicAdd(&yp[r], a[r]);
}

// t4 + wfin fused
__global__ void __launch_bounds__(256) k_t4fin(const float* __restrict__ b3b){
    __shared__ float ys[2304];
    int b = blockIdx.x, t = threadIdx.x;
    for (int i=t;i<2304;i+=256) ys[i] = d_y[(size_t)b*2304 + i];
    __syncthreads();
    float acc = b3b[t];
    #pragma unroll 8
    for (int k=0;k<2304;k++)
        acc += __half2float(d_w4c[(size_t)k*256 + t]) * ys[k];
    d_sw2[b*C_ + t] = sigf(acc + d_rbstd[t]*(d_u[b*C_ + t] - d_bm[t]));
}

__global__ void __launch_bounds__(256) k_out(const float* __restrict__ x, float* __restrict__ out){
    size_t i = ((size_t)blockIdx.x*256 + threadIdx.x)*4;
    int p = (int)(i % HW_);
    int ch = (int)(i / HW_);
    int b = ch >> 8, c = ch & 255;
    int bg = b*G_ + (c>>5);
    float4 xv = *(const float4*)(x+i);
    __half2 w01 = *(const __half2*)(d_w1 + (size_t)bg*HW_ + p);
    __half2 w23 = *(const __half2*)(d_w1 + (size_t)bg*HW_ + p + 2);
    float2 f01 = __half22float2(w01), f23 = __half22float2(w23);
    float s2 = d_sw2[ch];
    float4 o;
    o.x = xv.x*(sigf(f01.x) + s2);
    o.y = xv.y*(sigf(f01.y) + s2);
    o.z = xv.z*(sigf(f23.x) + s2);
    o.w = xv.w*(sigf(f23.y) + s2);
    *(float4*)(out+i) = o;
}

// ---------------- launch ----------------
extern "C" void kernel_launch(void* const* d_in, const int* in_sizes, int n_in,
                              void* d_out, int out_size){
    const float* x   = (const float*)d_in[0];
    const float* w1  = (const float*)d_in[1];
    const float* b1  = (const float*)d_in[2];
    const float* w3a = (const float*)d_in[3];
    const float* b3a = (const float*)d_in[4];
    const float* w3b = (const float*)d_in[5];
    const float* b3b = (const float*)d_in[6];
    const float* gnw = (const float*)d_in[7];
    const float* gnb = (const float*)d_in[8];
    float* out = (float*)d_out;

    static cudaStream_t sB = nullptr, sC = nullptr;
    static cudaEvent_t evR=nullptr, evW=nullptr, evT=nullptr, evB=nullptr;
    if (!sB){
        cudaStreamCreateWithFlags(&sB, cudaStreamNonBlocking);
        cudaStreamCreateWithFlags(&sC, cudaStreamNonBlocking);
        cudaEventCreateWithFlags(&evR, cudaEventDisableTiming);
        cudaEventCreateWithFlags(&evW, cudaEventDisableTiming);
        cudaEventCreateWithFlags(&evT, cudaEventDisableTiming);
        cudaEventCreateWithFlags(&evB, cudaEventDisableTiming);
        cudaFuncSetAttribute(k_pass3, cudaFuncAttributeMaxDynamicSharedMemorySize, 256*57*4);
    }

    // default: root the capture
    k_zero  <<<288, 256>>>();
    cudaEventRecord(evR, 0);

    // sC: weight prep (independent of x)
    cudaStreamWaitEvent(sC, evR, 0);
    k_wa    <<<1, 288, 0, sC>>>(w3a, b3a, gnb);
    k_wprep <<<2304, 256, 0, sC>>>(w3b);
    k_wr    <<<288, 256, 0, sC>>>();
    cudaEventRecord(evW, sC);

    // sB: xT transpose -> correlations -> s4 softmax
    cudaStreamWaitEvent(sB, evR, 0);
    k_tr    <<<dim3(49, B_), 256, 0, sB>>>(x);
    cudaEventRecord(evT, sB);
    cudaStreamWaitEvent(sB, evW, 0);
    k_corr  <<<dim3(H_, B_), 256, 0, sB>>>();
    k_softmax<<<B_, 256, 0, sB>>>(1);
    cudaEventRecord(evB, sB);

    // default: gating / GN chain
    k_rowcol<<<B_*C_, 256>>>(x);
    k_hw    <<<BG_, 128>>>(w1, b1);
    cudaStreamWaitEvent(0, evT, 0);
    k_stats <<<dim3(H_, B_), 256>>>();
    k_gn2   <<<BG_, 256>>>(w3a, b3a, gnw, gnb, x);
    cudaStreamWaitEvent(0, evB, 0);
    k_pass3 <<<dim3(H_, B_), 256, 256*57*4>>>();
    k_softmax<<<B_, 256>>>(0);
    k_ycorr <<<dim3(8, B_), 256>>>();
    k_t4fin <<<B_, 256>>>(b3b);
    k_out   <<<25088, 256>>>(x, out);
}